// round 1
// baseline (speedup 1.0000x reference)
#include <cuda_runtime.h>

// Problem constants
#define BB 8
#define NN 1024
#define DD 768
#define HH 12
#define HD 64
#define MM (BB * NN)   // 8192 rows

// Scratch (allocation-free rule: __device__ globals)
__device__ float g_q[MM * DD];
__device__ float g_k[MM * DD];
__device__ float g_v[MM * DD];
__device__ float g_ctx[MM * DD];

// ---------------------------------------------------------------------------
// 128x128x8 register-blocked SGEMM body: C[M,768] = A[M,768] @ W[768,768] + b
// 256 threads, 8x8 micro-tile per thread.
// ---------------------------------------------------------------------------
__device__ __forceinline__ void gemm_body(const float* __restrict__ A,
                                          const float* __restrict__ W,
                                          const float* __restrict__ bias,
                                          float* __restrict__ C) {
    __shared__ float As[8][128];
    __shared__ float Bs[8][128];

    const int tid = threadIdx.x;
    const int tx = tid & 15;
    const int ty = tid >> 4;
    const int rowBase = blockIdx.y * 128;
    const int colBase = blockIdx.x * 128;

    const int arow = tid >> 1;          // 0..127
    const int acol = (tid & 1) * 4;     // 0 or 4
    const int brow = tid >> 5;          // 0..7
    const int bcol = (tid & 31) * 4;    // 0..124

    float acc[8][8];
#pragma unroll
    for (int i = 0; i < 8; i++)
#pragma unroll
        for (int j = 0; j < 8; j++) acc[i][j] = 0.0f;

    for (int k0 = 0; k0 < DD; k0 += 8) {
        float4 av = *reinterpret_cast<const float4*>(&A[(rowBase + arow) * DD + k0 + acol]);
        As[acol + 0][arow] = av.x;
        As[acol + 1][arow] = av.y;
        As[acol + 2][arow] = av.z;
        As[acol + 3][arow] = av.w;
        float4 wv = *reinterpret_cast<const float4*>(&W[(k0 + brow) * DD + colBase + bcol]);
        *reinterpret_cast<float4*>(&Bs[brow][bcol]) = wv;
        __syncthreads();

#pragma unroll
        for (int kk = 0; kk < 8; kk++) {
            float4 a0 = *reinterpret_cast<const float4*>(&As[kk][ty * 8]);
            float4 a1 = *reinterpret_cast<const float4*>(&As[kk][ty * 8 + 4]);
            float4 b0 = *reinterpret_cast<const float4*>(&Bs[kk][tx * 8]);
            float4 b1 = *reinterpret_cast<const float4*>(&Bs[kk][tx * 8 + 4]);
            float a[8] = {a0.x, a0.y, a0.z, a0.w, a1.x, a1.y, a1.z, a1.w};
            float b[8] = {b0.x, b0.y, b0.z, b0.w, b1.x, b1.y, b1.z, b1.w};
#pragma unroll
            for (int i = 0; i < 8; i++)
#pragma unroll
                for (int j = 0; j < 8; j++) acc[i][j] = fmaf(a[i], b[j], acc[i][j]);
        }
        __syncthreads();
    }

#pragma unroll
    for (int i = 0; i < 8; i++) {
        const int r = rowBase + ty * 8 + i;
#pragma unroll
        for (int j = 0; j < 8; j += 4) {
            const int c = colBase + tx * 8 + j;
            float4 o;
            o.x = acc[i][j + 0] + bias[c + 0];
            o.y = acc[i][j + 1] + bias[c + 1];
            o.z = acc[i][j + 2] + bias[c + 2];
            o.w = acc[i][j + 3] + bias[c + 3];
            *reinterpret_cast<float4*>(&C[r * DD + c]) = o;
        }
    }
}

__global__ __launch_bounds__(256) void qkv_gemm_kernel(
    const float* __restrict__ x,
    const float* __restrict__ Wq, const float* __restrict__ bq,
    const float* __restrict__ Wk, const float* __restrict__ bk,
    const float* __restrict__ Wv, const float* __restrict__ bv,
    float* __restrict__ q, float* __restrict__ k, float* __restrict__ v) {
    const int z = blockIdx.z;
    const float* W;
    const float* bias;
    float* out;
    if (z == 0) { W = Wq; bias = bq; out = q; }
    else if (z == 1) { W = Wk; bias = bk; out = k; }
    else { W = Wv; bias = bv; out = v; }
    gemm_body(x, W, bias, out);
}

__global__ __launch_bounds__(256) void out_gemm_kernel(
    const float* __restrict__ A, const float* __restrict__ W,
    const float* __restrict__ bias, float* __restrict__ C) {
    gemm_body(A, W, bias, C);
}

// ---------------------------------------------------------------------------
// Fused flash-style attention with QUIET softmax:
//   attn_i = exp(s_i - m) / (1 + sum_j exp(s_j - m)),  m = max_j s_j
// One block per (q-tile of 128 rows, b, h). 256 threads (16x16).
// Thread (ty,tx): rows ty*8..+7, cols tx*4..+3 of the 128x64 S tile /
// d-cols tx*4..+3 of the 128x64 ctx tile.
// ---------------------------------------------------------------------------
#define ATTN_SMEM_FLOATS (128 * 65 * 2 + 64 * 64 * 2)
#define ATTN_SMEM_BYTES (ATTN_SMEM_FLOATS * 4)

__global__ __launch_bounds__(256, 2) void attn_kernel(
    const float* __restrict__ q, const float* __restrict__ k,
    const float* __restrict__ v, float* __restrict__ ctx) {
    extern __shared__ float smem[];
    float* Qs = smem;                 // [128][65] padded
    float* Ps = Qs + 128 * 65;        // [128][65] padded
    float* Ks = Ps + 128 * 65;        // [64 d][64 j], XOR-swizzled over j
    float* Vs = Ks + 64 * 64;         // [64 j][64 d] natural

    const int tid = threadIdx.x;
    const int tx = tid & 15;
    const int ty = tid >> 4;
    const int tx4 = tx * 4;
    const int qt = blockIdx.x;        // 0..7
    const int bh = blockIdx.y;        // 0..95
    const int b = bh / HH;
    const int h = bh - b * HH;
    const int hoff = h * HD;
    const int q0 = b * NN + qt * 128; // global row of first q in tile
    const int krow0 = b * NN;

    // Load Q tile [128][64] -> padded smem
#pragma unroll
    for (int t = tid; t < 128 * 16; t += 256) {
        const int i = t >> 4;
        const int d4 = (t & 15) * 4;
        float4 qv = *reinterpret_cast<const float4*>(&q[(q0 + i) * DD + hoff + d4]);
        Qs[i * 65 + d4 + 0] = qv.x;
        Qs[i * 65 + d4 + 1] = qv.y;
        Qs[i * 65 + d4 + 2] = qv.z;
        Qs[i * 65 + d4 + 3] = qv.w;
    }

    float m_r[8], l_r[8], acc[8][4];
#pragma unroll
    for (int i = 0; i < 8; i++) {
        m_r[i] = -1e30f;
        l_r[i] = 0.0f;
#pragma unroll
        for (int j = 0; j < 4; j++) acc[i][j] = 0.0f;
    }
    __syncthreads();

    for (int kt = 0; kt < 16; kt++) {
        // Load K (transposed to d-major, XOR swizzle over j) and V (natural)
        const int base = krow0 + kt * 64;
#pragma unroll
        for (int t = tid; t < 64 * 16; t += 256) {
            const int j = t >> 4;
            const int d4 = (t & 15) * 4;
            const int swz = ((d4 >> 2) & 7) * 4;  // same for d4..d4+3
            float4 kv = *reinterpret_cast<const float4*>(&k[(base + j) * DD + hoff + d4]);
            Ks[(d4 + 0) * 64 + (j ^ swz)] = kv.x;
            Ks[(d4 + 1) * 64 + (j ^ swz)] = kv.y;
            Ks[(d4 + 2) * 64 + (j ^ swz)] = kv.z;
            Ks[(d4 + 3) * 64 + (j ^ swz)] = kv.w;
            float4 vv = *reinterpret_cast<const float4*>(&v[(base + j) * DD + hoff + d4]);
            *reinterpret_cast<float4*>(&Vs[j * 64 + d4]) = vv;
        }
        __syncthreads();

        // S[128][64] = Q @ K^T * (1/8)
        float s[8][4];
#pragma unroll
        for (int i = 0; i < 8; i++)
#pragma unroll
            for (int j = 0; j < 4; j++) s[i][j] = 0.0f;

#pragma unroll 4
        for (int d = 0; d < 64; d++) {
            const int swz = ((d >> 2) & 7) * 4;
            float4 kv = *reinterpret_cast<const float4*>(&Ks[d * 64 + (tx4 ^ swz)]);
#pragma unroll
            for (int ii = 0; ii < 8; ii++) {
                const float qv = Qs[(ty * 8 + ii) * 65 + d];
                s[ii][0] = fmaf(qv, kv.x, s[ii][0]);
                s[ii][1] = fmaf(qv, kv.y, s[ii][1]);
                s[ii][2] = fmaf(qv, kv.z, s[ii][2]);
                s[ii][3] = fmaf(qv, kv.w, s[ii][3]);
            }
        }

        // Online quiet-softmax update; write P tile
#pragma unroll
        for (int ii = 0; ii < 8; ii++) {
            s[ii][0] *= 0.125f;
            s[ii][1] *= 0.125f;
            s[ii][2] *= 0.125f;
            s[ii][3] *= 0.125f;
            float mx = fmaxf(fmaxf(s[ii][0], s[ii][1]), fmaxf(s[ii][2], s[ii][3]));
            mx = fmaxf(mx, __shfl_xor_sync(0xffffffffu, mx, 8));
            mx = fmaxf(mx, __shfl_xor_sync(0xffffffffu, mx, 4));
            mx = fmaxf(mx, __shfl_xor_sync(0xffffffffu, mx, 2));
            mx = fmaxf(mx, __shfl_xor_sync(0xffffffffu, mx, 1));
            const float mnew = fmaxf(m_r[ii], mx);
            const float corr = __expf(m_r[ii] - mnew);
            float psum = 0.0f;
#pragma unroll
            for (int jj = 0; jj < 4; jj++) {
                const float p = __expf(s[ii][jj] - mnew);
                s[ii][jj] = p;
                psum += p;
            }
            psum += __shfl_xor_sync(0xffffffffu, psum, 8);
            psum += __shfl_xor_sync(0xffffffffu, psum, 4);
            psum += __shfl_xor_sync(0xffffffffu, psum, 2);
            psum += __shfl_xor_sync(0xffffffffu, psum, 1);
            l_r[ii] = l_r[ii] * corr + psum;
            m_r[ii] = mnew;
#pragma unroll
            for (int jj = 0; jj < 4; jj++) acc[ii][jj] *= corr;
            const int prow = (ty * 8 + ii) * 65 + tx4;
            Ps[prow + 0] = s[ii][0];
            Ps[prow + 1] = s[ii][1];
            Ps[prow + 2] = s[ii][2];
            Ps[prow + 3] = s[ii][3];
        }
        __syncthreads();

        // ctx[128][64] += P @ V
#pragma unroll 4
        for (int j = 0; j < 64; j++) {
            float4 vv = *reinterpret_cast<const float4*>(&Vs[j * 64 + tx4]);
#pragma unroll
            for (int ii = 0; ii < 8; ii++) {
                const float p = Ps[(ty * 8 + ii) * 65 + j];
                acc[ii][0] = fmaf(p, vv.x, acc[ii][0]);
                acc[ii][1] = fmaf(p, vv.y, acc[ii][1]);
                acc[ii][2] = fmaf(p, vv.z, acc[ii][2]);
                acc[ii][3] = fmaf(p, vv.w, acc[ii][3]);
            }
        }
        __syncthreads();
    }

    // Epilogue: quiet softmax denominator = 1 + l
#pragma unroll
    for (int ii = 0; ii < 8; ii++) {
        const float inv = 1.0f / (1.0f + l_r[ii]);
        const int r = q0 + ty * 8 + ii;
        float4 o;
        o.x = acc[ii][0] * inv;
        o.y = acc[ii][1] * inv;
        o.z = acc[ii][2] * inv;
        o.w = acc[ii][3] * inv;
        *reinterpret_cast<float4*>(&ctx[r * DD + hoff + tx4]) = o;
    }
}

// ---------------------------------------------------------------------------
// Launch
// ---------------------------------------------------------------------------
extern "C" void kernel_launch(void* const* d_in, const int* in_sizes, int n_in,
                              void* d_out, int out_size) {
    const float* x  = (const float*)d_in[0];
    const float* Wq = (const float*)d_in[1];
    const float* bq = (const float*)d_in[2];
    const float* Wk = (const float*)d_in[3];
    const float* bk = (const float*)d_in[4];
    const float* Wv = (const float*)d_in[5];
    const float* bv = (const float*)d_in[6];
    const float* Wo = (const float*)d_in[7];
    const float* bo = (const float*)d_in[8];
    float* out = (float*)d_out;
    (void)in_sizes; (void)n_in; (void)out_size;

    float *q, *k, *v, *ctx;
    cudaGetSymbolAddress((void**)&q, g_q);
    cudaGetSymbolAddress((void**)&k, g_k);
    cudaGetSymbolAddress((void**)&v, g_v);
    cudaGetSymbolAddress((void**)&ctx, g_ctx);

    cudaFuncSetAttribute(attn_kernel, cudaFuncAttributeMaxDynamicSharedMemorySize,
                         ATTN_SMEM_BYTES);

    dim3 blk(256);
    qkv_gemm_kernel<<<dim3(6, 64, 3), blk>>>(x, Wq, bq, Wk, bk, Wv, bv, q, k, v);
    attn_kernel<<<dim3(8, BB * HH), blk, ATTN_SMEM_BYTES>>>(q, k, v, ctx);
    out_gemm_kernel<<<dim3(6, 64, 1), blk>>>(ctx, Wo, bo, out);
}

// round 3
// speedup vs baseline: 1.6203x; 1.6203x over previous
#include <cuda_runtime.h>
#include <cuda_bf16.h>
#include <cstdint>

// Problem constants
#define BB 8
#define NN 1024
#define DD 768
#define HH 12
#define HD 64
#define MM (BB * NN)   // 8192 rows

// ---------------------------------------------------------------------------
// Scratch (__device__ globals; no allocation allowed)
// ---------------------------------------------------------------------------
__device__ float g_q[MM * DD];
__device__ float g_k[MM * DD];
__device__ float g_v[MM * DD];
__device__ float g_ctx[MM * DD];
// bf16 hi/lo splits, plain row-major
__device__ __nv_bfloat16 g_xh[MM * DD];
__device__ __nv_bfloat16 g_xl[MM * DD];
__device__ __nv_bfloat16 g_ch[MM * DD];
__device__ __nv_bfloat16 g_cl[MM * DD];
// transposed weights Wt[n][k], 4 matrices (q,k,v,o)
__device__ __nv_bfloat16 g_wh[4 * DD * DD];
__device__ __nv_bfloat16 g_wl[4 * DD * DD];

// ---------------------------------------------------------------------------
// PTX helpers
// ---------------------------------------------------------------------------
__device__ __forceinline__ uint32_t s2u(const void* p) {
    uint32_t a;
    asm("{ .reg .u64 t; cvta.to.shared.u64 t, %1; cvt.u32.u64 %0, t; }"
        : "=r"(a) : "l"(p));
    return a;
}

__device__ __forceinline__ void cp16(uint32_t dst, const void* src) {
    asm volatile("cp.async.cg.shared.global [%0], [%1], 16;" :: "r"(dst), "l"(src));
}
#define CP_COMMIT() asm volatile("cp.async.commit_group;" ::: "memory")
#define CP_WAIT1()  asm volatile("cp.async.wait_group 1;" ::: "memory")

__device__ __forceinline__ void ldm_x4(uint32_t* r, uint32_t addr) {
    asm volatile("ldmatrix.sync.aligned.m8n8.x4.shared.b16 {%0,%1,%2,%3}, [%4];"
                 : "=r"(r[0]), "=r"(r[1]), "=r"(r[2]), "=r"(r[3]) : "r"(addr));
}

__device__ __forceinline__ void mma16816(float* c, const uint32_t* a, const uint32_t* b) {
    asm volatile(
        "mma.sync.aligned.m16n8k16.row.col.f32.bf16.bf16.f32 "
        "{%0,%1,%2,%3}, {%4,%5,%6,%7}, {%8,%9}, {%0,%1,%2,%3};"
        : "+f"(c[0]), "+f"(c[1]), "+f"(c[2]), "+f"(c[3])
        : "r"(a[0]), "r"(a[1]), "r"(a[2]), "r"(a[3]), "r"(b[0]), "r"(b[1]));
}

// swizzled smem address: tile rows of 128B (64 bf16), 16B units, u' = u ^ (r&7)
__device__ __forceinline__ uint32_t swz(uint32_t base, int r, int u) {
    return base + r * 128 + ((u ^ (r & 7)) << 4);
}

// ---------------------------------------------------------------------------
// Conversions: f32 -> bf16 hi/lo
// ---------------------------------------------------------------------------
__device__ __forceinline__ uint32_t pack2(__nv_bfloat16 a, __nv_bfloat16 b) {
    return (uint32_t)__bfloat16_as_ushort(a) | ((uint32_t)__bfloat16_as_ushort(b) << 16);
}

__global__ __launch_bounds__(256) void convert_split_kernel(
    const float* __restrict__ src, __nv_bfloat16* __restrict__ dh,
    __nv_bfloat16* __restrict__ dl) {
    const int idx = blockIdx.x * 256 + threadIdx.x;   // 8-element unit
    const float4 v0 = *reinterpret_cast<const float4*>(&src[idx * 8]);
    const float4 v1 = *reinterpret_cast<const float4*>(&src[idx * 8 + 4]);
    float v[8] = {v0.x, v0.y, v0.z, v0.w, v1.x, v1.y, v1.z, v1.w};
    __nv_bfloat16 h[8], l[8];
#pragma unroll
    for (int i = 0; i < 8; i++) {
        h[i] = __float2bfloat16(v[i]);
        l[i] = __float2bfloat16(v[i] - __bfloat162float(h[i]));
    }
    uint4 ph = {pack2(h[0], h[1]), pack2(h[2], h[3]), pack2(h[4], h[5]), pack2(h[6], h[7])};
    uint4 pl = {pack2(l[0], l[1]), pack2(l[2], l[3]), pack2(l[4], l[5]), pack2(l[6], l[7])};
    reinterpret_cast<uint4*>(dh)[idx] = ph;
    reinterpret_cast<uint4*>(dl)[idx] = pl;
}

// W [k][n] f32 -> Wt [n][k] bf16 hi/lo (per z matrix)
__global__ __launch_bounds__(256) void convert_wt_kernel(
    const float* __restrict__ Wq, const float* __restrict__ Wk,
    const float* __restrict__ Wv, const float* __restrict__ Wo,
    __nv_bfloat16* __restrict__ dh, __nv_bfloat16* __restrict__ dl) {
    __shared__ float tile[64][65];
    const int z = blockIdx.z;
    const float* W = (z == 0) ? Wq : (z == 1) ? Wk : (z == 2) ? Wv : Wo;
    __nv_bfloat16* oh = dh + (size_t)z * DD * DD;
    __nv_bfloat16* ol = dl + (size_t)z * DD * DD;
    const int k0 = blockIdx.x * 64;
    const int n0 = blockIdx.y * 64;
    const int tid = threadIdx.x;
#pragma unroll
    for (int t = tid; t < 64 * 16; t += 256) {
        const int i = t >> 4;
        const int j4 = (t & 15) * 4;
        const float4 w = *reinterpret_cast<const float4*>(&W[(k0 + i) * DD + n0 + j4]);
        tile[i][j4 + 0] = w.x;
        tile[i][j4 + 1] = w.y;
        tile[i][j4 + 2] = w.z;
        tile[i][j4 + 3] = w.w;
    }
    __syncthreads();
#pragma unroll
    for (int t = tid; t < 64 * 8; t += 256) {
        const int nl = t >> 3;
        const int kin = (t & 7) * 8;
        __nv_bfloat16 h[8], l[8];
#pragma unroll
        for (int m = 0; m < 8; m++) {
            const float v = tile[kin + m][nl];
            h[m] = __float2bfloat16(v);
            l[m] = __float2bfloat16(v - __bfloat162float(h[m]));
        }
        uint4 ph = {pack2(h[0], h[1]), pack2(h[2], h[3]), pack2(h[4], h[5]), pack2(h[6], h[7])};
        uint4 pl = {pack2(l[0], l[1]), pack2(l[2], l[3]), pack2(l[4], l[5]), pack2(l[6], l[7])};
        const size_t d = ((size_t)(n0 + nl) * DD + k0 + kin) >> 3;
        reinterpret_cast<uint4*>(oh)[d] = ph;
        reinterpret_cast<uint4*>(ol)[d] = pl;
    }
}

// ---------------------------------------------------------------------------
// mma.sync bf16 3-split GEMM: C[128x128 tile] = A[8192x768] @ Wt^T + bias
// A: [m][k] row-major hi/lo; B = Wt: [n][k] row-major hi/lo.
// 256 threads = 8 warps (2 m x 4 n), warp tile 64x32, K-tile 64, 2-stage cp.async.
// ---------------------------------------------------------------------------
#define KT 64
#define TILEB 16384                   // 128 rows x 128B
#define STAGEB (4 * TILEB)            // Ah, Al, Bh, Bl
#define GEMM_SMEM (2 * STAGEB)        // 131072

struct GemmArgs {
    const __nv_bfloat16 *Ah, *Al, *Bh, *Bl;
    const float* bias;
    float* C;
};

__device__ __forceinline__ void issue_stage(
    uint32_t sb, const __nv_bfloat16* Ah, const __nv_bfloat16* Al,
    const __nv_bfloat16* Bh, const __nv_bfloat16* Bl,
    int mBase, int nBase, int kBase, int tid) {
    // each tile: 1024 16B-units; 256 threads x 4 units
#pragma unroll
    for (int i = 0; i < 4; i++) {
        const int t2 = tid + i * 256;
        const int r = t2 >> 3;
        const int u = t2 & 7;
        const uint32_t dA = swz(sb, r, u);
        const uint32_t dB = swz(sb + 2 * TILEB, r, u);
        const size_t offA = (size_t)(mBase + r) * DD + kBase + u * 8;
        const size_t offB = (size_t)(nBase + r) * DD + kBase + u * 8;
        cp16(dA, Ah + offA);
        cp16(dA + TILEB, Al + offA);
        cp16(dB, Bh + offB);
        cp16(dB + TILEB, Bl + offB);
    }
}

__device__ __forceinline__ void gemm_mma_body(
    const __nv_bfloat16* __restrict__ Ah, const __nv_bfloat16* __restrict__ Al,
    const __nv_bfloat16* __restrict__ Bh, const __nv_bfloat16* __restrict__ Bl,
    const float* __restrict__ bias, float* __restrict__ C) {
    extern __shared__ char smem[];
    const uint32_t sbase = s2u(smem);

    const int tid = threadIdx.x;
    const int wid = tid >> 5;
    const int lane = tid & 31;
    const int warp_m = wid >> 2;        // 0..1
    const int warp_n = wid & 3;         // 0..3
    const int m0 = warp_m * 64;
    const int n0 = warp_n * 32;
    const int mBase = blockIdx.y * 128;
    const int nBase = blockIdx.x * 128;

    float acc[4][4][4];
#pragma unroll
    for (int i = 0; i < 4; i++)
#pragma unroll
        for (int j = 0; j < 4; j++)
#pragma unroll
            for (int q = 0; q < 4; q++) acc[i][j][q] = 0.0f;

    // prologue: stages 0,1
    issue_stage(sbase, Ah, Al, Bh, Bl, mBase, nBase, 0, tid);
    CP_COMMIT();
    issue_stage(sbase + STAGEB, Ah, Al, Bh, Bl, mBase, nBase, KT, tid);
    CP_COMMIT();

    // precomputed lane fragments
    const int a_r = lane & 15;          // row within 16
    const int a_uh = lane >> 4;         // k half
    const int b_r = ((lane >> 4) & 1) * 8 + (lane & 7);
    const int b_uh = (lane >> 3) & 1;

    for (int kt = 0; kt < DD / KT; kt++) {
        CP_WAIT1();
        __syncthreads();
        const uint32_t st = sbase + (kt & 1) * STAGEB;
        const uint32_t aH = st;
        const uint32_t aL = st + TILEB;
        const uint32_t bH = st + 2 * TILEB;
        const uint32_t bL = st + 3 * TILEB;

#pragma unroll
        for (int ks = 0; ks < 4; ks++) {
            uint32_t ah[4][4], al[4][4], bh[2][4], bl[2][4];
#pragma unroll
            for (int fm = 0; fm < 4; fm++) {
                const int r = m0 + fm * 16 + a_r;
                const int u = ks * 2 + a_uh;
                ldm_x4(ah[fm], swz(aH, r, u));
                ldm_x4(al[fm], swz(aL, r, u));
            }
#pragma unroll
            for (int fn2 = 0; fn2 < 2; fn2++) {
                const int r = n0 + fn2 * 16 + b_r;
                const int u = ks * 2 + b_uh;
                ldm_x4(bh[fn2], swz(bH, r, u));
                ldm_x4(bl[fn2], swz(bL, r, u));
            }
#pragma unroll
            for (int fm = 0; fm < 4; fm++) {
#pragma unroll
                for (int fn = 0; fn < 4; fn++) {
                    const uint32_t* bhp = &bh[fn >> 1][(fn & 1) * 2];
                    const uint32_t* blp = &bl[fn >> 1][(fn & 1) * 2];
                    mma16816(acc[fm][fn], ah[fm], bhp);
                    mma16816(acc[fm][fn], al[fm], bhp);
                    mma16816(acc[fm][fn], ah[fm], blp);
                }
            }
        }
        __syncthreads();
        const int kn = kt + 2;
        if (kn < DD / KT)
            issue_stage(sbase + (kt & 1) * STAGEB, Ah, Al, Bh, Bl,
                        mBase, nBase, kn * KT, tid);
        CP_COMMIT();
    }

    // epilogue: C = acc + bias
    const int row_l = lane >> 2;
    const int col_l = (lane & 3) * 2;
#pragma unroll
    for (int fn = 0; fn < 4; fn++) {
        const int col = nBase + n0 + fn * 8 + col_l;
        const float2 bv = *reinterpret_cast<const float2*>(&bias[col]);
#pragma unroll
        for (int fm = 0; fm < 4; fm++) {
            const int row = mBase + m0 + fm * 16 + row_l;
            float2 o0 = {acc[fm][fn][0] + bv.x, acc[fm][fn][1] + bv.y};
            float2 o1 = {acc[fm][fn][2] + bv.x, acc[fm][fn][3] + bv.y};
            *reinterpret_cast<float2*>(&C[(size_t)row * DD + col]) = o0;
            *reinterpret_cast<float2*>(&C[(size_t)(row + 8) * DD + col]) = o1;
        }
    }
}

__global__ __launch_bounds__(256) void qkv_mma_kernel(
    const __nv_bfloat16* __restrict__ Ah, const __nv_bfloat16* __restrict__ Al,
    const __nv_bfloat16* __restrict__ Wh, const __nv_bfloat16* __restrict__ Wl,
    const float* __restrict__ bq, const float* __restrict__ bk,
    const float* __restrict__ bv, float* __restrict__ q, float* __restrict__ k,
    float* __restrict__ v) {
    const int z = blockIdx.z;
    const size_t ws = (size_t)z * DD * DD;
    const float* bias = (z == 0) ? bq : (z == 1) ? bk : bv;
    float* out = (z == 0) ? q : (z == 1) ? k : v;
    gemm_mma_body(Ah, Al, Wh + ws, Wl + ws, bias, out);
}

__global__ __launch_bounds__(256) void out_mma_kernel(
    const __nv_bfloat16* __restrict__ Ah, const __nv_bfloat16* __restrict__ Al,
    const __nv_bfloat16* __restrict__ Wh, const __nv_bfloat16* __restrict__ Wl,
    const float* __restrict__ bias, float* __restrict__ C) {
    gemm_mma_body(Ah, Al, Wh, Wl, bias, C);
}

// ---------------------------------------------------------------------------
// Fused flash-style attention with QUIET softmax (unchanged from R1, passing)
// ---------------------------------------------------------------------------
#define ATTN_SMEM_FLOATS (128 * 65 * 2 + 64 * 64 * 2)
#define ATTN_SMEM_BYTES (ATTN_SMEM_FLOATS * 4)

__global__ __launch_bounds__(256, 2) void attn_kernel(
    const float* __restrict__ q, const float* __restrict__ k,
    const float* __restrict__ v, float* __restrict__ ctx) {
    extern __shared__ float smemf[];
    float* Qs = smemf;
    float* Ps = Qs + 128 * 65;
    float* Ks = Ps + 128 * 65;
    float* Vs = Ks + 64 * 64;

    const int tid = threadIdx.x;
    const int tx = tid & 15;
    const int ty = tid >> 4;
    const int tx4 = tx * 4;
    const int qt = blockIdx.x;
    const int bh = blockIdx.y;
    const int b = bh / HH;
    const int h = bh - b * HH;
    const int hoff = h * HD;
    const int q0 = b * NN + qt * 128;
    const int krow0 = b * NN;

#pragma unroll
    for (int t = tid; t < 128 * 16; t += 256) {
        const int i = t >> 4;
        const int d4 = (t & 15) * 4;
        float4 qv = *reinterpret_cast<const float4*>(&q[(q0 + i) * DD + hoff + d4]);
        Qs[i * 65 + d4 + 0] = qv.x;
        Qs[i * 65 + d4 + 1] = qv.y;
        Qs[i * 65 + d4 + 2] = qv.z;
        Qs[i * 65 + d4 + 3] = qv.w;
    }

    float m_r[8], l_r[8], acc[8][4];
#pragma unroll
    for (int i = 0; i < 8; i++) {
        m_r[i] = -1e30f;
        l_r[i] = 0.0f;
#pragma unroll
        for (int j = 0; j < 4; j++) acc[i][j] = 0.0f;
    }
    __syncthreads();

    for (int kt = 0; kt < 16; kt++) {
        const int base = krow0 + kt * 64;
#pragma unroll
        for (int t = tid; t < 64 * 16; t += 256) {
            const int j = t >> 4;
            const int d4 = (t & 15) * 4;
            const int swzj = ((d4 >> 2) & 7) * 4;
            float4 kv = *reinterpret_cast<const float4*>(&k[(base + j) * DD + hoff + d4]);
            Ks[(d4 + 0) * 64 + (j ^ swzj)] = kv.x;
            Ks[(d4 + 1) * 64 + (j ^ swzj)] = kv.y;
            Ks[(d4 + 2) * 64 + (j ^ swzj)] = kv.z;
            Ks[(d4 + 3) * 64 + (j ^ swzj)] = kv.w;
            float4 vv = *reinterpret_cast<const float4*>(&v[(base + j) * DD + hoff + d4]);
            *reinterpret_cast<float4*>(&Vs[j * 64 + d4]) = vv;
        }
        __syncthreads();

        float s[8][4];
#pragma unroll
        for (int i = 0; i < 8; i++)
#pragma unroll
            for (int j = 0; j < 4; j++) s[i][j] = 0.0f;

#pragma unroll 4
        for (int d = 0; d < 64; d++) {
            const int swzd = ((d >> 2) & 7) * 4;
            float4 kv = *reinterpret_cast<const float4*>(&Ks[d * 64 + (tx4 ^ swzd)]);
#pragma unroll
            for (int ii = 0; ii < 8; ii++) {
                const float qv = Qs[(ty * 8 + ii) * 65 + d];
                s[ii][0] = fmaf(qv, kv.x, s[ii][0]);
                s[ii][1] = fmaf(qv, kv.y, s[ii][1]);
                s[ii][2] = fmaf(qv, kv.z, s[ii][2]);
                s[ii][3] = fmaf(qv, kv.w, s[ii][3]);
            }
        }

#pragma unroll
        for (int ii = 0; ii < 8; ii++) {
            s[ii][0] *= 0.125f;
            s[ii][1] *= 0.125f;
            s[ii][2] *= 0.125f;
            s[ii][3] *= 0.125f;
            float mx = fmaxf(fmaxf(s[ii][0], s[ii][1]), fmaxf(s[ii][2], s[ii][3]));
            mx = fmaxf(mx, __shfl_xor_sync(0xffffffffu, mx, 8));
            mx = fmaxf(mx, __shfl_xor_sync(0xffffffffu, mx, 4));
            mx = fmaxf(mx, __shfl_xor_sync(0xffffffffu, mx, 2));
            mx = fmaxf(mx, __shfl_xor_sync(0xffffffffu, mx, 1));
            const float mnew = fmaxf(m_r[ii], mx);
            const float corr = __expf(m_r[ii] - mnew);
            float psum = 0.0f;
#pragma unroll
            for (int jj = 0; jj < 4; jj++) {
                const float p = __expf(s[ii][jj] - mnew);
                s[ii][jj] = p;
                psum += p;
            }
            psum += __shfl_xor_sync(0xffffffffu, psum, 8);
            psum += __shfl_xor_sync(0xffffffffu, psum, 4);
            psum += __shfl_xor_sync(0xffffffffu, psum, 2);
            psum += __shfl_xor_sync(0xffffffffu, psum, 1);
            l_r[ii] = l_r[ii] * corr + psum;
            m_r[ii] = mnew;
#pragma unroll
            for (int jj = 0; jj < 4; jj++) acc[ii][jj] *= corr;
            const int prow = (ty * 8 + ii) * 65 + tx4;
            Ps[prow + 0] = s[ii][0];
            Ps[prow + 1] = s[ii][1];
            Ps[prow + 2] = s[ii][2];
            Ps[prow + 3] = s[ii][3];
        }
        __syncthreads();

#pragma unroll 4
        for (int j = 0; j < 64; j++) {
            float4 vv = *reinterpret_cast<const float4*>(&Vs[j * 64 + tx4]);
#pragma unroll
            for (int ii = 0; ii < 8; ii++) {
                const float p = Ps[(ty * 8 + ii) * 65 + j];
                acc[ii][0] = fmaf(p, vv.x, acc[ii][0]);
                acc[ii][1] = fmaf(p, vv.y, acc[ii][1]);
                acc[ii][2] = fmaf(p, vv.z, acc[ii][2]);
                acc[ii][3] = fmaf(p, vv.w, acc[ii][3]);
            }
        }
        __syncthreads();
    }

#pragma unroll
    for (int ii = 0; ii < 8; ii++) {
        const float inv = 1.0f / (1.0f + l_r[ii]);
        const int r = q0 + ty * 8 + ii;
        float4 o;
        o.x = acc[ii][0] * inv;
        o.y = acc[ii][1] * inv;
        o.z = acc[ii][2] * inv;
        o.w = acc[ii][3] * inv;
        *reinterpret_cast<float4*>(&ctx[r * DD + hoff + tx4]) = o;
    }
}

// ---------------------------------------------------------------------------
// Launch
// ---------------------------------------------------------------------------
extern "C" void kernel_launch(void* const* d_in, const int* in_sizes, int n_in,
                              void* d_out, int out_size) {
    const float* x  = (const float*)d_in[0];
    const float* Wq = (const float*)d_in[1];
    const float* bq = (const float*)d_in[2];
    const float* Wk = (const float*)d_in[3];
    const float* bk = (const float*)d_in[4];
    const float* Wv = (const float*)d_in[5];
    const float* bv = (const float*)d_in[6];
    const float* Wo = (const float*)d_in[7];
    const float* bo = (const float*)d_in[8];
    float* out = (float*)d_out;
    (void)in_sizes; (void)n_in; (void)out_size;

    float *q, *k, *v, *ctx;
    __nv_bfloat16 *xh, *xl, *ch, *cl, *wh, *wl;
    cudaGetSymbolAddress((void**)&q, g_q);
    cudaGetSymbolAddress((void**)&k, g_k);
    cudaGetSymbolAddress((void**)&v, g_v);
    cudaGetSymbolAddress((void**)&ctx, g_ctx);
    cudaGetSymbolAddress((void**)&xh, g_xh);
    cudaGetSymbolAddress((void**)&xl, g_xl);
    cudaGetSymbolAddress((void**)&ch, g_ch);
    cudaGetSymbolAddress((void**)&cl, g_cl);
    cudaGetSymbolAddress((void**)&wh, g_wh);
    cudaGetSymbolAddress((void**)&wl, g_wl);

    cudaFuncSetAttribute(attn_kernel, cudaFuncAttributeMaxDynamicSharedMemorySize,
                         ATTN_SMEM_BYTES);
    cudaFuncSetAttribute(qkv_mma_kernel, cudaFuncAttributeMaxDynamicSharedMemorySize,
                         GEMM_SMEM);
    cudaFuncSetAttribute(out_mma_kernel, cudaFuncAttributeMaxDynamicSharedMemorySize,
                         GEMM_SMEM);

    dim3 blk(256);
    convert_split_kernel<<<MM * DD / 8 / 256, blk>>>(x, xh, xl);
    convert_wt_kernel<<<dim3(12, 12, 4), blk>>>(Wq, Wk, Wv, Wo, wh, wl);
    qkv_mma_kernel<<<dim3(6, 64, 3), blk, GEMM_SMEM>>>(xh, xl, wh, wl, bq, bk, bv, q, k, v);
    attn_kernel<<<dim3(8, BB * HH), blk, ATTN_SMEM_BYTES>>>(q, k, v, ctx);
    convert_split_kernel<<<MM * DD / 8 / 256, blk>>>(ctx, ch, cl);
    out_mma_kernel<<<dim3(6, 64), blk, GEMM_SMEM>>>(
        ch, cl, wh + (size_t)3 * DD * DD, wl + (size_t)3 * DD * DD, bo, out);
}

// round 5
// speedup vs baseline: 2.8478x; 1.7576x over previous
#include <cuda_runtime.h>
#include <cuda_bf16.h>
#include <cstdint>

// Problem constants
#define BB 8
#define NN 1024
#define DD 768
#define HH 12
#define HD 64
#define MM (BB * NN)   // 8192 rows
#define SCALEQ 0.18033688011112042591f   // 0.125 * log2(e)

// ---------------------------------------------------------------------------
// Scratch (__device__ globals; no allocation allowed)
// ---------------------------------------------------------------------------
__device__ __nv_bfloat16 g_xh[MM * DD], g_xl[MM * DD];
__device__ __nv_bfloat16 g_qh[MM * DD], g_ql[MM * DD];     // scaled by SCALEQ
__device__ __nv_bfloat16 g_kh[MM * DD], g_kl[MM * DD];
__device__ __nv_bfloat16 g_vth[MM * DD], g_vtl[MM * DD];   // transposed: [(b*768+d)][n]
__device__ __nv_bfloat16 g_ch[MM * DD], g_cl[MM * DD];     // attention output split
__device__ __nv_bfloat16 g_wh[4 * DD * DD], g_wl[4 * DD * DD];

// ---------------------------------------------------------------------------
// PTX helpers
// ---------------------------------------------------------------------------
__device__ __forceinline__ uint32_t s2u(const void* p) {
    uint32_t a;
    asm("{ .reg .u64 t; cvta.to.shared.u64 t, %1; cvt.u32.u64 %0, t; }"
        : "=r"(a) : "l"(p));
    return a;
}
__device__ __forceinline__ void cp16(uint32_t dst, const void* src) {
    asm volatile("cp.async.cg.shared.global [%0], [%1], 16;" :: "r"(dst), "l"(src));
}
#define CP_COMMIT() asm volatile("cp.async.commit_group;" ::: "memory")
#define CP_WAIT1()  asm volatile("cp.async.wait_group 1;" ::: "memory")
#define CP_WAIT2()  asm volatile("cp.async.wait_group 2;" ::: "memory")

__device__ __forceinline__ void ldm_x4(uint32_t* r, uint32_t addr) {
    asm volatile("ldmatrix.sync.aligned.m8n8.x4.shared.b16 {%0,%1,%2,%3}, [%4];"
                 : "=r"(r[0]), "=r"(r[1]), "=r"(r[2]), "=r"(r[3]) : "r"(addr));
}
__device__ __forceinline__ void mma16816(float* c, const uint32_t* a, const uint32_t* b) {
    asm volatile(
        "mma.sync.aligned.m16n8k16.row.col.f32.bf16.bf16.f32 "
        "{%0,%1,%2,%3}, {%4,%5,%6,%7}, {%8,%9}, {%0,%1,%2,%3};"
        : "+f"(c[0]), "+f"(c[1]), "+f"(c[2]), "+f"(c[3])
        : "r"(a[0]), "r"(a[1]), "r"(a[2]), "r"(a[3]), "r"(b[0]), "r"(b[1]));
}
__device__ __forceinline__ float ex2(float x) {
    float y;
    asm("ex2.approx.ftz.f32 %0, %1;" : "=f"(y) : "f"(x));
    return y;
}

// swizzled offsets: rows of 128B (8 units) or 256B (16 units)
__device__ __forceinline__ uint32_t swz8o(int r, int u) {
    return (uint32_t)(r * 128 + ((u ^ (r & 7)) << 4));
}
__device__ __forceinline__ uint32_t swz16o(int r, int u) {
    return (uint32_t)(r * 256 + (((u & 8) | ((u ^ r) & 7)) << 4));
}

__device__ __forceinline__ uint32_t pack2(__nv_bfloat16 a, __nv_bfloat16 b) {
    return (uint32_t)__bfloat16_as_ushort(a) | ((uint32_t)__bfloat16_as_ushort(b) << 16);
}
__device__ __forceinline__ void split2(float x, float y, uint32_t& hi, uint32_t& lo) {
    __nv_bfloat16 hx = __float2bfloat16(x), hy = __float2bfloat16(y);
    __nv_bfloat16 lx = __float2bfloat16(x - __bfloat162float(hx));
    __nv_bfloat16 ly = __float2bfloat16(y - __bfloat162float(hy));
    hi = pack2(hx, hy);
    lo = pack2(lx, ly);
}

// ---------------------------------------------------------------------------
// Conversions
// ---------------------------------------------------------------------------
__global__ __launch_bounds__(256) void convert_split_kernel(
    const float* __restrict__ src, __nv_bfloat16* __restrict__ dh,
    __nv_bfloat16* __restrict__ dl) {
    const int idx = blockIdx.x * 256 + threadIdx.x;
    const float4 v0 = *reinterpret_cast<const float4*>(&src[idx * 8]);
    const float4 v1 = *reinterpret_cast<const float4*>(&src[idx * 8 + 4]);
    float v[8] = {v0.x, v0.y, v0.z, v0.w, v1.x, v1.y, v1.z, v1.w};
    uint4 ph, pl;
    uint32_t* hp = &ph.x;
    uint32_t* lp = &pl.x;
#pragma unroll
    for (int i = 0; i < 4; i++) split2(v[i * 2], v[i * 2 + 1], hp[i], lp[i]);
    reinterpret_cast<uint4*>(dh)[idx] = ph;
    reinterpret_cast<uint4*>(dl)[idx] = pl;
}

__global__ __launch_bounds__(256) void convert_wt_kernel(
    const float* __restrict__ Wq, const float* __restrict__ Wk,
    const float* __restrict__ Wv, const float* __restrict__ Wo,
    __nv_bfloat16* __restrict__ dh, __nv_bfloat16* __restrict__ dl) {
    __shared__ float tile[64][65];
    const int z = blockIdx.z;
    const float* W = (z == 0) ? Wq : (z == 1) ? Wk : (z == 2) ? Wv : Wo;
    __nv_bfloat16* oh = dh + (size_t)z * DD * DD;
    __nv_bfloat16* ol = dl + (size_t)z * DD * DD;
    const int k0 = blockIdx.x * 64;
    const int n0 = blockIdx.y * 64;
    const int tid = threadIdx.x;
#pragma unroll
    for (int t = tid; t < 64 * 16; t += 256) {
        const int i = t >> 4;
        const int j4 = (t & 15) * 4;
        const float4 w = *reinterpret_cast<const float4*>(&W[(k0 + i) * DD + n0 + j4]);
        tile[i][j4 + 0] = w.x;
        tile[i][j4 + 1] = w.y;
        tile[i][j4 + 2] = w.z;
        tile[i][j4 + 3] = w.w;
    }
    __syncthreads();
#pragma unroll
    for (int t = tid; t < 64 * 8; t += 256) {
        const int nl = t >> 3;
        const int kin = (t & 7) * 8;
        uint4 ph, pl;
        uint32_t* hp = &ph.x;
        uint32_t* lp = &pl.x;
#pragma unroll
        for (int m = 0; m < 4; m++)
            split2(tile[kin + m * 2][nl], tile[kin + m * 2 + 1][nl], hp[m], lp[m]);
        const size_t d = ((size_t)(n0 + nl) * DD + k0 + kin) >> 3;
        reinterpret_cast<uint4*>(oh)[d] = ph;
        reinterpret_cast<uint4*>(ol)[d] = pl;
    }
}

// ---------------------------------------------------------------------------
// mma.sync bf16 3-split GEMM with selectable epilogue
// MODE 0: fp32 C = acc + bias
// MODE 1: bf16 hi/lo split of (acc+bias)*scale, row-major
// MODE 2: bf16 hi/lo split of (acc+bias), transposed to vt[(b*768+col)][n]
// ---------------------------------------------------------------------------
#define KT 64
#define TILEB 16384
#define STAGEB (4 * TILEB)
#define GEMM_SMEM (2 * STAGEB)

__device__ __forceinline__ void issue_stage(
    uint32_t sb, const __nv_bfloat16* Ah, const __nv_bfloat16* Al,
    const __nv_bfloat16* Bh, const __nv_bfloat16* Bl,
    int mBase, int nBase, int kBase, int tid) {
#pragma unroll
    for (int i = 0; i < 4; i++) {
        const int t2 = tid + i * 256;
        const int r = t2 >> 3;
        const int u = t2 & 7;
        const uint32_t dA = sb + swz8o(r, u);
        const uint32_t dB = sb + 2 * TILEB + swz8o(r, u);
        const size_t offA = (size_t)(mBase + r) * DD + kBase + u * 8;
        const size_t offB = (size_t)(nBase + r) * DD + kBase + u * 8;
        cp16(dA, Ah + offA);
        cp16(dA + TILEB, Al + offA);
        cp16(dB, Bh + offB);
        cp16(dB + TILEB, Bl + offB);
    }
}

template <int MODE>
__global__ __launch_bounds__(256) void gemm_mma_kernel(
    const __nv_bfloat16* __restrict__ Ah, const __nv_bfloat16* __restrict__ Al,
    const __nv_bfloat16* __restrict__ Bh, const __nv_bfloat16* __restrict__ Bl,
    const float* __restrict__ bias, float scale, float* __restrict__ C,
    __nv_bfloat16* __restrict__ Oh, __nv_bfloat16* __restrict__ Ol) {
    extern __shared__ char smem[];
    const uint32_t sbase = s2u(smem);

    const int tid = threadIdx.x;
    const int wid = tid >> 5;
    const int lane = tid & 31;
    const int m0 = (wid >> 2) * 64;
    const int n0 = (wid & 3) * 32;
    const int mBase = blockIdx.y * 128;
    const int nBase = blockIdx.x * 128;

    float acc[4][4][4];
#pragma unroll
    for (int i = 0; i < 4; i++)
#pragma unroll
        for (int j = 0; j < 4; j++)
#pragma unroll
            for (int q = 0; q < 4; q++) acc[i][j][q] = 0.0f;

    issue_stage(sbase, Ah, Al, Bh, Bl, mBase, nBase, 0, tid);
    CP_COMMIT();
    issue_stage(sbase + STAGEB, Ah, Al, Bh, Bl, mBase, nBase, KT, tid);
    CP_COMMIT();

    const int a_r = lane & 15;
    const int a_uh = lane >> 4;
    const int b_r = ((lane >> 4) & 1) * 8 + (lane & 7);
    const int b_uh = (lane >> 3) & 1;

    for (int kt = 0; kt < DD / KT; kt++) {
        CP_WAIT1();
        __syncthreads();
        const uint32_t st = sbase + (kt & 1) * STAGEB;
#pragma unroll
        for (int ks = 0; ks < 4; ks++) {
            uint32_t ah[4][4], al[4][4], bh[2][4], bl[2][4];
#pragma unroll
            for (int fm = 0; fm < 4; fm++) {
                const int r = m0 + fm * 16 + a_r;
                const int u = ks * 2 + a_uh;
                ldm_x4(ah[fm], st + swz8o(r, u));
                ldm_x4(al[fm], st + TILEB + swz8o(r, u));
            }
#pragma unroll
            for (int fn2 = 0; fn2 < 2; fn2++) {
                const int r = n0 + fn2 * 16 + b_r;
                const int u = ks * 2 + b_uh;
                ldm_x4(bh[fn2], st + 2 * TILEB + swz8o(r, u));
                ldm_x4(bl[fn2], st + 3 * TILEB + swz8o(r, u));
            }
#pragma unroll
            for (int fm = 0; fm < 4; fm++) {
#pragma unroll
                for (int fn = 0; fn < 4; fn++) {
                    const uint32_t* bhp = &bh[fn >> 1][(fn & 1) * 2];
                    const uint32_t* blp = &bl[fn >> 1][(fn & 1) * 2];
                    mma16816(acc[fm][fn], ah[fm], bhp);
                    mma16816(acc[fm][fn], al[fm], bhp);
                    mma16816(acc[fm][fn], ah[fm], blp);
                }
            }
        }
        __syncthreads();
        const int kn = kt + 2;
        if (kn < DD / KT)
            issue_stage(sbase + (kt & 1) * STAGEB, Ah, Al, Bh, Bl,
                        mBase, nBase, kn * KT, tid);
        CP_COMMIT();
    }

    const int row_l = lane >> 2;
    const int col_l = (lane & 3) * 2;
#pragma unroll
    for (int fn = 0; fn < 4; fn++) {
        const int col = nBase + n0 + fn * 8 + col_l;
        const float2 bv = *reinterpret_cast<const float2*>(&bias[col]);
#pragma unroll
        for (int fm = 0; fm < 4; fm++) {
            const int row = mBase + m0 + fm * 16 + row_l;
            float v0 = acc[fm][fn][0] + bv.x;
            float v1 = acc[fm][fn][1] + bv.y;
            float v2 = acc[fm][fn][2] + bv.x;
            float v3 = acc[fm][fn][3] + bv.y;
            if (MODE == 0) {
                *reinterpret_cast<float2*>(&C[(size_t)row * DD + col]) = make_float2(v0, v1);
                *reinterpret_cast<float2*>(&C[(size_t)(row + 8) * DD + col]) = make_float2(v2, v3);
            } else if (MODE == 1) {
                v0 *= scale; v1 *= scale; v2 *= scale; v3 *= scale;
                uint32_t h01, l01, h23, l23;
                split2(v0, v1, h01, l01);
                split2(v2, v3, h23, l23);
                *reinterpret_cast<uint32_t*>(&Oh[(size_t)row * DD + col]) = h01;
                *reinterpret_cast<uint32_t*>(&Ol[(size_t)row * DD + col]) = l01;
                *reinterpret_cast<uint32_t*>(&Oh[(size_t)(row + 8) * DD + col]) = h23;
                *reinterpret_cast<uint32_t*>(&Ol[(size_t)(row + 8) * DD + col]) = l23;
            } else {
                // transposed hi/lo: vt[(b*768+col)][n]
                const int b0 = row >> 10, nn0 = row & 1023;
                const int b1 = (row + 8) >> 10, nn1 = (row + 8) & 1023;
                float vv[4] = {v0, v1, v2, v3};
                const int cols[4] = {col, col + 1, col, col + 1};
                const int bb[4] = {b0, b0, b1, b1};
                const int nn[4] = {nn0, nn0, nn1, nn1};
#pragma unroll
                for (int e = 0; e < 4; e++) {
                    __nv_bfloat16 h = __float2bfloat16(vv[e]);
                    __nv_bfloat16 l = __float2bfloat16(vv[e] - __bfloat162float(h));
                    const size_t d = (size_t)(bb[e] * DD + cols[e]) * NN + nn[e];
                    Oh[d] = h;
                    Ol[d] = l;
                }
            }
        }
    }
}

// ---------------------------------------------------------------------------
// Tensor-core flash attention with quiet softmax (base-2 domain; Q pre-scaled)
// Grid (8 q-tiles, 96 b*h), 256 threads = 8 warps, each warp 16 q-rows.
// K-tile = 128 keys, 2-stage cp.async pipeline.
// smem: [Qh 16K][Ql 16K][stage0: Kh,Kl,Vh,Vl 16K each][stage1: same]
// ---------------------------------------------------------------------------
#define ATTN_SMEM (32768 + 2 * 65536)

__device__ __forceinline__ void attn_issue(
    uint32_t st, const __nv_bfloat16* kh_, const __nv_bfloat16* kl_,
    const __nv_bfloat16* vth_, const __nv_bfloat16* vtl_,
    int b, int hoff, int kt, int tid) {
    const int tok0 = b * NN + kt * 128;
#pragma unroll
    for (int i = 0; i < 8; i++) {   // K: 2048 units (2 arrays x 128 rows x 8)
        const int t = tid + i * 256;
        const int arr = t >> 10, r = (t >> 3) & 127, u = t & 7;
        const __nv_bfloat16* src =
            (arr ? kl_ : kh_) + (size_t)(tok0 + r) * DD + hoff + u * 8;
        cp16(st + arr * 16384 + swz8o(r, u), src);
    }
#pragma unroll
    for (int i = 0; i < 8; i++) {   // V: 2048 units (2 arrays x 64 rows x 16)
        const int t = tid + i * 256;
        const int arr = t >> 10, d = (t >> 4) & 63, u = t & 15;
        const __nv_bfloat16* src =
            (arr ? vtl_ : vth_) + (size_t)(b * DD + hoff + d) * NN + kt * 128 + u * 8;
        cp16(st + 32768 + arr * 16384 + swz16o(d, u), src);
    }
}

__global__ __launch_bounds__(256) void attn_mma_kernel(
    const __nv_bfloat16* __restrict__ qh_, const __nv_bfloat16* __restrict__ ql_,
    const __nv_bfloat16* __restrict__ kh_, const __nv_bfloat16* __restrict__ kl_,
    const __nv_bfloat16* __restrict__ vth_, const __nv_bfloat16* __restrict__ vtl_,
    __nv_bfloat16* __restrict__ ch_, __nv_bfloat16* __restrict__ cl_) {
    extern __shared__ char smem[];
    const uint32_t sb = s2u(smem);
    const int tid = threadIdx.x;
    const int wid = tid >> 5;
    const int lane = tid & 31;
    const int qt = blockIdx.x;
    const int bh = blockIdx.y;
    const int b = bh / HH;
    const int h = bh - b * HH;
    const int hoff = h * HD;
    const int q0 = b * NN + qt * 128;
    const int strip = wid * 16;

    // Q tile (hi+lo) via cp.async
#pragma unroll
    for (int i = 0; i < 8; i++) {
        const int t = tid + i * 256;
        const int arr = t >> 10, r = (t >> 3) & 127, u = t & 7;
        const __nv_bfloat16* src =
            (arr ? ql_ : qh_) + (size_t)(q0 + r) * DD + hoff + u * 8;
        cp16(sb + arr * 16384 + swz8o(r, u), src);
    }
    CP_COMMIT();
    attn_issue(sb + 32768, kh_, kl_, vth_, vtl_, b, hoff, 0, tid);
    CP_COMMIT();
    attn_issue(sb + 32768 + 65536, kh_, kl_, vth_, vtl_, b, hoff, 1, tid);
    CP_COMMIT();
    CP_WAIT2();
    __syncthreads();

    const int a_r = lane & 15;
    const int a_uh = lane >> 4;
    const int b_r = ((lane >> 4) & 1) * 8 + (lane & 7);
    const int b_uh = (lane >> 3) & 1;

    uint32_t qhf[4][4], qlf[4][4];
#pragma unroll
    for (int ks = 0; ks < 4; ks++) {
        const int u = ks * 2 + a_uh;
        ldm_x4(qhf[ks], sb + swz8o(strip + a_r, u));
        ldm_x4(qlf[ks], sb + 16384 + swz8o(strip + a_r, u));
    }

    float mA = -1e30f, mB = -1e30f, lA = 0.0f, lB = 0.0f;
    float ctx[8][4];
#pragma unroll
    for (int i = 0; i < 8; i++)
#pragma unroll
        for (int j = 0; j < 4; j++) ctx[i][j] = 0.0f;

    for (int kt = 0; kt < 8; kt++) {
        CP_WAIT1();
        __syncthreads();
        const uint32_t st = sb + 32768 + (kt & 1) * 65536;

        // ---- S = Q K^T (base-2 logits; Q pre-scaled) ----
        float S[16][4];
#pragma unroll
        for (int i = 0; i < 16; i++)
#pragma unroll
            for (int j = 0; j < 4; j++) S[i][j] = 0.0f;

#pragma unroll
        for (int ks = 0; ks < 4; ks++) {
#pragma unroll
            for (int fn2 = 0; fn2 < 8; fn2++) {
                uint32_t kh4[4], kl4[4];
                const int r = fn2 * 16 + b_r;
                const int u = ks * 2 + b_uh;
                ldm_x4(kh4, st + swz8o(r, u));
                ldm_x4(kl4, st + 16384 + swz8o(r, u));
#pragma unroll
                for (int hf = 0; hf < 2; hf++) {
                    float* c = S[fn2 * 2 + hf];
                    mma16816(c, qhf[ks], &kh4[hf * 2]);
                    mma16816(c, qlf[ks], &kh4[hf * 2]);
                    mma16816(c, qhf[ks], &kl4[hf * 2]);
                }
            }
        }

        // ---- online quiet softmax (rows r = lane>>2 and r+8) ----
        float mxa = -1e30f, mxb = -1e30f;
#pragma unroll
        for (int fn = 0; fn < 16; fn++) {
            mxa = fmaxf(mxa, fmaxf(S[fn][0], S[fn][1]));
            mxb = fmaxf(mxb, fmaxf(S[fn][2], S[fn][3]));
        }
        mxa = fmaxf(mxa, __shfl_xor_sync(0xffffffffu, mxa, 1));
        mxa = fmaxf(mxa, __shfl_xor_sync(0xffffffffu, mxa, 2));
        mxb = fmaxf(mxb, __shfl_xor_sync(0xffffffffu, mxb, 1));
        mxb = fmaxf(mxb, __shfl_xor_sync(0xffffffffu, mxb, 2));
        const float mnA = fmaxf(mA, mxa);
        const float mnB = fmaxf(mB, mxb);
        const float cA = ex2(mA - mnA);
        const float cB = ex2(mB - mnB);
        mA = mnA;
        mB = mnB;
        float pa = 0.0f, pb = 0.0f;
#pragma unroll
        for (int fn = 0; fn < 16; fn++) {
            S[fn][0] = ex2(S[fn][0] - mnA);
            S[fn][1] = ex2(S[fn][1] - mnA);
            S[fn][2] = ex2(S[fn][2] - mnB);
            S[fn][3] = ex2(S[fn][3] - mnB);
            pa += S[fn][0] + S[fn][1];
            pb += S[fn][2] + S[fn][3];
        }
        pa += __shfl_xor_sync(0xffffffffu, pa, 1);
        pa += __shfl_xor_sync(0xffffffffu, pa, 2);
        pb += __shfl_xor_sync(0xffffffffu, pb, 1);
        pb += __shfl_xor_sync(0xffffffffu, pb, 2);
        lA = lA * cA + pa;
        lB = lB * cB + pb;
#pragma unroll
        for (int fn = 0; fn < 8; fn++) {
            ctx[fn][0] *= cA;
            ctx[fn][1] *= cA;
            ctx[fn][2] *= cB;
            ctx[fn][3] *= cB;
        }

        // ---- ctx += P V ----
#pragma unroll
        for (int kb = 0; kb < 8; kb++) {
            uint32_t pah[4], pal[4];
            split2(S[2 * kb][0], S[2 * kb][1], pah[0], pal[0]);
            split2(S[2 * kb][2], S[2 * kb][3], pah[1], pal[1]);
            split2(S[2 * kb + 1][0], S[2 * kb + 1][1], pah[2], pal[2]);
            split2(S[2 * kb + 1][2], S[2 * kb + 1][3], pah[3], pal[3]);
#pragma unroll
            for (int fn2 = 0; fn2 < 4; fn2++) {
                uint32_t vh4[4], vl4[4];
                const int r = fn2 * 16 + b_r;
                const int u = kb * 2 + b_uh;
                ldm_x4(vh4, st + 32768 + swz16o(r, u));
                ldm_x4(vl4, st + 49152 + swz16o(r, u));
#pragma unroll
                for (int hf = 0; hf < 2; hf++) {
                    float* c = ctx[fn2 * 2 + hf];
                    mma16816(c, pah, &vh4[hf * 2]);
                    mma16816(c, pal, &vh4[hf * 2]);
                    mma16816(c, pah, &vl4[hf * 2]);
                }
            }
        }
        __syncthreads();
        if (kt + 2 < 8)
            attn_issue(sb + 32768 + (kt & 1) * 65536, kh_, kl_, vth_, vtl_,
                       b, hoff, kt + 2, tid);
        CP_COMMIT();
    }

    // ---- epilogue: out = ctx / (1 + l); emit bf16 hi/lo ----
    const float iA = 1.0f / (1.0f + lA);
    const float iB = 1.0f / (1.0f + lB);
    const int rowA = q0 + strip + (lane >> 2);
    const int rowB = rowA + 8;
#pragma unroll
    for (int fn = 0; fn < 8; fn++) {
        const int col = hoff + fn * 8 + (lane & 3) * 2;
        uint32_t hA, lA2, hB, lB2;
        split2(ctx[fn][0] * iA, ctx[fn][1] * iA, hA, lA2);
        split2(ctx[fn][2] * iB, ctx[fn][3] * iB, hB, lB2);
        *reinterpret_cast<uint32_t*>(&ch_[(size_t)rowA * DD + col]) = hA;
        *reinterpret_cast<uint32_t*>(&cl_[(size_t)rowA * DD + col]) = lA2;
        *reinterpret_cast<uint32_t*>(&ch_[(size_t)rowB * DD + col]) = hB;
        *reinterpret_cast<uint32_t*>(&cl_[(size_t)rowB * DD + col]) = lB2;
    }
}

// ---------------------------------------------------------------------------
// Launch
// ---------------------------------------------------------------------------
extern "C" void kernel_launch(void* const* d_in, const int* in_sizes, int n_in,
                              void* d_out, int out_size) {
    const float* x  = (const float*)d_in[0];
    const float* Wq = (const float*)d_in[1];
    const float* bq = (const float*)d_in[2];
    const float* Wk = (const float*)d_in[3];
    const float* bk = (const float*)d_in[4];
    const float* Wv = (const float*)d_in[5];
    const float* bv = (const float*)d_in[6];
    const float* Wo = (const float*)d_in[7];
    const float* bo = (const float*)d_in[8];
    float* out = (float*)d_out;
    (void)in_sizes; (void)n_in; (void)out_size;

    __nv_bfloat16 *xh, *xl, *qh, *ql, *kh, *kl, *vth, *vtl, *ch, *cl, *wh, *wl;
    cudaGetSymbolAddress((void**)&xh, g_xh);
    cudaGetSymbolAddress((void**)&xl, g_xl);
    cudaGetSymbolAddress((void**)&qh, g_qh);
    cudaGetSymbolAddress((void**)&ql, g_ql);
    cudaGetSymbolAddress((void**)&kh, g_kh);
    cudaGetSymbolAddress((void**)&kl, g_kl);
    cudaGetSymbolAddress((void**)&vth, g_vth);
    cudaGetSymbolAddress((void**)&vtl, g_vtl);
    cudaGetSymbolAddress((void**)&ch, g_ch);
    cudaGetSymbolAddress((void**)&cl, g_cl);
    cudaGetSymbolAddress((void**)&wh, g_wh);
    cudaGetSymbolAddress((void**)&wl, g_wl);

    cudaFuncSetAttribute(gemm_mma_kernel<0>, cudaFuncAttributeMaxDynamicSharedMemorySize, GEMM_SMEM);
    cudaFuncSetAttribute(gemm_mma_kernel<1>, cudaFuncAttributeMaxDynamicSharedMemorySize, GEMM_SMEM);
    cudaFuncSetAttribute(gemm_mma_kernel<2>, cudaFuncAttributeMaxDynamicSharedMemorySize, GEMM_SMEM);
    cudaFuncSetAttribute(attn_mma_kernel, cudaFuncAttributeMaxDynamicSharedMemorySize, ATTN_SMEM);

    const size_t ws = (size_t)DD * DD;
    dim3 blk(256);
    dim3 gg(6, 64);

    convert_split_kernel<<<MM * DD / 8 / 256, blk>>>(x, xh, xl);
    convert_wt_kernel<<<dim3(12, 12, 4), blk>>>(Wq, Wk, Wv, Wo, wh, wl);
    gemm_mma_kernel<1><<<gg, blk, GEMM_SMEM>>>(xh, xl, wh, wl, bq, SCALEQ,
                                               nullptr, qh, ql);
    gemm_mma_kernel<1><<<gg, blk, GEMM_SMEM>>>(xh, xl, wh + ws, wl + ws, bk, 1.0f,
                                               nullptr, kh, kl);
    gemm_mma_kernel<2><<<gg, blk, GEMM_SMEM>>>(xh, xl, wh + 2 * ws, wl + 2 * ws, bv, 1.0f,
                                               nullptr, vth, vtl);
    attn_mma_kernel<<<dim3(8, BB * HH), blk, ATTN_SMEM>>>(qh, ql, kh, kl, vth, vtl, ch, cl);
    gemm_mma_kernel<0><<<gg, blk, GEMM_SMEM>>>(ch, cl, wh + 3 * ws, wl + 3 * ws, bo, 1.0f,
                                               out, nullptr, nullptr);
}

// round 6
// speedup vs baseline: 3.0139x; 1.0583x over previous
#include <cuda_runtime.h>
#include <cuda_bf16.h>
#include <cstdint>

// Problem constants
#define BB 8
#define NN 1024
#define DD 768
#define HH 12
#define HD 64
#define MM (BB * NN)   // 8192 rows
#define SCALEQ 0.18033688011112042591f   // 0.125 * log2(e)

// ---------------------------------------------------------------------------
// Scratch (__device__ globals; no allocation allowed)
// ---------------------------------------------------------------------------
__device__ __nv_bfloat16 g_xh[MM * DD], g_xl[MM * DD];
__device__ __nv_bfloat16 g_qh[MM * DD], g_ql[MM * DD];     // scaled by SCALEQ
__device__ __nv_bfloat16 g_kh[MM * DD], g_kl[MM * DD];
__device__ __nv_bfloat16 g_vth[MM * DD], g_vtl[MM * DD];   // transposed: [(b*768+d)][n]
__device__ __nv_bfloat16 g_ch[MM * DD], g_cl[MM * DD];     // attention output split
__device__ __nv_bfloat16 g_wh[4 * DD * DD], g_wl[4 * DD * DD];

// ---------------------------------------------------------------------------
// PTX helpers
// ---------------------------------------------------------------------------
__device__ __forceinline__ uint32_t s2u(const void* p) {
    uint32_t a;
    asm("{ .reg .u64 t; cvta.to.shared.u64 t, %1; cvt.u32.u64 %0, t; }"
        : "=r"(a) : "l"(p));
    return a;
}
__device__ __forceinline__ void cp16(uint32_t dst, const void* src) {
    asm volatile("cp.async.cg.shared.global [%0], [%1], 16;" :: "r"(dst), "l"(src));
}
#define CP_COMMIT() asm volatile("cp.async.commit_group;" ::: "memory")
#define CP_WAIT1()  asm volatile("cp.async.wait_group 1;" ::: "memory")
#define CP_WAIT2()  asm volatile("cp.async.wait_group 2;" ::: "memory")

__device__ __forceinline__ void ldm_x4(uint32_t* r, uint32_t addr) {
    asm volatile("ldmatrix.sync.aligned.m8n8.x4.shared.b16 {%0,%1,%2,%3}, [%4];"
                 : "=r"(r[0]), "=r"(r[1]), "=r"(r[2]), "=r"(r[3]) : "r"(addr));
}
__device__ __forceinline__ void mma16816(float* c, const uint32_t* a, const uint32_t* b) {
    asm volatile(
        "mma.sync.aligned.m16n8k16.row.col.f32.bf16.bf16.f32 "
        "{%0,%1,%2,%3}, {%4,%5,%6,%7}, {%8,%9}, {%0,%1,%2,%3};"
        : "+f"(c[0]), "+f"(c[1]), "+f"(c[2]), "+f"(c[3])
        : "r"(a[0]), "r"(a[1]), "r"(a[2]), "r"(a[3]), "r"(b[0]), "r"(b[1]));
}
__device__ __forceinline__ float ex2(float x) {
    float y;
    asm("ex2.approx.ftz.f32 %0, %1;" : "=f"(y) : "f"(x));
    return y;
}

// swizzled offset within a tile of 128B rows (8 16B units per row)
__device__ __forceinline__ uint32_t swz8o(int r, int u) {
    return (uint32_t)(r * 128 + ((u ^ (r & 7)) << 4));
}

__device__ __forceinline__ uint32_t pack2(__nv_bfloat16 a, __nv_bfloat16 b) {
    return (uint32_t)__bfloat16_as_ushort(a) | ((uint32_t)__bfloat16_as_ushort(b) << 16);
}
__device__ __forceinline__ void split2(float x, float y, uint32_t& hi, uint32_t& lo) {
    __nv_bfloat16 hx = __float2bfloat16(x), hy = __float2bfloat16(y);
    __nv_bfloat16 lx = __float2bfloat16(x - __bfloat162float(hx));
    __nv_bfloat16 ly = __float2bfloat16(y - __bfloat162float(hy));
    hi = pack2(hx, hy);
    lo = pack2(lx, ly);
}

// ---------------------------------------------------------------------------
// Conversions
// ---------------------------------------------------------------------------
__global__ __launch_bounds__(256) void convert_split_kernel(
    const float* __restrict__ src, __nv_bfloat16* __restrict__ dh,
    __nv_bfloat16* __restrict__ dl) {
    const int idx = blockIdx.x * 256 + threadIdx.x;
    const float4 v0 = *reinterpret_cast<const float4*>(&src[idx * 8]);
    const float4 v1 = *reinterpret_cast<const float4*>(&src[idx * 8 + 4]);
    float v[8] = {v0.x, v0.y, v0.z, v0.w, v1.x, v1.y, v1.z, v1.w};
    uint4 ph, pl;
    uint32_t* hp = &ph.x;
    uint32_t* lp = &pl.x;
#pragma unroll
    for (int i = 0; i < 4; i++) split2(v[i * 2], v[i * 2 + 1], hp[i], lp[i]);
    reinterpret_cast<uint4*>(dh)[idx] = ph;
    reinterpret_cast<uint4*>(dl)[idx] = pl;
}

__global__ __launch_bounds__(256) void convert_wt_kernel(
    const float* __restrict__ Wq, const float* __restrict__ Wk,
    const float* __restrict__ Wv, const float* __restrict__ Wo,
    __nv_bfloat16* __restrict__ dh, __nv_bfloat16* __restrict__ dl) {
    __shared__ float tile[64][65];
    const int z = blockIdx.z;
    const float* W = (z == 0) ? Wq : (z == 1) ? Wk : (z == 2) ? Wv : Wo;
    __nv_bfloat16* oh = dh + (size_t)z * DD * DD;
    __nv_bfloat16* ol = dl + (size_t)z * DD * DD;
    const int k0 = blockIdx.x * 64;
    const int n0 = blockIdx.y * 64;
    const int tid = threadIdx.x;
#pragma unroll
    for (int t = tid; t < 64 * 16; t += 256) {
        const int i = t >> 4;
        const int j4 = (t & 15) * 4;
        const float4 w = *reinterpret_cast<const float4*>(&W[(k0 + i) * DD + n0 + j4]);
        tile[i][j4 + 0] = w.x;
        tile[i][j4 + 1] = w.y;
        tile[i][j4 + 2] = w.z;
        tile[i][j4 + 3] = w.w;
    }
    __syncthreads();
#pragma unroll
    for (int t = tid; t < 64 * 8; t += 256) {
        const int nl = t >> 3;
        const int kin = (t & 7) * 8;
        uint4 ph, pl;
        uint32_t* hp = &ph.x;
        uint32_t* lp = &pl.x;
#pragma unroll
        for (int m = 0; m < 4; m++)
            split2(tile[kin + m * 2][nl], tile[kin + m * 2 + 1][nl], hp[m], lp[m]);
        const size_t d = ((size_t)(n0 + nl) * DD + k0 + kin) >> 3;
        reinterpret_cast<uint4*>(oh)[d] = ph;
        reinterpret_cast<uint4*>(ol)[d] = pl;
    }
}

// ---------------------------------------------------------------------------
// mma.sync bf16 3-split GEMM.  CTA tile 128m x 256n, 8 warps (2m x 4n),
// warp tile 64x64.  K-tile 64, 2-stage cp.async pipeline.
// stage layout: Ah 16K | Al 16K | Bh 32K | Bl 32K  = 96K;  2 stages = 192K.
// Epilogue modes: 0 = fp32 +bias; 1 = bf16 hi/lo *(scale); 2 = transposed hi/lo.
// ---------------------------------------------------------------------------
#define KT 64
#define GEMM_STAGE 98304
#define GEMM_SMEM (2 * GEMM_STAGE)

__device__ __forceinline__ void gemm_issue(
    uint32_t sb, const __nv_bfloat16* Ah, const __nv_bfloat16* Al,
    const __nv_bfloat16* Bh, const __nv_bfloat16* Bl,
    int mBase, int nBase, int kBase, int tid) {
#pragma unroll
    for (int i = 0; i < 8; i++) {      // A: 2048 units (2 arrays x 128r x 8u)
        const int t = tid + i * 256;
        const int arr = t >> 10, r = (t >> 3) & 127, u = t & 7;
        const __nv_bfloat16* src =
            (arr ? Al : Ah) + (size_t)(mBase + r) * DD + kBase + u * 8;
        cp16(sb + arr * 16384 + swz8o(r, u), src);
    }
#pragma unroll
    for (int i = 0; i < 16; i++) {     // B: 4096 units (2 arrays x 256r x 8u)
        const int t = tid + i * 256;
        const int arr = t >> 11, r = (t >> 3) & 255, u = t & 7;
        const __nv_bfloat16* src =
            (arr ? Bl : Bh) + (size_t)(nBase + r) * DD + kBase + u * 8;
        cp16(sb + 32768 + arr * 32768 + swz8o(r, u), src);
    }
}

__device__ __forceinline__ void gemm_body(
    const __nv_bfloat16* __restrict__ Ah, const __nv_bfloat16* __restrict__ Al,
    const __nv_bfloat16* __restrict__ Bh, const __nv_bfloat16* __restrict__ Bl,
    const float* __restrict__ bias, float scale, int mode,
    float* __restrict__ C, __nv_bfloat16* __restrict__ Oh,
    __nv_bfloat16* __restrict__ Ol) {
    extern __shared__ char smem[];
    const uint32_t sbase = s2u(smem);

    const int tid = threadIdx.x;
    const int wid = tid >> 5;
    const int lane = tid & 31;
    const int m0 = (wid >> 2) * 64;
    const int n0 = (wid & 3) * 64;
    const int mBase = blockIdx.y * 128;
    const int nBase = blockIdx.x * 256;

    float acc[4][8][4];
#pragma unroll
    for (int i = 0; i < 4; i++)
#pragma unroll
        for (int j = 0; j < 8; j++)
#pragma unroll
            for (int q = 0; q < 4; q++) acc[i][j][q] = 0.0f;

    gemm_issue(sbase, Ah, Al, Bh, Bl, mBase, nBase, 0, tid);
    CP_COMMIT();
    gemm_issue(sbase + GEMM_STAGE, Ah, Al, Bh, Bl, mBase, nBase, KT, tid);
    CP_COMMIT();

    const int a_r = lane & 15;
    const int a_uh = lane >> 4;
    const int b_r = ((lane >> 4) & 1) * 8 + (lane & 7);
    const int b_uh = (lane >> 3) & 1;

    for (int kt = 0; kt < DD / KT; kt++) {
        CP_WAIT1();
        __syncthreads();
        const uint32_t st = sbase + (kt & 1) * GEMM_STAGE;
#pragma unroll
        for (int ks = 0; ks < 4; ks++) {
            const int ua = ks * 2 + a_uh;
            const int ub = ks * 2 + b_uh;
            uint32_t ah[4][4], al[4][4];
#pragma unroll
            for (int fm = 0; fm < 4; fm++) {
                const int r = m0 + fm * 16 + a_r;
                ldm_x4(ah[fm], st + swz8o(r, ua));
                ldm_x4(al[fm], st + 16384 + swz8o(r, ua));
            }
#pragma unroll
            for (int fn2 = 0; fn2 < 4; fn2++) {
                uint32_t bh4[4], bl4[4];
                const int r = n0 + fn2 * 16 + b_r;
                ldm_x4(bh4, st + 32768 + swz8o(r, ub));
                ldm_x4(bl4, st + 65536 + swz8o(r, ub));
#pragma unroll
                for (int fm = 0; fm < 4; fm++) {
#pragma unroll
                    for (int hf = 0; hf < 2; hf++) {
                        float* c = acc[fm][fn2 * 2 + hf];
                        mma16816(c, ah[fm], &bh4[hf * 2]);
                        mma16816(c, al[fm], &bh4[hf * 2]);
                        mma16816(c, ah[fm], &bl4[hf * 2]);
                    }
                }
            }
        }
        __syncthreads();
        const int kn = kt + 2;
        if (kn < DD / KT)
            gemm_issue(sbase + (kt & 1) * GEMM_STAGE, Ah, Al, Bh, Bl,
                       mBase, nBase, kn * KT, tid);
        CP_COMMIT();
    }

    const int row_l = lane >> 2;
    const int col_l = (lane & 3) * 2;
#pragma unroll
    for (int fn = 0; fn < 8; fn++) {
        const int col = nBase + n0 + fn * 8 + col_l;
        const float2 bv = *reinterpret_cast<const float2*>(&bias[col]);
#pragma unroll
        for (int fm = 0; fm < 4; fm++) {
            const int row = mBase + m0 + fm * 16 + row_l;
            float v0 = acc[fm][fn][0] + bv.x;
            float v1 = acc[fm][fn][1] + bv.y;
            float v2 = acc[fm][fn][2] + bv.x;
            float v3 = acc[fm][fn][3] + bv.y;
            if (mode == 0) {
                *reinterpret_cast<float2*>(&C[(size_t)row * DD + col]) = make_float2(v0, v1);
                *reinterpret_cast<float2*>(&C[(size_t)(row + 8) * DD + col]) = make_float2(v2, v3);
            } else if (mode == 1) {
                v0 *= scale; v1 *= scale; v2 *= scale; v3 *= scale;
                uint32_t h01, l01, h23, l23;
                split2(v0, v1, h01, l01);
                split2(v2, v3, h23, l23);
                *reinterpret_cast<uint32_t*>(&Oh[(size_t)row * DD + col]) = h01;
                *reinterpret_cast<uint32_t*>(&Ol[(size_t)row * DD + col]) = l01;
                *reinterpret_cast<uint32_t*>(&Oh[(size_t)(row + 8) * DD + col]) = h23;
                *reinterpret_cast<uint32_t*>(&Ol[(size_t)(row + 8) * DD + col]) = l23;
            } else {
                // transposed hi/lo: vt[(b*768+col)][n]
                float vv[4] = {v0, v1, v2, v3};
#pragma unroll
                for (int e = 0; e < 4; e++) {
                    const int rr = row + (e >> 1) * 8;
                    const int cc = col + (e & 1);
                    const int bb = rr >> 10, nn = rr & 1023;
                    __nv_bfloat16 h = __float2bfloat16(vv[e]);
                    __nv_bfloat16 l = __float2bfloat16(vv[e] - __bfloat162float(h));
                    const size_t d = (size_t)(bb * DD + cc) * NN + nn;
                    Oh[d] = h;
                    Ol[d] = l;
                }
            }
        }
    }
}

__global__ __launch_bounds__(256) void qkv_mma_kernel(
    const __nv_bfloat16* __restrict__ Ah, const __nv_bfloat16* __restrict__ Al,
    const __nv_bfloat16* __restrict__ Wh, const __nv_bfloat16* __restrict__ Wl,
    const float* __restrict__ bq, const float* __restrict__ bk,
    const float* __restrict__ bv,
    __nv_bfloat16* __restrict__ qh, __nv_bfloat16* __restrict__ ql,
    __nv_bfloat16* __restrict__ kh, __nv_bfloat16* __restrict__ kl,
    __nv_bfloat16* __restrict__ vth, __nv_bfloat16* __restrict__ vtl) {
    const int z = blockIdx.z;
    const size_t ws = (size_t)z * DD * DD;
    const float* bias = (z == 0) ? bq : (z == 1) ? bk : bv;
    __nv_bfloat16* oh = (z == 0) ? qh : (z == 1) ? kh : vth;
    __nv_bfloat16* ol = (z == 0) ? ql : (z == 1) ? kl : vtl;
    gemm_body(Ah, Al, Wh + ws, Wl + ws, bias, (z == 0) ? SCALEQ : 1.0f,
              (z == 2) ? 2 : 1, nullptr, oh, ol);
}

__global__ __launch_bounds__(256) void out_mma_kernel(
    const __nv_bfloat16* __restrict__ Ah, const __nv_bfloat16* __restrict__ Al,
    const __nv_bfloat16* __restrict__ Wh, const __nv_bfloat16* __restrict__ Wl,
    const float* __restrict__ bias, float* __restrict__ C) {
    gemm_body(Ah, Al, Wh, Wl, bias, 1.0f, 0, C, nullptr, nullptr);
}

// ---------------------------------------------------------------------------
// Tensor-core flash attention, quiet softmax (base-2; Q pre-scaled).
// Block = 256 q-rows of one (b,h); 8 warps x 32 rows; 64-key tiles, 16 iters.
// 4-stage cp.async pipeline.
// smem: Qh 32K | Ql 32K | 4 stages x (Kh 8K | Kl 8K | Vh 8K | Vl 8K)
// ---------------------------------------------------------------------------
#define ATTN_STAGE 32768
#define ATTN_SMEM (65536 + 4 * ATTN_STAGE)   // 196608

__device__ __forceinline__ void attn_issue(
    uint32_t st, const __nv_bfloat16* kh_, const __nv_bfloat16* kl_,
    const __nv_bfloat16* vth_, const __nv_bfloat16* vtl_,
    int b, int hoff, int kt, int tid) {
    const int tok0 = b * NN + kt * 64;
#pragma unroll
    for (int i = 0; i < 4; i++) {   // K: 1024 units (2 arrays x 64 rows x 8u)
        const int t = tid + i * 256;
        const int arr = t >> 9, r = (t >> 3) & 63, u = t & 7;
        const __nv_bfloat16* src =
            (arr ? kl_ : kh_) + (size_t)(tok0 + r) * DD + hoff + u * 8;
        cp16(st + arr * 8192 + swz8o(r, u), src);
    }
#pragma unroll
    for (int i = 0; i < 4; i++) {   // V: 1024 units (2 arrays x 64 d-rows x 8u)
        const int t = tid + i * 256;
        const int arr = t >> 9, r = (t >> 3) & 63, u = t & 7;
        const __nv_bfloat16* src =
            (arr ? vtl_ : vth_) + (size_t)(b * DD + hoff + r) * NN + kt * 64 + u * 8;
        cp16(st + 16384 + arr * 8192 + swz8o(r, u), src);
    }
}

__global__ __launch_bounds__(256) void attn_mma_kernel(
    const __nv_bfloat16* __restrict__ qh_, const __nv_bfloat16* __restrict__ ql_,
    const __nv_bfloat16* __restrict__ kh_, const __nv_bfloat16* __restrict__ kl_,
    const __nv_bfloat16* __restrict__ vth_, const __nv_bfloat16* __restrict__ vtl_,
    __nv_bfloat16* __restrict__ ch_, __nv_bfloat16* __restrict__ cl_) {
    extern __shared__ char smem[];
    const uint32_t sb = s2u(smem);
    const int tid = threadIdx.x;
    const int wid = tid >> 5;
    const int lane = tid & 31;
    const int qt = blockIdx.x;        // 0..3 (256-row tiles)
    const int bh = blockIdx.y;        // 0..95
    const int b = bh / HH;
    const int h = bh - b * HH;
    const int hoff = h * HD;
    const int q0 = b * NN + qt * 256;
    const int strip = wid * 32;

    // Q tile: 4096 units (2 arrays x 256 rows x 8u)
#pragma unroll
    for (int i = 0; i < 16; i++) {
        const int t = tid + i * 256;
        const int arr = t >> 11, r = (t >> 3) & 255, u = t & 7;
        const __nv_bfloat16* src =
            (arr ? ql_ : qh_) + (size_t)(q0 + r) * DD + hoff + u * 8;
        cp16(sb + arr * 32768 + swz8o(r, u), src);
    }
    CP_COMMIT();
    attn_issue(sb + 65536 + 0 * ATTN_STAGE, kh_, kl_, vth_, vtl_, b, hoff, 0, tid);
    CP_COMMIT();
    attn_issue(sb + 65536 + 1 * ATTN_STAGE, kh_, kl_, vth_, vtl_, b, hoff, 1, tid);
    CP_COMMIT();
    attn_issue(sb + 65536 + 2 * ATTN_STAGE, kh_, kl_, vth_, vtl_, b, hoff, 2, tid);
    CP_COMMIT();

    const int a_r = lane & 15;
    const int a_uh = lane >> 4;
    const int b_r = ((lane >> 4) & 1) * 8 + (lane & 7);
    const int b_uh = (lane >> 3) & 1;

    float m_[4], l_[4];
#pragma unroll
    for (int j = 0; j < 4; j++) { m_[j] = -1e30f; l_[j] = 0.0f; }
    float ctx[2][8][4];
#pragma unroll
    for (int fm = 0; fm < 2; fm++)
#pragma unroll
        for (int fn = 0; fn < 8; fn++)
#pragma unroll
            for (int q = 0; q < 4; q++) ctx[fm][fn][q] = 0.0f;

    for (int kt = 0; kt < 16; kt++) {
        CP_WAIT2();
        __syncthreads();
        const uint32_t st = sb + 65536 + (kt & 3) * ATTN_STAGE;

        // ---- S[32 q x 64 keys] = Q K^T ----
        float S[2][8][4];
#pragma unroll
        for (int fm = 0; fm < 2; fm++)
#pragma unroll
            for (int fn = 0; fn < 8; fn++)
#pragma unroll
                for (int q = 0; q < 4; q++) S[fm][fn][q] = 0.0f;

#pragma unroll
        for (int ks = 0; ks < 4; ks++) {
            const int ua = ks * 2 + a_uh;
            const int ub = ks * 2 + b_uh;
            uint32_t qh4[2][4], ql4[2][4];
#pragma unroll
            for (int fm = 0; fm < 2; fm++) {
                const int r = strip + fm * 16 + a_r;
                ldm_x4(qh4[fm], sb + swz8o(r, ua));
                ldm_x4(ql4[fm], sb + 32768 + swz8o(r, ua));
            }
#pragma unroll
            for (int fn2 = 0; fn2 < 4; fn2++) {
                uint32_t kh4[4], kl4[4];
                const int r = fn2 * 16 + b_r;
                ldm_x4(kh4, st + swz8o(r, ub));
                ldm_x4(kl4, st + 8192 + swz8o(r, ub));
#pragma unroll
                for (int fm = 0; fm < 2; fm++) {
#pragma unroll
                    for (int hf = 0; hf < 2; hf++) {
                        float* c = S[fm][fn2 * 2 + hf];
                        mma16816(c, qh4[fm], &kh4[hf * 2]);
                        mma16816(c, ql4[fm], &kh4[hf * 2]);
                        mma16816(c, qh4[fm], &kl4[hf * 2]);
                    }
                }
            }
        }

        // ---- online quiet softmax; 4 row-groups (fm, half) ----
        float mx[4] = {-1e30f, -1e30f, -1e30f, -1e30f};
#pragma unroll
        for (int fm = 0; fm < 2; fm++)
#pragma unroll
            for (int fn = 0; fn < 8; fn++) {
                mx[fm * 2 + 0] = fmaxf(mx[fm * 2 + 0], fmaxf(S[fm][fn][0], S[fm][fn][1]));
                mx[fm * 2 + 1] = fmaxf(mx[fm * 2 + 1], fmaxf(S[fm][fn][2], S[fm][fn][3]));
            }
        float corr[4];
#pragma unroll
        for (int j = 0; j < 4; j++) {
            mx[j] = fmaxf(mx[j], __shfl_xor_sync(0xffffffffu, mx[j], 1));
            mx[j] = fmaxf(mx[j], __shfl_xor_sync(0xffffffffu, mx[j], 2));
            const float mn = fmaxf(m_[j], mx[j]);
            corr[j] = ex2(m_[j] - mn);
            m_[j] = mn;
        }
        float ps[4] = {0.0f, 0.0f, 0.0f, 0.0f};
#pragma unroll
        for (int fm = 0; fm < 2; fm++)
#pragma unroll
            for (int fn = 0; fn < 8; fn++) {
                S[fm][fn][0] = ex2(S[fm][fn][0] - m_[fm * 2]);
                S[fm][fn][1] = ex2(S[fm][fn][1] - m_[fm * 2]);
                S[fm][fn][2] = ex2(S[fm][fn][2] - m_[fm * 2 + 1]);
                S[fm][fn][3] = ex2(S[fm][fn][3] - m_[fm * 2 + 1]);
                ps[fm * 2] += S[fm][fn][0] + S[fm][fn][1];
                ps[fm * 2 + 1] += S[fm][fn][2] + S[fm][fn][3];
            }
#pragma unroll
        for (int j = 0; j < 4; j++) {
            ps[j] += __shfl_xor_sync(0xffffffffu, ps[j], 1);
            ps[j] += __shfl_xor_sync(0xffffffffu, ps[j], 2);
            l_[j] = l_[j] * corr[j] + ps[j];
        }
#pragma unroll
        for (int fm = 0; fm < 2; fm++)
#pragma unroll
            for (int fn = 0; fn < 8; fn++) {
                ctx[fm][fn][0] *= corr[fm * 2];
                ctx[fm][fn][1] *= corr[fm * 2];
                ctx[fm][fn][2] *= corr[fm * 2 + 1];
                ctx[fm][fn][3] *= corr[fm * 2 + 1];
            }

        // ---- ctx += P V ----
#pragma unroll
        for (int kb = 0; kb < 4; kb++) {
            uint32_t pah[2][4], pal[2][4];
#pragma unroll
            for (int fm = 0; fm < 2; fm++) {
                split2(S[fm][2 * kb][0], S[fm][2 * kb][1], pah[fm][0], pal[fm][0]);
                split2(S[fm][2 * kb][2], S[fm][2 * kb][3], pah[fm][1], pal[fm][1]);
                split2(S[fm][2 * kb + 1][0], S[fm][2 * kb + 1][1], pah[fm][2], pal[fm][2]);
                split2(S[fm][2 * kb + 1][2], S[fm][2 * kb + 1][3], pah[fm][3], pal[fm][3]);
            }
            const int ub = kb * 2 + b_uh;
#pragma unroll
            for (int fn2 = 0; fn2 < 4; fn2++) {
                uint32_t vh4[4], vl4[4];
                const int r = fn2 * 16 + b_r;
                ldm_x4(vh4, st + 16384 + swz8o(r, ub));
                ldm_x4(vl4, st + 24576 + swz8o(r, ub));
#pragma unroll
                for (int fm = 0; fm < 2; fm++) {
#pragma unroll
                    for (int hf = 0; hf < 2; hf++) {
                        float* c = ctx[fm][fn2 * 2 + hf];
                        mma16816(c, pah[fm], &vh4[hf * 2]);
                        mma16816(c, pal[fm], &vh4[hf * 2]);
                        mma16816(c, pah[fm], &vl4[hf * 2]);
                    }
                }
            }
        }
        __syncthreads();
        if (kt + 3 < 16)
            attn_issue(sb + 65536 + ((kt + 3) & 3) * ATTN_STAGE,
                       kh_, kl_, vth_, vtl_, b, hoff, kt + 3, tid);
        CP_COMMIT();
    }

    // ---- epilogue: out = ctx / (1 + l); emit bf16 hi/lo ----
    float inv[4];
#pragma unroll
    for (int j = 0; j < 4; j++) inv[j] = 1.0f / (1.0f + l_[j]);
#pragma unroll
    for (int fm = 0; fm < 2; fm++) {
        const int rowA = q0 + strip + fm * 16 + (lane >> 2);
        const int rowB = rowA + 8;
#pragma unroll
        for (int fn = 0; fn < 8; fn++) {
            const int col = hoff + fn * 8 + (lane & 3) * 2;
            uint32_t hA, lA2, hB, lB2;
            split2(ctx[fm][fn][0] * inv[fm * 2], ctx[fm][fn][1] * inv[fm * 2], hA, lA2);
            split2(ctx[fm][fn][2] * inv[fm * 2 + 1], ctx[fm][fn][3] * inv[fm * 2 + 1], hB, lB2);
            *reinterpret_cast<uint32_t*>(&ch_[(size_t)rowA * DD + col]) = hA;
            *reinterpret_cast<uint32_t*>(&cl_[(size_t)rowA * DD + col]) = lA2;
            *reinterpret_cast<uint32_t*>(&ch_[(size_t)rowB * DD + col]) = hB;
            *reinterpret_cast<uint32_t*>(&cl_[(size_t)rowB * DD + col]) = lB2;
        }
    }
}

// ---------------------------------------------------------------------------
// Launch
// ---------------------------------------------------------------------------
extern "C" void kernel_launch(void* const* d_in, const int* in_sizes, int n_in,
                              void* d_out, int out_size) {
    const float* x  = (const float*)d_in[0];
    const float* Wq = (const float*)d_in[1];
    const float* bq = (const float*)d_in[2];
    const float* Wk = (const float*)d_in[3];
    const float* bk = (const float*)d_in[4];
    const float* Wv = (const float*)d_in[5];
    const float* bv = (const float*)d_in[6];
    const float* Wo = (const float*)d_in[7];
    const float* bo = (const float*)d_in[8];
    float* out = (float*)d_out;
    (void)in_sizes; (void)n_in; (void)out_size;

    __nv_bfloat16 *xh, *xl, *qh, *ql, *kh, *kl, *vth, *vtl, *ch, *cl, *wh, *wl;
    cudaGetSymbolAddress((void**)&xh, g_xh);
    cudaGetSymbolAddress((void**)&xl, g_xl);
    cudaGetSymbolAddress((void**)&qh, g_qh);
    cudaGetSymbolAddress((void**)&ql, g_ql);
    cudaGetSymbolAddress((void**)&kh, g_kh);
    cudaGetSymbolAddress((void**)&kl, g_kl);
    cudaGetSymbolAddress((void**)&vth, g_vth);
    cudaGetSymbolAddress((void**)&vtl, g_vtl);
    cudaGetSymbolAddress((void**)&ch, g_ch);
    cudaGetSymbolAddress((void**)&cl, g_cl);
    cudaGetSymbolAddress((void**)&wh, g_wh);
    cudaGetSymbolAddress((void**)&wl, g_wl);

    cudaFuncSetAttribute(qkv_mma_kernel, cudaFuncAttributeMaxDynamicSharedMemorySize, GEMM_SMEM);
    cudaFuncSetAttribute(out_mma_kernel, cudaFuncAttributeMaxDynamicSharedMemorySize, GEMM_SMEM);
    cudaFuncSetAttribute(attn_mma_kernel, cudaFuncAttributeMaxDynamicSharedMemorySize, ATTN_SMEM);

    const size_t ws = (size_t)DD * DD;
    dim3 blk(256);

    convert_split_kernel<<<MM * DD / 8 / 256, blk>>>(x, xh, xl);
    convert_wt_kernel<<<dim3(12, 12, 4), blk>>>(Wq, Wk, Wv, Wo, wh, wl);
    qkv_mma_kernel<<<dim3(3, 64, 3), blk, GEMM_SMEM>>>(xh, xl, wh, wl, bq, bk, bv,
                                                       qh, ql, kh, kl, vth, vtl);
    attn_mma_kernel<<<dim3(4, 96), blk, ATTN_SMEM>>>(qh, ql, kh, kl, vth, vtl, ch, cl);
    out_mma_kernel<<<dim3(3, 64), blk, GEMM_SMEM>>>(ch, cl, wh + 3 * ws, wl + 3 * ws, bo, out);
}

// round 7
// speedup vs baseline: 3.1237x; 1.0364x over previous
#include <cuda_runtime.h>
#include <cuda_bf16.h>
#include <cstdint>

// Problem constants
#define BB 8
#define NN 1024
#define DD 768
#define HH 12
#define HD 64
#define MM (BB * NN)   // 8192 rows
#define SCALEQ 0.18033688011112042591f   // 0.125 * log2(e)

// ---------------------------------------------------------------------------
// Scratch (__device__ globals; no allocation allowed)
// ---------------------------------------------------------------------------
__device__ __nv_bfloat16 g_xh[MM * DD], g_xl[MM * DD];
__device__ __nv_bfloat16 g_qh[MM * DD], g_ql[MM * DD];     // scaled by SCALEQ
__device__ __nv_bfloat16 g_kh[MM * DD], g_kl[MM * DD];
__device__ __nv_bfloat16 g_vth[MM * DD], g_vtl[MM * DD];   // transposed: [(b*768+d)][n]
__device__ __nv_bfloat16 g_ch[MM * DD], g_cl[MM * DD];     // attention output split
__device__ __nv_bfloat16 g_wh[4 * DD * DD], g_wl[4 * DD * DD];

// ---------------------------------------------------------------------------
// PTX helpers
// ---------------------------------------------------------------------------
__device__ __forceinline__ uint32_t s2u(const void* p) {
    uint32_t a;
    asm("{ .reg .u64 t; cvta.to.shared.u64 t, %1; cvt.u32.u64 %0, t; }"
        : "=r"(a) : "l"(p));
    return a;
}
__device__ __forceinline__ void cp16(uint32_t dst, const void* src) {
    asm volatile("cp.async.cg.shared.global [%0], [%1], 16;" :: "r"(dst), "l"(src));
}
#define CP_COMMIT() asm volatile("cp.async.commit_group;" ::: "memory")
#define CP_WAIT1()  asm volatile("cp.async.wait_group 1;" ::: "memory")
#define CP_WAIT2()  asm volatile("cp.async.wait_group 2;" ::: "memory")

__device__ __forceinline__ void ldm_x4(uint32_t* r, uint32_t addr) {
    asm volatile("ldmatrix.sync.aligned.m8n8.x4.shared.b16 {%0,%1,%2,%3}, [%4];"
                 : "=r"(r[0]), "=r"(r[1]), "=r"(r[2]), "=r"(r[3]) : "r"(addr));
}
__device__ __forceinline__ void mma16816(float* c, const uint32_t* a, const uint32_t* b) {
    asm volatile(
        "mma.sync.aligned.m16n8k16.row.col.f32.bf16.bf16.f32 "
        "{%0,%1,%2,%3}, {%4,%5,%6,%7}, {%8,%9}, {%0,%1,%2,%3};"
        : "+f"(c[0]), "+f"(c[1]), "+f"(c[2]), "+f"(c[3])
        : "r"(a[0]), "r"(a[1]), "r"(a[2]), "r"(a[3]), "r"(b[0]), "r"(b[1]));
}
__device__ __forceinline__ float ex2(float x) {
    float y;
    asm("ex2.approx.ftz.f32 %0, %1;" : "=f"(y) : "f"(x));
    return y;
}

// swizzled offset within a tile of 128B rows (8 16B units per row)
__device__ __forceinline__ uint32_t swz8o(int r, int u) {
    return (uint32_t)(r * 128 + ((u ^ (r & 7)) << 4));
}

__device__ __forceinline__ uint32_t pack2(__nv_bfloat16 a, __nv_bfloat16 b) {
    return (uint32_t)__bfloat16_as_ushort(a) | ((uint32_t)__bfloat16_as_ushort(b) << 16);
}
__device__ __forceinline__ void split2(float x, float y, uint32_t& hi, uint32_t& lo) {
    __nv_bfloat16 hx = __float2bfloat16(x), hy = __float2bfloat16(y);
    __nv_bfloat16 lx = __float2bfloat16(x - __bfloat162float(hx));
    __nv_bfloat16 ly = __float2bfloat16(y - __bfloat162float(hy));
    hi = pack2(hx, hy);
    lo = pack2(lx, ly);
}

// ---------------------------------------------------------------------------
// Conversions
// ---------------------------------------------------------------------------
__global__ __launch_bounds__(256) void convert_split_kernel(
    const float* __restrict__ src, __nv_bfloat16* __restrict__ dh,
    __nv_bfloat16* __restrict__ dl) {
    const int idx = blockIdx.x * 256 + threadIdx.x;
    const float4 v0 = *reinterpret_cast<const float4*>(&src[idx * 8]);
    const float4 v1 = *reinterpret_cast<const float4*>(&src[idx * 8 + 4]);
    float v[8] = {v0.x, v0.y, v0.z, v0.w, v1.x, v1.y, v1.z, v1.w};
    uint4 ph, pl;
    uint32_t* hp = &ph.x;
    uint32_t* lp = &pl.x;
#pragma unroll
    for (int i = 0; i < 4; i++) split2(v[i * 2], v[i * 2 + 1], hp[i], lp[i]);
    reinterpret_cast<uint4*>(dh)[idx] = ph;
    reinterpret_cast<uint4*>(dl)[idx] = pl;
}

__global__ __launch_bounds__(256) void convert_wt_kernel(
    const float* __restrict__ Wq, const float* __restrict__ Wk,
    const float* __restrict__ Wv, const float* __restrict__ Wo,
    __nv_bfloat16* __restrict__ dh, __nv_bfloat16* __restrict__ dl) {
    __shared__ float tile[64][65];
    const int z = blockIdx.z;
    const float* W = (z == 0) ? Wq : (z == 1) ? Wk : (z == 2) ? Wv : Wo;
    __nv_bfloat16* oh = dh + (size_t)z * DD * DD;
    __nv_bfloat16* ol = dl + (size_t)z * DD * DD;
    const int k0 = blockIdx.x * 64;
    const int n0 = blockIdx.y * 64;
    const int tid = threadIdx.x;
#pragma unroll
    for (int t = tid; t < 64 * 16; t += 256) {
        const int i = t >> 4;
        const int j4 = (t & 15) * 4;
        const float4 w = *reinterpret_cast<const float4*>(&W[(k0 + i) * DD + n0 + j4]);
        tile[i][j4 + 0] = w.x;
        tile[i][j4 + 1] = w.y;
        tile[i][j4 + 2] = w.z;
        tile[i][j4 + 3] = w.w;
    }
    __syncthreads();
#pragma unroll
    for (int t = tid; t < 64 * 8; t += 256) {
        const int nl = t >> 3;
        const int kin = (t & 7) * 8;
        uint4 ph, pl;
        uint32_t* hp = &ph.x;
        uint32_t* lp = &pl.x;
#pragma unroll
        for (int m = 0; m < 4; m++)
            split2(tile[kin + m * 2][nl], tile[kin + m * 2 + 1][nl], hp[m], lp[m]);
        const size_t d = ((size_t)(n0 + nl) * DD + k0 + kin) >> 3;
        reinterpret_cast<uint4*>(oh)[d] = ph;
        reinterpret_cast<uint4*>(ol)[d] = pl;
    }
}

// ---------------------------------------------------------------------------
// mma.sync bf16 3-split GEMM.  CTA tile 128m x 128n, 8 warps (2m x 4n),
// warp tile 64x32.  K-tile 32 with hi/lo interleaved in each 128B smem row
// (units 0-3 = hi k-chunk, units 4-7 = lo).  3-stage cp.async pipeline,
// 32KB/stage -> 96KB smem -> 2 CTAs/SM.
// Epilogue modes: 0 = fp32 +bias; 1 = bf16 hi/lo *(scale); 2 = transposed hi/lo.
// ---------------------------------------------------------------------------
#define KT 32
#define GEMM_STAGE 32768
#define GEMM_SMEM (3 * GEMM_STAGE)   // 98304

__device__ __forceinline__ void gemm_issue(
    uint32_t sb, const __nv_bfloat16* Ah, const __nv_bfloat16* Al,
    const __nv_bfloat16* Bh, const __nv_bfloat16* Bl,
    int mBase, int nBase, int kBase, int tid) {
#pragma unroll
    for (int i = 0; i < 4; i++) {      // A: 1024 units (2 arr x 128 r x 4 u)
        const int t = tid + i * 256;
        const int arr = t >> 9, r = (t >> 2) & 127, u = t & 3;
        const __nv_bfloat16* src =
            (arr ? Al : Ah) + (size_t)(mBase + r) * DD + kBase + u * 8;
        cp16(sb + swz8o(r, u + arr * 4), src);
    }
#pragma unroll
    for (int i = 0; i < 4; i++) {      // B: 1024 units
        const int t = tid + i * 256;
        const int arr = t >> 9, r = (t >> 2) & 127, u = t & 3;
        const __nv_bfloat16* src =
            (arr ? Bl : Bh) + (size_t)(nBase + r) * DD + kBase + u * 8;
        cp16(sb + 16384 + swz8o(r, u + arr * 4), src);
    }
}

__device__ __forceinline__ void gemm_body(
    const __nv_bfloat16* __restrict__ Ah, const __nv_bfloat16* __restrict__ Al,
    const __nv_bfloat16* __restrict__ Bh, const __nv_bfloat16* __restrict__ Bl,
    const float* __restrict__ bias, float scale, int mode,
    float* __restrict__ C, __nv_bfloat16* __restrict__ Oh,
    __nv_bfloat16* __restrict__ Ol) {
    extern __shared__ char smem[];
    const uint32_t sbase = s2u(smem);

    const int tid = threadIdx.x;
    const int wid = tid >> 5;
    const int lane = tid & 31;
    const int m0 = (wid >> 2) * 64;
    const int n0 = (wid & 3) * 32;
    const int mBase = blockIdx.y * 128;
    const int nBase = blockIdx.x * 128;

    float acc[4][4][4];
#pragma unroll
    for (int i = 0; i < 4; i++)
#pragma unroll
        for (int j = 0; j < 4; j++)
#pragma unroll
            for (int q = 0; q < 4; q++) acc[i][j][q] = 0.0f;

    gemm_issue(sbase, Ah, Al, Bh, Bl, mBase, nBase, 0, tid);
    CP_COMMIT();
    gemm_issue(sbase + GEMM_STAGE, Ah, Al, Bh, Bl, mBase, nBase, KT, tid);
    CP_COMMIT();
    gemm_issue(sbase + 2 * GEMM_STAGE, Ah, Al, Bh, Bl, mBase, nBase, 2 * KT, tid);
    CP_COMMIT();

    const int a_r = lane & 15;
    const int a_uh = lane >> 4;
    const int b_r = ((lane >> 4) & 1) * 8 + (lane & 7);
    const int b_uh = (lane >> 3) & 1;

    const int NKT = DD / KT;   // 24
    int slot = 0;
    for (int kt = 0; kt < NKT; kt++) {
        CP_WAIT2();
        __syncthreads();
        const uint32_t st = sbase + slot * GEMM_STAGE;
#pragma unroll
        for (int ks = 0; ks < 2; ks++) {
            const int ua = ks * 2 + a_uh;    // 0..3 (hi); +4 = lo
            const int ub = ks * 2 + b_uh;
            uint32_t ah[4][4], al[4][4];
#pragma unroll
            for (int fm = 0; fm < 4; fm++) {
                const int r = m0 + fm * 16 + a_r;
                ldm_x4(ah[fm], st + swz8o(r, ua));
                ldm_x4(al[fm], st + swz8o(r, ua + 4));
            }
#pragma unroll
            for (int fn2 = 0; fn2 < 2; fn2++) {
                uint32_t bh4[4], bl4[4];
                const int r = n0 + fn2 * 16 + b_r;
                ldm_x4(bh4, st + 16384 + swz8o(r, ub));
                ldm_x4(bl4, st + 16384 + swz8o(r, ub + 4));
#pragma unroll
                for (int fm = 0; fm < 4; fm++) {
#pragma unroll
                    for (int hf = 0; hf < 2; hf++) {
                        float* c = acc[fm][fn2 * 2 + hf];
                        mma16816(c, ah[fm], &bh4[hf * 2]);
                        mma16816(c, al[fm], &bh4[hf * 2]);
                        mma16816(c, ah[fm], &bl4[hf * 2]);
                    }
                }
            }
        }
        __syncthreads();
        if (kt + 3 < NKT)
            gemm_issue(sbase + slot * GEMM_STAGE, Ah, Al, Bh, Bl,
                       mBase, nBase, (kt + 3) * KT, tid);
        CP_COMMIT();
        slot = (slot == 2) ? 0 : slot + 1;
    }

    const int row_l = lane >> 2;
    const int col_l = (lane & 3) * 2;
#pragma unroll
    for (int fn = 0; fn < 4; fn++) {
        const int col = nBase + n0 + fn * 8 + col_l;
        const float2 bv = *reinterpret_cast<const float2*>(&bias[col]);
#pragma unroll
        for (int fm = 0; fm < 4; fm++) {
            const int row = mBase + m0 + fm * 16 + row_l;
            float v0 = acc[fm][fn][0] + bv.x;
            float v1 = acc[fm][fn][1] + bv.y;
            float v2 = acc[fm][fn][2] + bv.x;
            float v3 = acc[fm][fn][3] + bv.y;
            if (mode == 0) {
                *reinterpret_cast<float2*>(&C[(size_t)row * DD + col]) = make_float2(v0, v1);
                *reinterpret_cast<float2*>(&C[(size_t)(row + 8) * DD + col]) = make_float2(v2, v3);
            } else if (mode == 1) {
                v0 *= scale; v1 *= scale; v2 *= scale; v3 *= scale;
                uint32_t h01, l01, h23, l23;
                split2(v0, v1, h01, l01);
                split2(v2, v3, h23, l23);
                *reinterpret_cast<uint32_t*>(&Oh[(size_t)row * DD + col]) = h01;
                *reinterpret_cast<uint32_t*>(&Ol[(size_t)row * DD + col]) = l01;
                *reinterpret_cast<uint32_t*>(&Oh[(size_t)(row + 8) * DD + col]) = h23;
                *reinterpret_cast<uint32_t*>(&Ol[(size_t)(row + 8) * DD + col]) = l23;
            } else {
                // transposed hi/lo: vt[(b*768+col)][n]
                float vv[4] = {v0, v1, v2, v3};
#pragma unroll
                for (int e = 0; e < 4; e++) {
                    const int rr = row + (e >> 1) * 8;
                    const int cc = col + (e & 1);
                    const int bb = rr >> 10, nn = rr & 1023;
                    __nv_bfloat16 h = __float2bfloat16(vv[e]);
                    __nv_bfloat16 l = __float2bfloat16(vv[e] - __bfloat162float(h));
                    const size_t d = (size_t)(bb * DD + cc) * NN + nn;
                    Oh[d] = h;
                    Ol[d] = l;
                }
            }
        }
    }
}

__global__ __launch_bounds__(256, 2) void qkv_mma_kernel(
    const __nv_bfloat16* __restrict__ Ah, const __nv_bfloat16* __restrict__ Al,
    const __nv_bfloat16* __restrict__ Wh, const __nv_bfloat16* __restrict__ Wl,
    const float* __restrict__ bq, const float* __restrict__ bk,
    const float* __restrict__ bv,
    __nv_bfloat16* __restrict__ qh, __nv_bfloat16* __restrict__ ql,
    __nv_bfloat16* __restrict__ kh, __nv_bfloat16* __restrict__ kl,
    __nv_bfloat16* __restrict__ vth, __nv_bfloat16* __restrict__ vtl) {
    const int z = blockIdx.z;
    const size_t ws = (size_t)z * DD * DD;
    const float* bias = (z == 0) ? bq : (z == 1) ? bk : bv;
    __nv_bfloat16* oh = (z == 0) ? qh : (z == 1) ? kh : vth;
    __nv_bfloat16* ol = (z == 0) ? ql : (z == 1) ? kl : vtl;
    gemm_body(Ah, Al, Wh + ws, Wl + ws, bias, (z == 0) ? SCALEQ : 1.0f,
              (z == 2) ? 2 : 1, nullptr, oh, ol);
}

__global__ __launch_bounds__(256, 2) void out_mma_kernel(
    const __nv_bfloat16* __restrict__ Ah, const __nv_bfloat16* __restrict__ Al,
    const __nv_bfloat16* __restrict__ Wh, const __nv_bfloat16* __restrict__ Wl,
    const float* __restrict__ bias, float* __restrict__ C) {
    gemm_body(Ah, Al, Wh, Wl, bias, 1.0f, 0, C, nullptr, nullptr);
}

// ---------------------------------------------------------------------------
// Tensor-core flash attention, quiet softmax (base-2; Q pre-scaled).
// Block = 128 q-rows of one (b,h); 8 warps x 16 rows; 64-key tiles, 16 iters.
// 2-stage cp.async pipeline, 96KB smem -> 2 CTAs/SM.
// smem: Qh 16K | Ql 16K | 2 stages x (Kh 8K | Kl 8K | Vh 8K | Vl 8K)
// ---------------------------------------------------------------------------
#define ATTN_STAGE 32768
#define ATTN_SMEM (32768 + 2 * ATTN_STAGE)   // 98304

__device__ __forceinline__ void attn_issue(
    uint32_t st, const __nv_bfloat16* kh_, const __nv_bfloat16* kl_,
    const __nv_bfloat16* vth_, const __nv_bfloat16* vtl_,
    int b, int hoff, int kt, int tid) {
    const int tok0 = b * NN + kt * 64;
#pragma unroll
    for (int i = 0; i < 4; i++) {   // K: 1024 units (2 arrays x 64 rows x 8u)
        const int t = tid + i * 256;
        const int arr = t >> 9, r = (t >> 3) & 63, u = t & 7;
        const __nv_bfloat16* src =
            (arr ? kl_ : kh_) + (size_t)(tok0 + r) * DD + hoff + u * 8;
        cp16(st + arr * 8192 + swz8o(r, u), src);
    }
#pragma unroll
    for (int i = 0; i < 4; i++) {   // V: 1024 units (2 arrays x 64 d-rows x 8u)
        const int t = tid + i * 256;
        const int arr = t >> 9, r = (t >> 3) & 63, u = t & 7;
        const __nv_bfloat16* src =
            (arr ? vtl_ : vth_) + (size_t)(b * DD + hoff + r) * NN + kt * 64 + u * 8;
        cp16(st + 16384 + arr * 8192 + swz8o(r, u), src);
    }
}

__global__ __launch_bounds__(256, 2) void attn_mma_kernel(
    const __nv_bfloat16* __restrict__ qh_, const __nv_bfloat16* __restrict__ ql_,
    const __nv_bfloat16* __restrict__ kh_, const __nv_bfloat16* __restrict__ kl_,
    const __nv_bfloat16* __restrict__ vth_, const __nv_bfloat16* __restrict__ vtl_,
    __nv_bfloat16* __restrict__ ch_, __nv_bfloat16* __restrict__ cl_) {
    extern __shared__ char smem[];
    const uint32_t sb = s2u(smem);
    const int tid = threadIdx.x;
    const int wid = tid >> 5;
    const int lane = tid & 31;
    const int qt = blockIdx.x;        // 0..7 (128-row tiles)
    const int bh = blockIdx.y;        // 0..95
    const int b = bh / HH;
    const int h = bh - b * HH;
    const int hoff = h * HD;
    const int q0 = b * NN + qt * 128;
    const int strip = wid * 16;

    // Q tile: 2048 units (2 arrays x 128 rows x 8u)
#pragma unroll
    for (int i = 0; i < 8; i++) {
        const int t = tid + i * 256;
        const int arr = t >> 10, r = (t >> 3) & 127, u = t & 7;
        const __nv_bfloat16* src =
            (arr ? ql_ : qh_) + (size_t)(q0 + r) * DD + hoff + u * 8;
        cp16(sb + arr * 16384 + swz8o(r, u), src);
    }
    CP_COMMIT();
    attn_issue(sb + 32768, kh_, kl_, vth_, vtl_, b, hoff, 0, tid);
    CP_COMMIT();
    attn_issue(sb + 32768 + ATTN_STAGE, kh_, kl_, vth_, vtl_, b, hoff, 1, tid);
    CP_COMMIT();

    const int a_r = lane & 15;
    const int a_uh = lane >> 4;
    const int b_r = ((lane >> 4) & 1) * 8 + (lane & 7);
    const int b_uh = (lane >> 3) & 1;

    float m_[2] = {-1e30f, -1e30f};
    float l_[2] = {0.0f, 0.0f};
    float ctx[8][4];
#pragma unroll
    for (int fn = 0; fn < 8; fn++)
#pragma unroll
        for (int q = 0; q < 4; q++) ctx[fn][q] = 0.0f;

    for (int kt = 0; kt < 16; kt++) {
        CP_WAIT1();
        __syncthreads();
        const uint32_t st = sb + 32768 + (kt & 1) * ATTN_STAGE;

        // ---- S[16 q x 64 keys] = Q K^T ----
        float S[8][4];
#pragma unroll
        for (int fn = 0; fn < 8; fn++)
#pragma unroll
            for (int q = 0; q < 4; q++) S[fn][q] = 0.0f;

#pragma unroll
        for (int ks = 0; ks < 4; ks++) {
            const int ua = ks * 2 + a_uh;
            const int ub = ks * 2 + b_uh;
            uint32_t qh4[4], ql4[4];
            const int rq = strip + a_r;
            ldm_x4(qh4, sb + swz8o(rq, ua));
            ldm_x4(ql4, sb + 16384 + swz8o(rq, ua));
#pragma unroll
            for (int fn2 = 0; fn2 < 4; fn2++) {
                uint32_t kh4[4], kl4[4];
                const int r = fn2 * 16 + b_r;
                ldm_x4(kh4, st + swz8o(r, ub));
                ldm_x4(kl4, st + 8192 + swz8o(r, ub));
#pragma unroll
                for (int hf = 0; hf < 2; hf++) {
                    float* c = S[fn2 * 2 + hf];
                    mma16816(c, qh4, &kh4[hf * 2]);
                    mma16816(c, ql4, &kh4[hf * 2]);
                    mma16816(c, qh4, &kl4[hf * 2]);
                }
            }
        }

        // ---- online quiet softmax; 2 row-groups ----
        float mx[2] = {-1e30f, -1e30f};
#pragma unroll
        for (int fn = 0; fn < 8; fn++) {
            mx[0] = fmaxf(mx[0], fmaxf(S[fn][0], S[fn][1]));
            mx[1] = fmaxf(mx[1], fmaxf(S[fn][2], S[fn][3]));
        }
        float corr[2];
#pragma unroll
        for (int j = 0; j < 2; j++) {
            mx[j] = fmaxf(mx[j], __shfl_xor_sync(0xffffffffu, mx[j], 1));
            mx[j] = fmaxf(mx[j], __shfl_xor_sync(0xffffffffu, mx[j], 2));
            const float mn = fmaxf(m_[j], mx[j]);
            corr[j] = ex2(m_[j] - mn);
            m_[j] = mn;
        }
        float ps[2] = {0.0f, 0.0f};
#pragma unroll
        for (int fn = 0; fn < 8; fn++) {
            S[fn][0] = ex2(S[fn][0] - m_[0]);
            S[fn][1] = ex2(S[fn][1] - m_[0]);
            S[fn][2] = ex2(S[fn][2] - m_[1]);
            S[fn][3] = ex2(S[fn][3] - m_[1]);
            ps[0] += S[fn][0] + S[fn][1];
            ps[1] += S[fn][2] + S[fn][3];
        }
#pragma unroll
        for (int j = 0; j < 2; j++) {
            ps[j] += __shfl_xor_sync(0xffffffffu, ps[j], 1);
            ps[j] += __shfl_xor_sync(0xffffffffu, ps[j], 2);
            l_[j] = l_[j] * corr[j] + ps[j];
        }
#pragma unroll
        for (int fn = 0; fn < 8; fn++) {
            ctx[fn][0] *= corr[0];
            ctx[fn][1] *= corr[0];
            ctx[fn][2] *= corr[1];
            ctx[fn][3] *= corr[1];
        }

        // ---- ctx += P V ----
#pragma unroll
        for (int kb = 0; kb < 4; kb++) {
            uint32_t pah[4], pal[4];
            split2(S[2 * kb][0], S[2 * kb][1], pah[0], pal[0]);
            split2(S[2 * kb][2], S[2 * kb][3], pah[1], pal[1]);
            split2(S[2 * kb + 1][0], S[2 * kb + 1][1], pah[2], pal[2]);
            split2(S[2 * kb + 1][2], S[2 * kb + 1][3], pah[3], pal[3]);
            const int ub = kb * 2 + b_uh;
#pragma unroll
            for (int fn2 = 0; fn2 < 4; fn2++) {
                uint32_t vh4[4], vl4[4];
                const int r = fn2 * 16 + b_r;
                ldm_x4(vh4, st + 16384 + swz8o(r, ub));
                ldm_x4(vl4, st + 24576 + swz8o(r, ub));
#pragma unroll
                for (int hf = 0; hf < 2; hf++) {
                    float* c = ctx[fn2 * 2 + hf];
                    mma16816(c, pah, &vh4[hf * 2]);
                    mma16816(c, pal, &vh4[hf * 2]);
                    mma16816(c, pah, &vl4[hf * 2]);
                }
            }
        }
        __syncthreads();
        if (kt + 2 < 16)
            attn_issue(sb + 32768 + (kt & 1) * ATTN_STAGE,
                       kh_, kl_, vth_, vtl_, b, hoff, kt + 2, tid);
        CP_COMMIT();
    }

    // ---- epilogue: out = ctx / (1 + l); emit bf16 hi/lo ----
    const float inv0 = 1.0f / (1.0f + l_[0]);
    const float inv1 = 1.0f / (1.0f + l_[1]);
    const int rowA = q0 + strip + (lane >> 2);
    const int rowB = rowA + 8;
#pragma unroll
    for (int fn = 0; fn < 8; fn++) {
        const int col = hoff + fn * 8 + (lane & 3) * 2;
        uint32_t hA, lA2, hB, lB2;
        split2(ctx[fn][0] * inv0, ctx[fn][1] * inv0, hA, lA2);
        split2(ctx[fn][2] * inv1, ctx[fn][3] * inv1, hB, lB2);
        *reinterpret_cast<uint32_t*>(&ch_[(size_t)rowA * DD + col]) = hA;
        *reinterpret_cast<uint32_t*>(&cl_[(size_t)rowA * DD + col]) = lA2;
        *reinterpret_cast<uint32_t*>(&ch_[(size_t)rowB * DD + col]) = hB;
        *reinterpret_cast<uint32_t*>(&cl_[(size_t)rowB * DD + col]) = lB2;
    }
}

// ---------------------------------------------------------------------------
// Launch
// ---------------------------------------------------------------------------
extern "C" void kernel_launch(void* const* d_in, const int* in_sizes, int n_in,
                              void* d_out, int out_size) {
    const float* x  = (const float*)d_in[0];
    const float* Wq = (const float*)d_in[1];
    const float* bq = (const float*)d_in[2];
    const float* Wk = (const float*)d_in[3];
    const float* bk = (const float*)d_in[4];
    const float* Wv = (const float*)d_in[5];
    const float* bv = (const float*)d_in[6];
    const float* Wo = (const float*)d_in[7];
    const float* bo = (const float*)d_in[8];
    float* out = (float*)d_out;
    (void)in_sizes; (void)n_in; (void)out_size;

    __nv_bfloat16 *xh, *xl, *qh, *ql, *kh, *kl, *vth, *vtl, *ch, *cl, *wh, *wl;
    cudaGetSymbolAddress((void**)&xh, g_xh);
    cudaGetSymbolAddress((void**)&xl, g_xl);
    cudaGetSymbolAddress((void**)&qh, g_qh);
    cudaGetSymbolAddress((void**)&ql, g_ql);
    cudaGetSymbolAddress((void**)&kh, g_kh);
    cudaGetSymbolAddress((void**)&kl, g_kl);
    cudaGetSymbolAddress((void**)&vth, g_vth);
    cudaGetSymbolAddress((void**)&vtl, g_vtl);
    cudaGetSymbolAddress((void**)&ch, g_ch);
    cudaGetSymbolAddress((void**)&cl, g_cl);
    cudaGetSymbolAddress((void**)&wh, g_wh);
    cudaGetSymbolAddress((void**)&wl, g_wl);

    cudaFuncSetAttribute(qkv_mma_kernel, cudaFuncAttributeMaxDynamicSharedMemorySize, GEMM_SMEM);
    cudaFuncSetAttribute(out_mma_kernel, cudaFuncAttributeMaxDynamicSharedMemorySize, GEMM_SMEM);
    cudaFuncSetAttribute(attn_mma_kernel, cudaFuncAttributeMaxDynamicSharedMemorySize, ATTN_SMEM);

    const size_t ws = (size_t)DD * DD;
    dim3 blk(256);

    convert_split_kernel<<<MM * DD / 8 / 256, blk>>>(x, xh, xl);
    convert_wt_kernel<<<dim3(12, 12, 4), blk>>>(Wq, Wk, Wv, Wo, wh, wl);
    qkv_mma_kernel<<<dim3(6, 64, 3), blk, GEMM_SMEM>>>(xh, xl, wh, wl, bq, bk, bv,
                                                       qh, ql, kh, kl, vth, vtl);
    attn_mma_kernel<<<dim3(8, 96), blk, ATTN_SMEM>>>(qh, ql, kh, kl, vth, vtl, ch, cl);
    out_mma_kernel<<<dim3(6, 64), blk, GEMM_SMEM>>>(ch, cl, wh + 3 * ws, wl + 3 * ws, bo, out);
}

// round 8
// speedup vs baseline: 4.5116x; 1.4443x over previous
#include <cuda_runtime.h>
#include <cuda_fp16.h>
#include <cstdint>

// Problem constants
#define BB 8
#define NN 1024
#define DD 768
#define HH 12
#define HD 64
#define MM (BB * NN)   // 8192 rows
#define SCALEQ 0.18033688011112042591f   // 0.125 * log2(e), applied post-MMA

// ---------------------------------------------------------------------------
// Scratch (__device__ globals; no allocation allowed)
// ---------------------------------------------------------------------------
__device__ __half g_xh[MM * DD], g_xl[MM * DD];   // x split
__device__ __half g_qh[MM * DD], g_ql[MM * DD];   // q split (UNSCALED)
__device__ __half g_k[MM * DD];                   // k single
__device__ __half g_vt[MM * DD];                  // v single, transposed [(b*768+d)][n]
__device__ __half g_ch[MM * DD], g_cl[MM * DD];   // attention output split
__device__ __half g_w[4 * DD * DD];               // weights single, transposed [n][k]

// ---------------------------------------------------------------------------
// PTX helpers
// ---------------------------------------------------------------------------
__device__ __forceinline__ uint32_t s2u(const void* p) {
    uint32_t a;
    asm("{ .reg .u64 t; cvta.to.shared.u64 t, %1; cvt.u32.u64 %0, t; }"
        : "=r"(a) : "l"(p));
    return a;
}
__device__ __forceinline__ void cp16(uint32_t dst, const void* src) {
    asm volatile("cp.async.cg.shared.global [%0], [%1], 16;" :: "r"(dst), "l"(src));
}
#define CP_COMMIT() asm volatile("cp.async.commit_group;" ::: "memory")
#define CP_WAIT1()  asm volatile("cp.async.wait_group 1;" ::: "memory")
#define CP_WAIT2()  asm volatile("cp.async.wait_group 2;" ::: "memory")

__device__ __forceinline__ void ldm_x4(uint32_t* r, uint32_t addr) {
    asm volatile("ldmatrix.sync.aligned.m8n8.x4.shared.b16 {%0,%1,%2,%3}, [%4];"
                 : "=r"(r[0]), "=r"(r[1]), "=r"(r[2]), "=r"(r[3]) : "r"(addr));
}
__device__ __forceinline__ void mma16816(float* c, const uint32_t* a, const uint32_t* b) {
    asm volatile(
        "mma.sync.aligned.m16n8k16.row.col.f32.f16.f16.f32 "
        "{%0,%1,%2,%3}, {%4,%5,%6,%7}, {%8,%9}, {%0,%1,%2,%3};"
        : "+f"(c[0]), "+f"(c[1]), "+f"(c[2]), "+f"(c[3])
        : "r"(a[0]), "r"(a[1]), "r"(a[2]), "r"(a[3]), "r"(b[0]), "r"(b[1]));
}
__device__ __forceinline__ float ex2(float x) {
    float y;
    asm("ex2.approx.ftz.f32 %0, %1;" : "=f"(y) : "f"(x));
    return y;
}

// swizzled offset within a tile of 128B rows (8 16B units per row)
__device__ __forceinline__ uint32_t swz8o(int r, int u) {
    return (uint32_t)(r * 128 + ((u ^ (r & 7)) << 4));
}

__device__ __forceinline__ uint32_t pack2h(__half a, __half b) {
    return (uint32_t)__half_as_ushort(a) | ((uint32_t)__half_as_ushort(b) << 16);
}
__device__ __forceinline__ void split2h(float x, float y, uint32_t& hi, uint32_t& lo) {
    __half hx = __float2half_rn(x), hy = __float2half_rn(y);
    __half lx = __float2half_rn(x - __half2float(hx));
    __half ly = __float2half_rn(y - __half2float(hy));
    hi = pack2h(hx, hy);
    lo = pack2h(lx, ly);
}

// ---------------------------------------------------------------------------
// Conversions
// ---------------------------------------------------------------------------
__global__ __launch_bounds__(256) void convert_split_kernel(
    const float* __restrict__ src, __half* __restrict__ dh,
    __half* __restrict__ dl) {
    const int idx = blockIdx.x * 256 + threadIdx.x;
    const float4 v0 = *reinterpret_cast<const float4*>(&src[idx * 8]);
    const float4 v1 = *reinterpret_cast<const float4*>(&src[idx * 8 + 4]);
    float v[8] = {v0.x, v0.y, v0.z, v0.w, v1.x, v1.y, v1.z, v1.w};
    uint4 ph, pl;
    uint32_t* hp = &ph.x;
    uint32_t* lp = &pl.x;
#pragma unroll
    for (int i = 0; i < 4; i++) split2h(v[i * 2], v[i * 2 + 1], hp[i], lp[i]);
    reinterpret_cast<uint4*>(dh)[idx] = ph;
    reinterpret_cast<uint4*>(dl)[idx] = pl;
}

__global__ __launch_bounds__(256) void convert_wt_kernel(
    const float* __restrict__ Wq, const float* __restrict__ Wk,
    const float* __restrict__ Wv, const float* __restrict__ Wo,
    __half* __restrict__ dw) {
    __shared__ float tile[64][65];
    const int z = blockIdx.z;
    const float* W = (z == 0) ? Wq : (z == 1) ? Wk : (z == 2) ? Wv : Wo;
    __half* ow = dw + (size_t)z * DD * DD;
    const int k0 = blockIdx.x * 64;
    const int n0 = blockIdx.y * 64;
    const int tid = threadIdx.x;
#pragma unroll
    for (int t = tid; t < 64 * 16; t += 256) {
        const int i = t >> 4;
        const int j4 = (t & 15) * 4;
        const float4 w = *reinterpret_cast<const float4*>(&W[(k0 + i) * DD + n0 + j4]);
        tile[i][j4 + 0] = w.x;
        tile[i][j4 + 1] = w.y;
        tile[i][j4 + 2] = w.z;
        tile[i][j4 + 3] = w.w;
    }
    __syncthreads();
#pragma unroll
    for (int t = tid; t < 64 * 8; t += 256) {
        const int nl = t >> 3;
        const int kin = (t & 7) * 8;
        uint4 pw;
        uint32_t* wp = &pw.x;
#pragma unroll
        for (int m = 0; m < 4; m++)
            wp[m] = pack2h(__float2half_rn(tile[kin + m * 2][nl]),
                           __float2half_rn(tile[kin + m * 2 + 1][nl]));
        reinterpret_cast<uint4*>(ow)[((size_t)(n0 + nl) * DD + k0 + kin) >> 3];
        reinterpret_cast<uint4*>(ow)[((size_t)(n0 + nl) * DD + k0 + kin) >> 3] = pw;
    }
}

// ---------------------------------------------------------------------------
// fp16 2-split GEMM: C = (Ah + Al) @ B^T (+bias).  A split fp16, B single fp16.
// CTA tile 128m x 128n, 8 warps (2m x 4n), warp tile 64x32.  KT=64,
// 2-stage cp.async pipeline.  Stage: Ah 16K | Al 16K | B 16K = 48K; x2 = 96K.
// Epilogue modes: 0 fp32+bias; 1 half split; 2 transposed half single; 3 half single.
// ---------------------------------------------------------------------------
#define KT 64
#define GEMM_STAGE 49152
#define GEMM_SMEM (2 * GEMM_STAGE)   // 98304

__device__ __forceinline__ void gemm_issue(
    uint32_t sb, const __half* Ah, const __half* Al, const __half* B,
    int mBase, int nBase, int kBase, int tid) {
#pragma unroll
    for (int i = 0; i < 8; i++) {      // A: 2048 units (2 arr x 128 r x 8 u)
        const int t = tid + i * 256;
        const int arr = t >> 10, r = (t >> 3) & 127, u = t & 7;
        const __half* src =
            (arr ? Al : Ah) + (size_t)(mBase + r) * DD + kBase + u * 8;
        cp16(sb + arr * 16384 + swz8o(r, u), src);
    }
#pragma unroll
    for (int i = 0; i < 4; i++) {      // B: 1024 units (128 r x 8 u)
        const int t = tid + i * 256;
        const int r = (t >> 3) & 127, u = t & 7;
        cp16(sb + 32768 + swz8o(r, u),
             B + (size_t)(nBase + r) * DD + kBase + u * 8);
    }
}

__device__ __forceinline__ void gemm_body(
    const __half* __restrict__ Ah, const __half* __restrict__ Al,
    const __half* __restrict__ B, const float* __restrict__ bias, int mode,
    float* __restrict__ C, __half* __restrict__ Oh, __half* __restrict__ Ol) {
    extern __shared__ char smem[];
    const uint32_t sbase = s2u(smem);

    const int tid = threadIdx.x;
    const int wid = tid >> 5;
    const int lane = tid & 31;
    const int m0 = (wid >> 2) * 64;
    const int n0 = (wid & 3) * 32;
    const int mBase = blockIdx.y * 128;
    const int nBase = blockIdx.x * 128;

    float acc[4][4][4];
#pragma unroll
    for (int i = 0; i < 4; i++)
#pragma unroll
        for (int j = 0; j < 4; j++)
#pragma unroll
            for (int q = 0; q < 4; q++) acc[i][j][q] = 0.0f;

    gemm_issue(sbase, Ah, Al, B, mBase, nBase, 0, tid);
    CP_COMMIT();
    gemm_issue(sbase + GEMM_STAGE, Ah, Al, B, mBase, nBase, KT, tid);
    CP_COMMIT();

    const int a_r = lane & 15;
    const int a_uh = lane >> 4;
    const int b_r = ((lane >> 4) & 1) * 8 + (lane & 7);
    const int b_uh = (lane >> 3) & 1;

    const int NKT = DD / KT;   // 12
    for (int kt = 0; kt < NKT; kt++) {
        CP_WAIT1();
        __syncthreads();
        const uint32_t st = sbase + (kt & 1) * GEMM_STAGE;
#pragma unroll
        for (int ks = 0; ks < 4; ks++) {
            const int ua = ks * 2 + a_uh;
            const int ub = ks * 2 + b_uh;
            uint32_t ah[4][4], al[4][4];
#pragma unroll
            for (int fm = 0; fm < 4; fm++) {
                const int r = m0 + fm * 16 + a_r;
                ldm_x4(ah[fm], st + swz8o(r, ua));
                ldm_x4(al[fm], st + 16384 + swz8o(r, ua));
            }
#pragma unroll
            for (int fn2 = 0; fn2 < 2; fn2++) {
                uint32_t b4[4];
                ldm_x4(b4, st + 32768 + swz8o(n0 + fn2 * 16 + b_r, ub));
#pragma unroll
                for (int fm = 0; fm < 4; fm++) {
#pragma unroll
                    for (int hf = 0; hf < 2; hf++) {
                        float* c = acc[fm][fn2 * 2 + hf];
                        mma16816(c, ah[fm], &b4[hf * 2]);
                        mma16816(c, al[fm], &b4[hf * 2]);
                    }
                }
            }
        }
        __syncthreads();
        if (kt + 2 < NKT)
            gemm_issue(sbase + (kt & 1) * GEMM_STAGE, Ah, Al, B,
                       mBase, nBase, (kt + 2) * KT, tid);
        CP_COMMIT();
    }

    const int row_l = lane >> 2;
    const int col_l = (lane & 3) * 2;
#pragma unroll
    for (int fn = 0; fn < 4; fn++) {
        const int col = nBase + n0 + fn * 8 + col_l;
        const float2 bv = *reinterpret_cast<const float2*>(&bias[col]);
#pragma unroll
        for (int fm = 0; fm < 4; fm++) {
            const int row = mBase + m0 + fm * 16 + row_l;
            float v0 = acc[fm][fn][0] + bv.x;
            float v1 = acc[fm][fn][1] + bv.y;
            float v2 = acc[fm][fn][2] + bv.x;
            float v3 = acc[fm][fn][3] + bv.y;
            if (mode == 0) {
                *reinterpret_cast<float2*>(&C[(size_t)row * DD + col]) = make_float2(v0, v1);
                *reinterpret_cast<float2*>(&C[(size_t)(row + 8) * DD + col]) = make_float2(v2, v3);
            } else if (mode == 1) {
                uint32_t h01, l01, h23, l23;
                split2h(v0, v1, h01, l01);
                split2h(v2, v3, h23, l23);
                *reinterpret_cast<uint32_t*>(&Oh[(size_t)row * DD + col]) = h01;
                *reinterpret_cast<uint32_t*>(&Ol[(size_t)row * DD + col]) = l01;
                *reinterpret_cast<uint32_t*>(&Oh[(size_t)(row + 8) * DD + col]) = h23;
                *reinterpret_cast<uint32_t*>(&Ol[(size_t)(row + 8) * DD + col]) = l23;
            } else if (mode == 3) {
                *reinterpret_cast<uint32_t*>(&Oh[(size_t)row * DD + col]) =
                    pack2h(__float2half_rn(v0), __float2half_rn(v1));
                *reinterpret_cast<uint32_t*>(&Oh[(size_t)(row + 8) * DD + col]) =
                    pack2h(__float2half_rn(v2), __float2half_rn(v3));
            } else {
                // transposed single: vt[(b*768+col)][n]
                float vv[4] = {v0, v1, v2, v3};
#pragma unroll
                for (int e = 0; e < 4; e++) {
                    const int rr = row + (e >> 1) * 8;
                    const int cc = col + (e & 1);
                    const int bb = rr >> 10, nn = rr & 1023;
                    Oh[(size_t)(bb * DD + cc) * NN + nn] = __float2half_rn(vv[e]);
                }
            }
        }
    }
}

__global__ __launch_bounds__(256, 2) void qkv_mma_kernel(
    const __half* __restrict__ Ah, const __half* __restrict__ Al,
    const __half* __restrict__ W,
    const float* __restrict__ bq, const float* __restrict__ bk,
    const float* __restrict__ bv,
    __half* __restrict__ qh, __half* __restrict__ ql,
    __half* __restrict__ k, __half* __restrict__ vt) {
    const int z = blockIdx.z;
    const size_t ws = (size_t)z * DD * DD;
    const float* bias = (z == 0) ? bq : (z == 1) ? bk : bv;
    if (z == 0)
        gemm_body(Ah, Al, W + ws, bias, 1, nullptr, qh, ql);
    else if (z == 1)
        gemm_body(Ah, Al, W + ws, bias, 3, nullptr, k, nullptr);
    else
        gemm_body(Ah, Al, W + ws, bias, 2, nullptr, vt, nullptr);
}

__global__ __launch_bounds__(256, 2) void out_mma_kernel(
    const __half* __restrict__ Ah, const __half* __restrict__ Al,
    const __half* __restrict__ W, const float* __restrict__ bias,
    float* __restrict__ C) {
    gemm_body(Ah, Al, W, bias, 0, C, nullptr, nullptr);
}

// ---------------------------------------------------------------------------
// fp16 tensor-core flash attention, quiet softmax (base-2; scale post-MMA,
// P scaled by 2^10 via exponent offset to keep Pl in fp16 normal range).
// Block = 128 q-rows of one (b,h); 8 warps x 16 rows; 64-key tiles, 16 iters.
// 4-stage pipeline.  smem: Qh 16K | Ql 16K | 4 x (K 8K | V 8K) = 96K.
// ---------------------------------------------------------------------------
#define ATTN_STAGE 16384
#define ATTN_SMEM (32768 + 4 * ATTN_STAGE)   // 98304

__device__ __forceinline__ void attn_issue(
    uint32_t st, const __half* k_, const __half* vt_,
    int b, int hoff, int kt, int tid) {
    const int tok0 = b * NN + kt * 64;
#pragma unroll
    for (int i = 0; i < 2; i++) {   // K: 512 units (64 rows x 8u)
        const int t = tid + i * 256;
        const int r = (t >> 3) & 63, u = t & 7;
        cp16(st + swz8o(r, u), k_ + (size_t)(tok0 + r) * DD + hoff + u * 8);
    }
#pragma unroll
    for (int i = 0; i < 2; i++) {   // V: 512 units (64 d-rows x 8u)
        const int t = tid + i * 256;
        const int r = (t >> 3) & 63, u = t & 7;
        cp16(st + 8192 + swz8o(r, u),
             vt_ + (size_t)(b * DD + hoff + r) * NN + kt * 64 + u * 8);
    }
}

__global__ __launch_bounds__(256, 2) void attn_mma_kernel(
    const __half* __restrict__ qh_, const __half* __restrict__ ql_,
    const __half* __restrict__ k_, const __half* __restrict__ vt_,
    __half* __restrict__ ch_, __half* __restrict__ cl_) {
    extern __shared__ char smem[];
    const uint32_t sb = s2u(smem);
    const int tid = threadIdx.x;
    const int wid = tid >> 5;
    const int lane = tid & 31;
    const int qt = blockIdx.x;        // 0..7 (128-row tiles)
    const int bh = blockIdx.y;        // 0..95
    const int b = bh / HH;
    const int h = bh - b * HH;
    const int hoff = h * HD;
    const int q0 = b * NN + qt * 128;
    const int strip = wid * 16;

    // Q tile: 2048 units (2 arrays x 128 rows x 8u)
#pragma unroll
    for (int i = 0; i < 8; i++) {
        const int t = tid + i * 256;
        const int arr = t >> 10, r = (t >> 3) & 127, u = t & 7;
        const __half* src =
            (arr ? ql_ : qh_) + (size_t)(q0 + r) * DD + hoff + u * 8;
        cp16(sb + arr * 16384 + swz8o(r, u), src);
    }
    CP_COMMIT();
    attn_issue(sb + 32768 + 0 * ATTN_STAGE, k_, vt_, b, hoff, 0, tid);
    CP_COMMIT();
    attn_issue(sb + 32768 + 1 * ATTN_STAGE, k_, vt_, b, hoff, 1, tid);
    CP_COMMIT();
    attn_issue(sb + 32768 + 2 * ATTN_STAGE, k_, vt_, b, hoff, 2, tid);
    CP_COMMIT();

    const int a_r = lane & 15;
    const int a_uh = lane >> 4;
    const int b_r = ((lane >> 4) & 1) * 8 + (lane & 7);
    const int b_uh = (lane >> 3) & 1;

    float m_[2] = {-1e30f, -1e30f};
    float l_[2] = {0.0f, 0.0f};
    float ctx[8][4];
#pragma unroll
    for (int fn = 0; fn < 8; fn++)
#pragma unroll
        for (int q = 0; q < 4; q++) ctx[fn][q] = 0.0f;

    for (int kt = 0; kt < 16; kt++) {
        CP_WAIT2();
        __syncthreads();
        const uint32_t st = sb + 32768 + (kt & 3) * ATTN_STAGE;

        // ---- S[16 q x 64 keys] = Q K^T ----
        float S[8][4];
#pragma unroll
        for (int fn = 0; fn < 8; fn++)
#pragma unroll
            for (int q = 0; q < 4; q++) S[fn][q] = 0.0f;

#pragma unroll
        for (int ks = 0; ks < 4; ks++) {
            const int ua = ks * 2 + a_uh;
            const int ub = ks * 2 + b_uh;
            uint32_t qh4[4], ql4[4];
            const int rq = strip + a_r;
            ldm_x4(qh4, sb + swz8o(rq, ua));
            ldm_x4(ql4, sb + 16384 + swz8o(rq, ua));
#pragma unroll
            for (int fn2 = 0; fn2 < 4; fn2++) {
                uint32_t k4[4];
                ldm_x4(k4, st + swz8o(fn2 * 16 + b_r, ub));
#pragma unroll
                for (int hf = 0; hf < 2; hf++) {
                    float* c = S[fn2 * 2 + hf];
                    mma16816(c, qh4, &k4[hf * 2]);
                    mma16816(c, ql4, &k4[hf * 2]);
                }
            }
        }

        // ---- scale to base-2 logits; online quiet softmax (P scaled 2^10) ----
        float mx[2] = {-1e30f, -1e30f};
#pragma unroll
        for (int fn = 0; fn < 8; fn++) {
            S[fn][0] *= SCALEQ;
            S[fn][1] *= SCALEQ;
            S[fn][2] *= SCALEQ;
            S[fn][3] *= SCALEQ;
            mx[0] = fmaxf(mx[0], fmaxf(S[fn][0], S[fn][1]));
            mx[1] = fmaxf(mx[1], fmaxf(S[fn][2], S[fn][3]));
        }
        float corr[2];
#pragma unroll
        for (int j = 0; j < 2; j++) {
            mx[j] = fmaxf(mx[j], __shfl_xor_sync(0xffffffffu, mx[j], 1));
            mx[j] = fmaxf(mx[j], __shfl_xor_sync(0xffffffffu, mx[j], 2));
            const float mn = fmaxf(m_[j], mx[j]);
            corr[j] = ex2(m_[j] - mn);
            m_[j] = mn;
        }
        float ps[2] = {0.0f, 0.0f};
#pragma unroll
        for (int fn = 0; fn < 8; fn++) {
            S[fn][0] = ex2(S[fn][0] - m_[0] + 10.0f);
            S[fn][1] = ex2(S[fn][1] - m_[0] + 10.0f);
            S[fn][2] = ex2(S[fn][2] - m_[1] + 10.0f);
            S[fn][3] = ex2(S[fn][3] - m_[1] + 10.0f);
            ps[0] += S[fn][0] + S[fn][1];
            ps[1] += S[fn][2] + S[fn][3];
        }
#pragma unroll
        for (int j = 0; j < 2; j++) {
            ps[j] += __shfl_xor_sync(0xffffffffu, ps[j], 1);
            ps[j] += __shfl_xor_sync(0xffffffffu, ps[j], 2);
            l_[j] = l_[j] * corr[j] + ps[j];
        }
#pragma unroll
        for (int fn = 0; fn < 8; fn++) {
            ctx[fn][0] *= corr[0];
            ctx[fn][1] *= corr[0];
            ctx[fn][2] *= corr[1];
            ctx[fn][3] *= corr[1];
        }

        // ---- ctx += P' V  (P' split fp16, V single) ----
#pragma unroll
        for (int kb = 0; kb < 4; kb++) {
            uint32_t pah[4], pal[4];
            split2h(S[2 * kb][0], S[2 * kb][1], pah[0], pal[0]);
            split2h(S[2 * kb][2], S[2 * kb][3], pah[1], pal[1]);
            split2h(S[2 * kb + 1][0], S[2 * kb + 1][1], pah[2], pal[2]);
            split2h(S[2 * kb + 1][2], S[2 * kb + 1][3], pah[3], pal[3]);
            const int ub = kb * 2 + b_uh;
#pragma unroll
            for (int fn2 = 0; fn2 < 4; fn2++) {
                uint32_t v4[4];
                ldm_x4(v4, st + 8192 + swz8o(fn2 * 16 + b_r, ub));
#pragma unroll
                for (int hf = 0; hf < 2; hf++) {
                    float* c = ctx[fn2 * 2 + hf];
                    mma16816(c, pah, &v4[hf * 2]);
                    mma16816(c, pal, &v4[hf * 2]);
                }
            }
        }
        __syncthreads();
        if (kt + 3 < 16)
            attn_issue(sb + 32768 + ((kt + 3) & 3) * ATTN_STAGE,
                       k_, vt_, b, hoff, kt + 3, tid);
        CP_COMMIT();
    }

    // ---- epilogue: out = ctx' / (1024 + l'); emit half hi/lo ----
    const float inv0 = 1.0f / (1024.0f + l_[0]);
    const float inv1 = 1.0f / (1024.0f + l_[1]);
    const int rowA = q0 + strip + (lane >> 2);
    const int rowB = rowA + 8;
#pragma unroll
    for (int fn = 0; fn < 8; fn++) {
        const int col = hoff + fn * 8 + (lane & 3) * 2;
        uint32_t hA, lA2, hB, lB2;
        split2h(ctx[fn][0] * inv0, ctx[fn][1] * inv0, hA, lA2);
        split2h(ctx[fn][2] * inv1, ctx[fn][3] * inv1, hB, lB2);
        *reinterpret_cast<uint32_t*>(&ch_[(size_t)rowA * DD + col]) = hA;
        *reinterpret_cast<uint32_t*>(&cl_[(size_t)rowA * DD + col]) = lA2;
        *reinterpret_cast<uint32_t*>(&ch_[(size_t)rowB * DD + col]) = hB;
        *reinterpret_cast<uint32_t*>(&cl_[(size_t)rowB * DD + col]) = lB2;
    }
}

// ---------------------------------------------------------------------------
// Launch
// ---------------------------------------------------------------------------
extern "C" void kernel_launch(void* const* d_in, const int* in_sizes, int n_in,
                              void* d_out, int out_size) {
    const float* x  = (const float*)d_in[0];
    const float* Wq = (const float*)d_in[1];
    const float* bq = (const float*)d_in[2];
    const float* Wk = (const float*)d_in[3];
    const float* bk = (const float*)d_in[4];
    const float* Wv = (const float*)d_in[5];
    const float* bv = (const float*)d_in[6];
    const float* Wo = (const float*)d_in[7];
    const float* bo = (const float*)d_in[8];
    float* out = (float*)d_out;
    (void)in_sizes; (void)n_in; (void)out_size;

    __half *xh, *xl, *qh, *ql, *k, *vt, *ch, *cl, *w;
    cudaGetSymbolAddress((void**)&xh, g_xh);
    cudaGetSymbolAddress((void**)&xl, g_xl);
    cudaGetSymbolAddress((void**)&qh, g_qh);
    cudaGetSymbolAddress((void**)&ql, g_ql);
    cudaGetSymbolAddress((void**)&k, g_k);
    cudaGetSymbolAddress((void**)&vt, g_vt);
    cudaGetSymbolAddress((void**)&ch, g_ch);
    cudaGetSymbolAddress((void**)&cl, g_cl);
    cudaGetSymbolAddress((void**)&w, g_w);

    cudaFuncSetAttribute(qkv_mma_kernel, cudaFuncAttributeMaxDynamicSharedMemorySize, GEMM_SMEM);
    cudaFuncSetAttribute(out_mma_kernel, cudaFuncAttributeMaxDynamicSharedMemorySize, GEMM_SMEM);
    cudaFuncSetAttribute(attn_mma_kernel, cudaFuncAttributeMaxDynamicSharedMemorySize, ATTN_SMEM);

    const size_t ws = (size_t)DD * DD;
    dim3 blk(256);

    convert_split_kernel<<<MM * DD / 8 / 256, blk>>>(x, xh, xl);
    convert_wt_kernel<<<dim3(12, 12, 4), blk>>>(Wq, Wk, Wv, Wo, w);
    qkv_mma_kernel<<<dim3(6, 64, 3), blk, GEMM_SMEM>>>(xh, xl, w, bq, bk, bv,
                                                       qh, ql, k, vt);
    attn_mma_kernel<<<dim3(8, 96), blk, ATTN_SMEM>>>(qh, ql, k, vt, ch, cl);
    out_mma_kernel<<<dim3(6, 64), blk, GEMM_SMEM>>>(ch, cl, w + 3 * ws, bo, out);
}

// round 9
// speedup vs baseline: 5.0034x; 1.1090x over previous
#include <cuda_runtime.h>
#include <cuda_fp16.h>
#include <cstdint>

// Problem constants
#define BB 8
#define NN 1024
#define DD 768
#define HH 12
#define HD 64
#define MM (BB * NN)   // 8192 rows
#define SCALEQ 0.18033688011112042591f   // 0.125 * log2(e), applied post-MMA

// ---------------------------------------------------------------------------
// Scratch (__device__ globals; no allocation allowed)
// ---------------------------------------------------------------------------
__device__ __half g_xh[MM * DD], g_xl[MM * DD];   // x split
__device__ __half g_qh[MM * DD], g_ql[MM * DD];   // q split (UNSCALED)
__device__ __half g_k[MM * DD];                   // k single
__device__ __half g_vt[MM * DD];                  // v single, transposed [(b*768+d)][n]
__device__ __half g_ch[MM * DD], g_cl[MM * DD];   // attention output split
__device__ __half g_w[4 * DD * DD];               // weights single, transposed [n][k]

// ---------------------------------------------------------------------------
// PTX helpers
// ---------------------------------------------------------------------------
__device__ __forceinline__ uint32_t s2u(const void* p) {
    uint32_t a;
    asm("{ .reg .u64 t; cvta.to.shared.u64 t, %1; cvt.u32.u64 %0, t; }"
        : "=r"(a) : "l"(p));
    return a;
}
__device__ __forceinline__ void cp16(uint32_t dst, const void* src) {
    asm volatile("cp.async.cg.shared.global [%0], [%1], 16;" :: "r"(dst), "l"(src));
}
#define CP_COMMIT() asm volatile("cp.async.commit_group;" ::: "memory")
#define CP_WAIT1()  asm volatile("cp.async.wait_group 1;" ::: "memory")
#define CP_WAIT2()  asm volatile("cp.async.wait_group 2;" ::: "memory")

__device__ __forceinline__ void ldm_x4(uint32_t* r, uint32_t addr) {
    asm volatile("ldmatrix.sync.aligned.m8n8.x4.shared.b16 {%0,%1,%2,%3}, [%4];"
                 : "=r"(r[0]), "=r"(r[1]), "=r"(r[2]), "=r"(r[3]) : "r"(addr));
}
__device__ __forceinline__ void mma16816(float* c, const uint32_t* a, const uint32_t* b) {
    asm volatile(
        "mma.sync.aligned.m16n8k16.row.col.f32.f16.f16.f32 "
        "{%0,%1,%2,%3}, {%4,%5,%6,%7}, {%8,%9}, {%0,%1,%2,%3};"
        : "+f"(c[0]), "+f"(c[1]), "+f"(c[2]), "+f"(c[3])
        : "r"(a[0]), "r"(a[1]), "r"(a[2]), "r"(a[3]), "r"(b[0]), "r"(b[1]));
}
__device__ __forceinline__ float ex2(float x) {
    float y;
    asm("ex2.approx.ftz.f32 %0, %1;" : "=f"(y) : "f"(x));
    return y;
}

// swizzled offset within a tile of 128B rows (8 16B units per row)
__device__ __forceinline__ uint32_t swz8o(int r, int u) {
    return (uint32_t)(r * 128 + ((u ^ (r & 7)) << 4));
}

__device__ __forceinline__ uint32_t pack2h(__half a, __half b) {
    return (uint32_t)__half_as_ushort(a) | ((uint32_t)__half_as_ushort(b) << 16);
}
__device__ __forceinline__ void split2h(float x, float y, uint32_t& hi, uint32_t& lo) {
    __half hx = __float2half_rn(x), hy = __float2half_rn(y);
    __half lx = __float2half_rn(x - __half2float(hx));
    __half ly = __float2half_rn(y - __half2float(hy));
    hi = pack2h(hx, hy);
    lo = pack2h(lx, ly);
}

// ---------------------------------------------------------------------------
// Conversions
// ---------------------------------------------------------------------------
__global__ __launch_bounds__(256) void convert_split_kernel(
    const float* __restrict__ src, __half* __restrict__ dh,
    __half* __restrict__ dl) {
    const int idx = blockIdx.x * 256 + threadIdx.x;
    const float4 v0 = *reinterpret_cast<const float4*>(&src[idx * 8]);
    const float4 v1 = *reinterpret_cast<const float4*>(&src[idx * 8 + 4]);
    float v[8] = {v0.x, v0.y, v0.z, v0.w, v1.x, v1.y, v1.z, v1.w};
    uint4 ph, pl;
    uint32_t* hp = &ph.x;
    uint32_t* lp = &pl.x;
#pragma unroll
    for (int i = 0; i < 4; i++) split2h(v[i * 2], v[i * 2 + 1], hp[i], lp[i]);
    reinterpret_cast<uint4*>(dh)[idx] = ph;
    reinterpret_cast<uint4*>(dl)[idx] = pl;
}

__global__ __launch_bounds__(256) void convert_wt_kernel(
    const float* __restrict__ Wq, const float* __restrict__ Wk,
    const float* __restrict__ Wv, const float* __restrict__ Wo,
    __half* __restrict__ dw) {
    __shared__ float tile[64][65];
    const int z = blockIdx.z;
    const float* W = (z == 0) ? Wq : (z == 1) ? Wk : (z == 2) ? Wv : Wo;
    __half* ow = dw + (size_t)z * DD * DD;
    const int k0 = blockIdx.x * 64;
    const int n0 = blockIdx.y * 64;
    const int tid = threadIdx.x;
#pragma unroll
    for (int t = tid; t < 64 * 16; t += 256) {
        const int i = t >> 4;
        const int j4 = (t & 15) * 4;
        const float4 w = *reinterpret_cast<const float4*>(&W[(k0 + i) * DD + n0 + j4]);
        tile[i][j4 + 0] = w.x;
        tile[i][j4 + 1] = w.y;
        tile[i][j4 + 2] = w.z;
        tile[i][j4 + 3] = w.w;
    }
    __syncthreads();
#pragma unroll
    for (int t = tid; t < 64 * 8; t += 256) {
        const int nl = t >> 3;
        const int kin = (t & 7) * 8;
        uint4 pw;
        uint32_t* wp = &pw.x;
#pragma unroll
        for (int m = 0; m < 4; m++)
            wp[m] = pack2h(__float2half_rn(tile[kin + m * 2][nl]),
                           __float2half_rn(tile[kin + m * 2 + 1][nl]));
        reinterpret_cast<uint4*>(ow)[((size_t)(n0 + nl) * DD + k0 + kin) >> 3] = pw;
    }
}

// ---------------------------------------------------------------------------
// fp16 2-split GEMM: C = (Ah + Al) @ B^T (+bias).  A split fp16, B single fp16.
// CTA tile 128m x 128n, 8 warps (2m x 4n), warp tile 64x32.  KT=64,
// 2-stage cp.async pipeline.  Stage: Ah 16K | Al 16K | B 16K = 48K; x2 = 96K.
// Epilogue modes: 0 fp32+bias; 1 half split; 2 transposed half single; 3 half single.
// ---------------------------------------------------------------------------
#define KT 64
#define GEMM_STAGE 49152
#define GEMM_SMEM (2 * GEMM_STAGE)   // 98304

__device__ __forceinline__ void gemm_issue(
    uint32_t sb, const __half* Ah, const __half* Al, const __half* B,
    int mBase, int nBase, int kBase, int tid) {
#pragma unroll
    for (int i = 0; i < 8; i++) {      // A: 2048 units (2 arr x 128 r x 8 u)
        const int t = tid + i * 256;
        const int arr = t >> 10, r = (t >> 3) & 127, u = t & 7;
        const __half* src =
            (arr ? Al : Ah) + (size_t)(mBase + r) * DD + kBase + u * 8;
        cp16(sb + arr * 16384 + swz8o(r, u), src);
    }
#pragma unroll
    for (int i = 0; i < 4; i++) {      // B: 1024 units (128 r x 8 u)
        const int t = tid + i * 256;
        const int r = (t >> 3) & 127, u = t & 7;
        cp16(sb + 32768 + swz8o(r, u),
             B + (size_t)(nBase + r) * DD + kBase + u * 8);
    }
}

__device__ __forceinline__ void gemm_body(
    const __half* __restrict__ Ah, const __half* __restrict__ Al,
    const __half* __restrict__ B, const float* __restrict__ bias, int mode,
    float* __restrict__ C, __half* __restrict__ Oh, __half* __restrict__ Ol) {
    extern __shared__ char smem[];
    const uint32_t sbase = s2u(smem);

    const int tid = threadIdx.x;
    const int wid = tid >> 5;
    const int lane = tid & 31;
    const int m0 = (wid >> 2) * 64;
    const int n0 = (wid & 3) * 32;
    const int mBase = blockIdx.y * 128;
    const int nBase = blockIdx.x * 128;

    float acc[4][4][4];
#pragma unroll
    for (int i = 0; i < 4; i++)
#pragma unroll
        for (int j = 0; j < 4; j++)
#pragma unroll
            for (int q = 0; q < 4; q++) acc[i][j][q] = 0.0f;

    gemm_issue(sbase, Ah, Al, B, mBase, nBase, 0, tid);
    CP_COMMIT();
    gemm_issue(sbase + GEMM_STAGE, Ah, Al, B, mBase, nBase, KT, tid);
    CP_COMMIT();

    const int a_r = lane & 15;
    const int a_uh = lane >> 4;
    const int b_r = ((lane >> 4) & 1) * 8 + (lane & 7);
    const int b_uh = (lane >> 3) & 1;

    const int NKT = DD / KT;   // 12
    for (int kt = 0; kt < NKT; kt++) {
        CP_WAIT1();
        __syncthreads();
        const uint32_t st = sbase + (kt & 1) * GEMM_STAGE;
#pragma unroll
        for (int ks = 0; ks < 4; ks++) {
            const int ua = ks * 2 + a_uh;
            const int ub = ks * 2 + b_uh;
            uint32_t ah[4][4], al[4][4];
#pragma unroll
            for (int fm = 0; fm < 4; fm++) {
                const int r = m0 + fm * 16 + a_r;
                ldm_x4(ah[fm], st + swz8o(r, ua));
                ldm_x4(al[fm], st + 16384 + swz8o(r, ua));
            }
#pragma unroll
            for (int fn2 = 0; fn2 < 2; fn2++) {
                uint32_t b4[4];
                ldm_x4(b4, st + 32768 + swz8o(n0 + fn2 * 16 + b_r, ub));
#pragma unroll
                for (int fm = 0; fm < 4; fm++) {
#pragma unroll
                    for (int hf = 0; hf < 2; hf++) {
                        float* c = acc[fm][fn2 * 2 + hf];
                        mma16816(c, ah[fm], &b4[hf * 2]);
                        mma16816(c, al[fm], &b4[hf * 2]);
                    }
                }
            }
        }
        __syncthreads();
        if (kt + 2 < NKT)
            gemm_issue(sbase + (kt & 1) * GEMM_STAGE, Ah, Al, B,
                       mBase, nBase, (kt + 2) * KT, tid);
        CP_COMMIT();
    }

    const int row_l = lane >> 2;
    const int col_l = (lane & 3) * 2;
#pragma unroll
    for (int fn = 0; fn < 4; fn++) {
        const int col = nBase + n0 + fn * 8 + col_l;
        const float2 bv = *reinterpret_cast<const float2*>(&bias[col]);
#pragma unroll
        for (int fm = 0; fm < 4; fm++) {
            const int row = mBase + m0 + fm * 16 + row_l;
            float v0 = acc[fm][fn][0] + bv.x;
            float v1 = acc[fm][fn][1] + bv.y;
            float v2 = acc[fm][fn][2] + bv.x;
            float v3 = acc[fm][fn][3] + bv.y;
            if (mode == 0) {
                *reinterpret_cast<float2*>(&C[(size_t)row * DD + col]) = make_float2(v0, v1);
                *reinterpret_cast<float2*>(&C[(size_t)(row + 8) * DD + col]) = make_float2(v2, v3);
            } else if (mode == 1) {
                uint32_t h01, l01, h23, l23;
                split2h(v0, v1, h01, l01);
                split2h(v2, v3, h23, l23);
                *reinterpret_cast<uint32_t*>(&Oh[(size_t)row * DD + col]) = h01;
                *reinterpret_cast<uint32_t*>(&Ol[(size_t)row * DD + col]) = l01;
                *reinterpret_cast<uint32_t*>(&Oh[(size_t)(row + 8) * DD + col]) = h23;
                *reinterpret_cast<uint32_t*>(&Ol[(size_t)(row + 8) * DD + col]) = l23;
            } else if (mode == 3) {
                *reinterpret_cast<uint32_t*>(&Oh[(size_t)row * DD + col]) =
                    pack2h(__float2half_rn(v0), __float2half_rn(v1));
                *reinterpret_cast<uint32_t*>(&Oh[(size_t)(row + 8) * DD + col]) =
                    pack2h(__float2half_rn(v2), __float2half_rn(v3));
            } else {
                // transposed single: vt[(b*768+col)][n]
                float vv[4] = {v0, v1, v2, v3};
#pragma unroll
                for (int e = 0; e < 4; e++) {
                    const int rr = row + (e >> 1) * 8;
                    const int cc = col + (e & 1);
                    const int bb = rr >> 10, nn = rr & 1023;
                    Oh[(size_t)(bb * DD + cc) * NN + nn] = __float2half_rn(vv[e]);
                }
            }
        }
    }
}

__global__ __launch_bounds__(256, 2) void qkv_mma_kernel(
    const __half* __restrict__ Ah, const __half* __restrict__ Al,
    const __half* __restrict__ W,
    const float* __restrict__ bq, const float* __restrict__ bk,
    const float* __restrict__ bv,
    __half* __restrict__ qh, __half* __restrict__ ql,
    __half* __restrict__ k, __half* __restrict__ vt) {
    const int z = blockIdx.z;
    const size_t ws = (size_t)z * DD * DD;
    const float* bias = (z == 0) ? bq : (z == 1) ? bk : bv;
    if (z == 0)
        gemm_body(Ah, Al, W + ws, bias, 1, nullptr, qh, ql);
    else if (z == 1)
        gemm_body(Ah, Al, W + ws, bias, 3, nullptr, k, nullptr);
    else
        gemm_body(Ah, Al, W + ws, bias, 2, nullptr, vt, nullptr);
}

__global__ __launch_bounds__(256, 2) void out_mma_kernel(
    const __half* __restrict__ Ah, const __half* __restrict__ Al,
    const __half* __restrict__ W, const float* __restrict__ bias,
    float* __restrict__ C) {
    gemm_body(Ah, Al, W, bias, 0, C, nullptr, nullptr);
}

// ---------------------------------------------------------------------------
// fp16 tensor-core flash attention, quiet softmax (base-2; scale post-MMA,
// P scaled by 2^10 via exponent offset; P SINGLE fp16 in PV).
// Block = 128 q-rows of one (b,h); 8 warps x 16 rows; 64-key tiles, 16 iters.
// 4-stage pipeline, ONE barrier per iteration (slot kt+3 == slot kt-1 is
// safe to overwrite once all warps passed the top barrier of iter kt).
// smem: Qh 16K | Ql 16K | 4 x (K 8K | V 8K) = 96K.
// ---------------------------------------------------------------------------
#define ATTN_STAGE 16384
#define ATTN_SMEM (32768 + 4 * ATTN_STAGE)   // 98304

__device__ __forceinline__ void attn_issue(
    uint32_t st, const __half* k_, const __half* vt_,
    int b, int hoff, int kt, int tid) {
    const int tok0 = b * NN + kt * 64;
#pragma unroll
    for (int i = 0; i < 2; i++) {   // K: 512 units (64 rows x 8u)
        const int t = tid + i * 256;
        const int r = (t >> 3) & 63, u = t & 7;
        cp16(st + swz8o(r, u), k_ + (size_t)(tok0 + r) * DD + hoff + u * 8);
    }
#pragma unroll
    for (int i = 0; i < 2; i++) {   // V: 512 units (64 d-rows x 8u)
        const int t = tid + i * 256;
        const int r = (t >> 3) & 63, u = t & 7;
        cp16(st + 8192 + swz8o(r, u),
             vt_ + (size_t)(b * DD + hoff + r) * NN + kt * 64 + u * 8);
    }
}

__global__ __launch_bounds__(256, 2) void attn_mma_kernel(
    const __half* __restrict__ qh_, const __half* __restrict__ ql_,
    const __half* __restrict__ k_, const __half* __restrict__ vt_,
    __half* __restrict__ ch_, __half* __restrict__ cl_) {
    extern __shared__ char smem[];
    const uint32_t sb = s2u(smem);
    const int tid = threadIdx.x;
    const int wid = tid >> 5;
    const int lane = tid & 31;
    const int qt = blockIdx.x;        // 0..7 (128-row tiles)
    const int bh = blockIdx.y;        // 0..95
    const int b = bh / HH;
    const int h = bh - b * HH;
    const int hoff = h * HD;
    const int q0 = b * NN + qt * 128;
    const int strip = wid * 16;

    // Q tile: 2048 units (2 arrays x 128 rows x 8u)
#pragma unroll
    for (int i = 0; i < 8; i++) {
        const int t = tid + i * 256;
        const int arr = t >> 10, r = (t >> 3) & 127, u = t & 7;
        const __half* src =
            (arr ? ql_ : qh_) + (size_t)(q0 + r) * DD + hoff + u * 8;
        cp16(sb + arr * 16384 + swz8o(r, u), src);
    }
    CP_COMMIT();
    attn_issue(sb + 32768 + 0 * ATTN_STAGE, k_, vt_, b, hoff, 0, tid);
    CP_COMMIT();
    attn_issue(sb + 32768 + 1 * ATTN_STAGE, k_, vt_, b, hoff, 1, tid);
    CP_COMMIT();
    attn_issue(sb + 32768 + 2 * ATTN_STAGE, k_, vt_, b, hoff, 2, tid);
    CP_COMMIT();

    const int a_r = lane & 15;
    const int a_uh = lane >> 4;
    const int b_r = ((lane >> 4) & 1) * 8 + (lane & 7);
    const int b_uh = (lane >> 3) & 1;

    float m_[2] = {-1e30f, -1e30f};
    float l_[2] = {0.0f, 0.0f};
    float ctx[8][4];
#pragma unroll
    for (int fn = 0; fn < 8; fn++)
#pragma unroll
        for (int q = 0; q < 4; q++) ctx[fn][q] = 0.0f;

    for (int kt = 0; kt < 16; kt++) {
        CP_WAIT2();
        __syncthreads();
        const uint32_t st = sb + 32768 + (kt & 3) * ATTN_STAGE;

        // ---- S[16 q x 64 keys] = Q K^T ----
        float S[8][4];
#pragma unroll
        for (int fn = 0; fn < 8; fn++)
#pragma unroll
            for (int q = 0; q < 4; q++) S[fn][q] = 0.0f;

#pragma unroll
        for (int ks = 0; ks < 4; ks++) {
            const int ua = ks * 2 + a_uh;
            const int ub = ks * 2 + b_uh;
            uint32_t qh4[4], ql4[4];
            const int rq = strip + a_r;
            ldm_x4(qh4, sb + swz8o(rq, ua));
            ldm_x4(ql4, sb + 16384 + swz8o(rq, ua));
#pragma unroll
            for (int fn2 = 0; fn2 < 4; fn2++) {
                uint32_t k4[4];
                ldm_x4(k4, st + swz8o(fn2 * 16 + b_r, ub));
#pragma unroll
                for (int hf = 0; hf < 2; hf++) {
                    float* c = S[fn2 * 2 + hf];
                    mma16816(c, qh4, &k4[hf * 2]);
                    mma16816(c, ql4, &k4[hf * 2]);
                }
            }
        }

        // ---- scale to base-2 logits; online quiet softmax (P scaled 2^10) ----
        float mx[2] = {-1e30f, -1e30f};
#pragma unroll
        for (int fn = 0; fn < 8; fn++) {
            S[fn][0] *= SCALEQ;
            S[fn][1] *= SCALEQ;
            S[fn][2] *= SCALEQ;
            S[fn][3] *= SCALEQ;
            mx[0] = fmaxf(mx[0], fmaxf(S[fn][0], S[fn][1]));
            mx[1] = fmaxf(mx[1], fmaxf(S[fn][2], S[fn][3]));
        }
        float corr[2];
#pragma unroll
        for (int j = 0; j < 2; j++) {
            mx[j] = fmaxf(mx[j], __shfl_xor_sync(0xffffffffu, mx[j], 1));
            mx[j] = fmaxf(mx[j], __shfl_xor_sync(0xffffffffu, mx[j], 2));
            const float mn = fmaxf(m_[j], mx[j]);
            corr[j] = ex2(m_[j] - mn);
            m_[j] = mn;
        }
        float ps[2] = {0.0f, 0.0f};
#pragma unroll
        for (int fn = 0; fn < 8; fn++) {
            S[fn][0] = ex2(S[fn][0] - m_[0] + 10.0f);
            S[fn][1] = ex2(S[fn][1] - m_[0] + 10.0f);
            S[fn][2] = ex2(S[fn][2] - m_[1] + 10.0f);
            S[fn][3] = ex2(S[fn][3] - m_[1] + 10.0f);
            ps[0] += S[fn][0] + S[fn][1];
            ps[1] += S[fn][2] + S[fn][3];
        }
#pragma unroll
        for (int j = 0; j < 2; j++) {
            ps[j] += __shfl_xor_sync(0xffffffffu, ps[j], 1);
            ps[j] += __shfl_xor_sync(0xffffffffu, ps[j], 2);
            l_[j] = l_[j] * corr[j] + ps[j];
        }
#pragma unroll
        for (int fn = 0; fn < 8; fn++) {
            ctx[fn][0] *= corr[0];
            ctx[fn][1] *= corr[0];
            ctx[fn][2] *= corr[1];
            ctx[fn][3] *= corr[1];
        }

        // ---- ctx += P V  (P SINGLE fp16, V single) ----
#pragma unroll
        for (int kb = 0; kb < 4; kb++) {
            uint32_t pa[4];
            pa[0] = pack2h(__float2half_rn(S[2 * kb][0]), __float2half_rn(S[2 * kb][1]));
            pa[1] = pack2h(__float2half_rn(S[2 * kb][2]), __float2half_rn(S[2 * kb][3]));
            pa[2] = pack2h(__float2half_rn(S[2 * kb + 1][0]), __float2half_rn(S[2 * kb + 1][1]));
            pa[3] = pack2h(__float2half_rn(S[2 * kb + 1][2]), __float2half_rn(S[2 * kb + 1][3]));
            const int ub = kb * 2 + b_uh;
#pragma unroll
            for (int fn2 = 0; fn2 < 4; fn2++) {
                uint32_t v4[4];
                ldm_x4(v4, st + 8192 + swz8o(fn2 * 16 + b_r, ub));
#pragma unroll
                for (int hf = 0; hf < 2; hf++)
                    mma16816(ctx[fn2 * 2 + hf], pa, &v4[hf * 2]);
            }
        }
        // Single barrier per iter: safe to refill slot (kt+3)&3 == (kt-1)&3
        // because every warp has passed the top barrier of iter kt, hence
        // finished reading slot kt-1.
        if (kt + 3 < 16)
            attn_issue(sb + 32768 + ((kt + 3) & 3) * ATTN_STAGE,
                       k_, vt_, b, hoff, kt + 3, tid);
        CP_COMMIT();
    }

    // ---- epilogue: out = ctx' / (1024 + l'); emit half hi/lo ----
    const float inv0 = 1.0f / (1024.0f + l_[0]);
    const float inv1 = 1.0f / (1024.0f + l_[1]);
    const int rowA = q0 + strip + (lane >> 2);
    const int rowB = rowA + 8;
#pragma unroll
    for (int fn = 0; fn < 8; fn++) {
        const int col = hoff + fn * 8 + (lane & 3) * 2;
        uint32_t hA, lA2, hB, lB2;
        split2h(ctx[fn][0] * inv0, ctx[fn][1] * inv0, hA, lA2);
        split2h(ctx[fn][2] * inv1, ctx[fn][3] * inv1, hB, lB2);
        *reinterpret_cast<uint32_t*>(&ch_[(size_t)rowA * DD + col]) = hA;
        *reinterpret_cast<uint32_t*>(&cl_[(size_t)rowA * DD + col]) = lA2;
        *reinterpret_cast<uint32_t*>(&ch_[(size_t)rowB * DD + col]) = hB;
        *reinterpret_cast<uint32_t*>(&cl_[(size_t)rowB * DD + col]) = lB2;
    }
}

// ---------------------------------------------------------------------------
// Launch
// ---------------------------------------------------------------------------
extern "C" void kernel_launch(void* const* d_in, const int* in_sizes, int n_in,
                              void* d_out, int out_size) {
    const float* x  = (const float*)d_in[0];
    const float* Wq = (const float*)d_in[1];
    const float* bq = (const float*)d_in[2];
    const float* Wk = (const float*)d_in[3];
    const float* bk = (const float*)d_in[4];
    const float* Wv = (const float*)d_in[5];
    const float* bv = (const float*)d_in[6];
    const float* Wo = (const float*)d_in[7];
    const float* bo = (const float*)d_in[8];
    float* out = (float*)d_out;
    (void)in_sizes; (void)n_in; (void)out_size;

    __half *xh, *xl, *qh, *ql, *k, *vt, *ch, *cl, *w;
    cudaGetSymbolAddress((void**)&xh, g_xh);
    cudaGetSymbolAddress((void**)&xl, g_xl);
    cudaGetSymbolAddress((void**)&qh, g_qh);
    cudaGetSymbolAddress((void**)&ql, g_ql);
    cudaGetSymbolAddress((void**)&k, g_k);
    cudaGetSymbolAddress((void**)&vt, g_vt);
    cudaGetSymbolAddress((void**)&ch, g_ch);
    cudaGetSymbolAddress((void**)&cl, g_cl);
    cudaGetSymbolAddress((void**)&w, g_w);

    cudaFuncSetAttribute(qkv_mma_kernel, cudaFuncAttributeMaxDynamicSharedMemorySize, GEMM_SMEM);
    cudaFuncSetAttribute(out_mma_kernel, cudaFuncAttributeMaxDynamicSharedMemorySize, GEMM_SMEM);
    cudaFuncSetAttribute(attn_mma_kernel, cudaFuncAttributeMaxDynamicSharedMemorySize, ATTN_SMEM);

    const size_t ws = (size_t)DD * DD;
    dim3 blk(256);

    convert_split_kernel<<<MM * DD / 8 / 256, blk>>>(x, xh, xl);
    convert_wt_kernel<<<dim3(12, 12, 4), blk>>>(Wq, Wk, Wv, Wo, w);
    qkv_mma_kernel<<<dim3(6, 64, 3), blk, GEMM_SMEM>>>(xh, xl, w, bq, bk, bv,
                                                       qh, ql, k, vt);
    attn_mma_kernel<<<dim3(8, 96), blk, ATTN_SMEM>>>(qh, ql, k, vt, ch, cl);
    out_mma_kernel<<<dim3(6, 64), blk, GEMM_SMEM>>>(ch, cl, w + 3 * ws, bo, out);
}

// round 10
// speedup vs baseline: 6.0340x; 1.2060x over previous
#include <cuda_runtime.h>
#include <cuda_fp16.h>
#include <cstdint>

// Problem constants
#define BB 8
#define NN 1024
#define DD 768
#define HH 12
#define HD 64
#define MM (BB * NN)   // 8192 rows
#define SCALEQ 0.18033688011112042591f   // 0.125 * log2(e), applied post-MMA

// ---------------------------------------------------------------------------
// Scratch (__device__ globals; no allocation allowed)
// ---------------------------------------------------------------------------
__device__ __half g_xh[MM * DD], g_xl[MM * DD];   // x split
__device__ __half g_q[MM * DD];                   // q single (UNSCALED)
__device__ __half g_k[MM * DD];                   // k single
__device__ __half g_vt[MM * DD];                  // v single, transposed [(b*768+d)][n]
__device__ __half g_c[MM * DD];                   // attention output single
__device__ __half g_w[4 * DD * DD];               // weights single, transposed [n][k]

// ---------------------------------------------------------------------------
// PTX helpers
// ---------------------------------------------------------------------------
__device__ __forceinline__ uint32_t s2u(const void* p) {
    uint32_t a;
    asm("{ .reg .u64 t; cvta.to.shared.u64 t, %1; cvt.u32.u64 %0, t; }"
        : "=r"(a) : "l"(p));
    return a;
}
__device__ __forceinline__ void cp16(uint32_t dst, const void* src) {
    asm volatile("cp.async.cg.shared.global [%0], [%1], 16;" :: "r"(dst), "l"(src));
}
#define CP_COMMIT() asm volatile("cp.async.commit_group;" ::: "memory")
#define CP_WAIT1()  asm volatile("cp.async.wait_group 1;" ::: "memory")
#define CP_WAIT2()  asm volatile("cp.async.wait_group 2;" ::: "memory")

__device__ __forceinline__ void ldm_x4(uint32_t* r, uint32_t addr) {
    asm volatile("ldmatrix.sync.aligned.m8n8.x4.shared.b16 {%0,%1,%2,%3}, [%4];"
                 : "=r"(r[0]), "=r"(r[1]), "=r"(r[2]), "=r"(r[3]) : "r"(addr));
}
__device__ __forceinline__ void mma16816(float* c, const uint32_t* a, const uint32_t* b) {
    asm volatile(
        "mma.sync.aligned.m16n8k16.row.col.f32.f16.f16.f32 "
        "{%0,%1,%2,%3}, {%4,%5,%6,%7}, {%8,%9}, {%0,%1,%2,%3};"
        : "+f"(c[0]), "+f"(c[1]), "+f"(c[2]), "+f"(c[3])
        : "r"(a[0]), "r"(a[1]), "r"(a[2]), "r"(a[3]), "r"(b[0]), "r"(b[1]));
}
__device__ __forceinline__ float ex2(float x) {
    float y;
    asm("ex2.approx.ftz.f32 %0, %1;" : "=f"(y) : "f"(x));
    return y;
}

// swizzled offset within a tile of 128B rows (8 16B units per row)
__device__ __forceinline__ uint32_t swz8o(int r, int u) {
    return (uint32_t)(r * 128 + ((u ^ (r & 7)) << 4));
}

__device__ __forceinline__ uint32_t pack2h(__half a, __half b) {
    return (uint32_t)__half_as_ushort(a) | ((uint32_t)__half_as_ushort(b) << 16);
}
__device__ __forceinline__ void split2h(float x, float y, uint32_t& hi, uint32_t& lo) {
    __half hx = __float2half_rn(x), hy = __float2half_rn(y);
    __half lx = __float2half_rn(x - __half2float(hx));
    __half ly = __float2half_rn(y - __half2float(hy));
    hi = pack2h(hx, hy);
    lo = pack2h(lx, ly);
}

// ---------------------------------------------------------------------------
// Conversions
// ---------------------------------------------------------------------------
__global__ __launch_bounds__(256) void convert_split_kernel(
    const float* __restrict__ src, __half* __restrict__ dh,
    __half* __restrict__ dl) {
    const int idx = blockIdx.x * 256 + threadIdx.x;
    const float4 v0 = *reinterpret_cast<const float4*>(&src[idx * 8]);
    const float4 v1 = *reinterpret_cast<const float4*>(&src[idx * 8 + 4]);
    float v[8] = {v0.x, v0.y, v0.z, v0.w, v1.x, v1.y, v1.z, v1.w};
    uint4 ph, pl;
    uint32_t* hp = &ph.x;
    uint32_t* lp = &pl.x;
#pragma unroll
    for (int i = 0; i < 4; i++) split2h(v[i * 2], v[i * 2 + 1], hp[i], lp[i]);
    reinterpret_cast<uint4*>(dh)[idx] = ph;
    reinterpret_cast<uint4*>(dl)[idx] = pl;
}

__global__ __launch_bounds__(256) void convert_wt_kernel(
    const float* __restrict__ Wq, const float* __restrict__ Wk,
    const float* __restrict__ Wv, const float* __restrict__ Wo,
    __half* __restrict__ dw) {
    __shared__ float tile[64][65];
    const int z = blockIdx.z;
    const float* W = (z == 0) ? Wq : (z == 1) ? Wk : (z == 2) ? Wv : Wo;
    __half* ow = dw + (size_t)z * DD * DD;
    const int k0 = blockIdx.x * 64;
    const int n0 = blockIdx.y * 64;
    const int tid = threadIdx.x;
#pragma unroll
    for (int t = tid; t < 64 * 16; t += 256) {
        const int i = t >> 4;
        const int j4 = (t & 15) * 4;
        const float4 w = *reinterpret_cast<const float4*>(&W[(k0 + i) * DD + n0 + j4]);
        tile[i][j4 + 0] = w.x;
        tile[i][j4 + 1] = w.y;
        tile[i][j4 + 2] = w.z;
        tile[i][j4 + 3] = w.w;
    }
    __syncthreads();
#pragma unroll
    for (int t = tid; t < 64 * 8; t += 256) {
        const int nl = t >> 3;
        const int kin = (t & 7) * 8;
        uint4 pw;
        uint32_t* wp = &pw.x;
#pragma unroll
        for (int m = 0; m < 4; m++)
            wp[m] = pack2h(__float2half_rn(tile[kin + m * 2][nl]),
                           __float2half_rn(tile[kin + m * 2 + 1][nl]));
        reinterpret_cast<uint4*>(ow)[((size_t)(n0 + nl) * DD + k0 + kin) >> 3] = pw;
    }
}

// ---------------------------------------------------------------------------
// fp16 GEMM, templated on ASPLIT.
// ASPLIT=1: C = (Ah + Al) @ B^T (+bias);  ASPLIT=0: C = A @ B^T (+bias).
// CTA tile 128m x 128n, 8 warps (2m x 4n), warp tile 64x32.  KT=64,
// 2-stage cp.async pipeline.
// Stage: ASPLIT=1: Ah 16K | Al 16K | B 16K = 48K; ASPLIT=0: A 16K | B 16K = 32K.
// Epilogue modes: 0 fp32+bias; 2 transposed half single; 3 half single.
// ---------------------------------------------------------------------------
#define KT 64

template <int ASPLIT>
__device__ __forceinline__ void gemm_issue(
    uint32_t sb, const __half* Ah, const __half* Al, const __half* B,
    int mBase, int nBase, int kBase, int tid) {
    if (ASPLIT) {
#pragma unroll
        for (int i = 0; i < 8; i++) {   // A: 2048 units (2 arr x 128 r x 8 u)
            const int t = tid + i * 256;
            const int arr = t >> 10, r = (t >> 3) & 127, u = t & 7;
            const __half* src =
                (arr ? Al : Ah) + (size_t)(mBase + r) * DD + kBase + u * 8;
            cp16(sb + arr * 16384 + swz8o(r, u), src);
        }
    } else {
#pragma unroll
        for (int i = 0; i < 4; i++) {   // A: 1024 units
            const int t = tid + i * 256;
            const int r = (t >> 3) & 127, u = t & 7;
            cp16(sb + swz8o(r, u), Ah + (size_t)(mBase + r) * DD + kBase + u * 8);
        }
    }
    const uint32_t boff = ASPLIT ? 32768u : 16384u;
#pragma unroll
    for (int i = 0; i < 4; i++) {       // B: 1024 units (128 r x 8 u)
        const int t = tid + i * 256;
        const int r = (t >> 3) & 127, u = t & 7;
        cp16(sb + boff + swz8o(r, u),
             B + (size_t)(nBase + r) * DD + kBase + u * 8);
    }
}

template <int ASPLIT>
__device__ __forceinline__ void gemm_body(
    const __half* __restrict__ Ah, const __half* __restrict__ Al,
    const __half* __restrict__ B, const float* __restrict__ bias, int mode,
    float* __restrict__ C, __half* __restrict__ Oh) {
    extern __shared__ char smem[];
    const uint32_t sbase = s2u(smem);
    const uint32_t STAGE = (2 + ASPLIT) * 16384u;
    const uint32_t boff = ASPLIT ? 32768u : 16384u;

    const int tid = threadIdx.x;
    const int wid = tid >> 5;
    const int lane = tid & 31;
    const int m0 = (wid >> 2) * 64;
    const int n0 = (wid & 3) * 32;
    const int mBase = blockIdx.y * 128;
    const int nBase = blockIdx.x * 128;

    float acc[4][4][4];
#pragma unroll
    for (int i = 0; i < 4; i++)
#pragma unroll
        for (int j = 0; j < 4; j++)
#pragma unroll
            for (int q = 0; q < 4; q++) acc[i][j][q] = 0.0f;

    gemm_issue<ASPLIT>(sbase, Ah, Al, B, mBase, nBase, 0, tid);
    CP_COMMIT();
    gemm_issue<ASPLIT>(sbase + STAGE, Ah, Al, B, mBase, nBase, KT, tid);
    CP_COMMIT();

    const int a_r = lane & 15;
    const int a_uh = lane >> 4;
    const int b_r = ((lane >> 4) & 1) * 8 + (lane & 7);
    const int b_uh = (lane >> 3) & 1;

    const int NKT = DD / KT;   // 12
    for (int kt = 0; kt < NKT; kt++) {
        CP_WAIT1();
        __syncthreads();
        const uint32_t st = sbase + (kt & 1) * STAGE;
#pragma unroll
        for (int ks = 0; ks < 4; ks++) {
            const int ua = ks * 2 + a_uh;
            const int ub = ks * 2 + b_uh;
            uint32_t ah[4][4], al[4][4];
#pragma unroll
            for (int fm = 0; fm < 4; fm++) {
                const int r = m0 + fm * 16 + a_r;
                ldm_x4(ah[fm], st + swz8o(r, ua));
                if (ASPLIT) ldm_x4(al[fm], st + 16384 + swz8o(r, ua));
            }
#pragma unroll
            for (int fn2 = 0; fn2 < 2; fn2++) {
                uint32_t b4[4];
                ldm_x4(b4, st + boff + swz8o(n0 + fn2 * 16 + b_r, ub));
#pragma unroll
                for (int fm = 0; fm < 4; fm++) {
#pragma unroll
                    for (int hf = 0; hf < 2; hf++) {
                        float* c = acc[fm][fn2 * 2 + hf];
                        mma16816(c, ah[fm], &b4[hf * 2]);
                        if (ASPLIT) mma16816(c, al[fm], &b4[hf * 2]);
                    }
                }
            }
        }
        __syncthreads();
        if (kt + 2 < NKT)
            gemm_issue<ASPLIT>(sbase + (kt & 1) * STAGE, Ah, Al, B,
                               mBase, nBase, (kt + 2) * KT, tid);
        CP_COMMIT();
    }

    const int row_l = lane >> 2;
    const int col_l = (lane & 3) * 2;
#pragma unroll
    for (int fn = 0; fn < 4; fn++) {
        const int col = nBase + n0 + fn * 8 + col_l;
        const float2 bv = *reinterpret_cast<const float2*>(&bias[col]);
#pragma unroll
        for (int fm = 0; fm < 4; fm++) {
            const int row = mBase + m0 + fm * 16 + row_l;
            float v0 = acc[fm][fn][0] + bv.x;
            float v1 = acc[fm][fn][1] + bv.y;
            float v2 = acc[fm][fn][2] + bv.x;
            float v3 = acc[fm][fn][3] + bv.y;
            if (mode == 0) {
                *reinterpret_cast<float2*>(&C[(size_t)row * DD + col]) = make_float2(v0, v1);
                *reinterpret_cast<float2*>(&C[(size_t)(row + 8) * DD + col]) = make_float2(v2, v3);
            } else if (mode == 3) {
                *reinterpret_cast<uint32_t*>(&Oh[(size_t)row * DD + col]) =
                    pack2h(__float2half_rn(v0), __float2half_rn(v1));
                *reinterpret_cast<uint32_t*>(&Oh[(size_t)(row + 8) * DD + col]) =
                    pack2h(__float2half_rn(v2), __float2half_rn(v3));
            } else {
                // transposed single: vt[(b*768+col)][n]
                float vv[4] = {v0, v1, v2, v3};
#pragma unroll
                for (int e = 0; e < 4; e++) {
                    const int rr = row + (e >> 1) * 8;
                    const int cc = col + (e & 1);
                    const int bb = rr >> 10, nn = rr & 1023;
                    Oh[(size_t)(bb * DD + cc) * NN + nn] = __float2half_rn(vv[e]);
                }
            }
        }
    }
}

#define GEMM_SMEM_SPLIT (2 * 49152)   // 96K
#define GEMM_SMEM_SINGLE (2 * 32768)  // 64K

__global__ __launch_bounds__(256, 2) void qkv_mma_kernel(
    const __half* __restrict__ Ah, const __half* __restrict__ Al,
    const __half* __restrict__ W,
    const float* __restrict__ bq, const float* __restrict__ bk,
    const float* __restrict__ bv,
    __half* __restrict__ q, __half* __restrict__ k, __half* __restrict__ vt) {
    const int z = blockIdx.z;
    const size_t ws = (size_t)z * DD * DD;
    if (z == 0)
        gemm_body<1>(Ah, Al, W + ws, bq, 3, nullptr, q);
    else if (z == 1)
        gemm_body<1>(Ah, Al, W + ws, bk, 3, nullptr, k);
    else
        gemm_body<1>(Ah, Al, W + ws, bv, 2, nullptr, vt);
}

__global__ __launch_bounds__(256, 2) void out_mma_kernel(
    const __half* __restrict__ A, const __half* __restrict__ W,
    const float* __restrict__ bias, float* __restrict__ C) {
    gemm_body<0>(A, nullptr, W, bias, 0, C, nullptr);
}

// ---------------------------------------------------------------------------
// fp16 tensor-core flash attention, quiet softmax.
// Raw-unit running max; P = ex2(fma(S, SCALEQ, 10 - m*SCALEQ)) (scaled 2^10).
// Q single, K single, P single, V single.
// Block = 128 q-rows of one (b,h); 8 warps x 16 rows; 64-key tiles, 16 iters.
// 4-stage pipeline, one barrier per iteration.
// smem: Q 16K | 4 x (K 8K | V 8K) = 80K.
// ---------------------------------------------------------------------------
#define ATTN_STAGE 16384
#define ATTN_SMEM (16384 + 4 * ATTN_STAGE)   // 81920

__device__ __forceinline__ void attn_issue(
    uint32_t st, const __half* k_, const __half* vt_,
    int b, int hoff, int kt, int tid) {
    const int tok0 = b * NN + kt * 64;
#pragma unroll
    for (int i = 0; i < 2; i++) {   // K: 512 units (64 rows x 8u)
        const int t = tid + i * 256;
        const int r = (t >> 3) & 63, u = t & 7;
        cp16(st + swz8o(r, u), k_ + (size_t)(tok0 + r) * DD + hoff + u * 8);
    }
#pragma unroll
    for (int i = 0; i < 2; i++) {   // V: 512 units (64 d-rows x 8u)
        const int t = tid + i * 256;
        const int r = (t >> 3) & 63, u = t & 7;
        cp16(st + 8192 + swz8o(r, u),
             vt_ + (size_t)(b * DD + hoff + r) * NN + kt * 64 + u * 8);
    }
}

__global__ __launch_bounds__(256, 2) void attn_mma_kernel(
    const __half* __restrict__ q_, const __half* __restrict__ k_,
    const __half* __restrict__ vt_, __half* __restrict__ c_) {
    extern __shared__ char smem[];
    const uint32_t sb = s2u(smem);
    const int tid = threadIdx.x;
    const int wid = tid >> 5;
    const int lane = tid & 31;
    const int qt = blockIdx.x;        // 0..7 (128-row tiles)
    const int bh = blockIdx.y;        // 0..95
    const int b = bh / HH;
    const int h = bh - b * HH;
    const int hoff = h * HD;
    const int q0 = b * NN + qt * 128;
    const int strip = wid * 16;

    // Q tile: 1024 units (128 rows x 8u)
#pragma unroll
    for (int i = 0; i < 4; i++) {
        const int t = tid + i * 256;
        const int r = (t >> 3) & 127, u = t & 7;
        cp16(sb + swz8o(r, u), q_ + (size_t)(q0 + r) * DD + hoff + u * 8);
    }
    CP_COMMIT();
    attn_issue(sb + 16384 + 0 * ATTN_STAGE, k_, vt_, b, hoff, 0, tid);
    CP_COMMIT();
    attn_issue(sb + 16384 + 1 * ATTN_STAGE, k_, vt_, b, hoff, 1, tid);
    CP_COMMIT();
    attn_issue(sb + 16384 + 2 * ATTN_STAGE, k_, vt_, b, hoff, 2, tid);
    CP_COMMIT();

    const int a_r = lane & 15;
    const int a_uh = lane >> 4;
    const int b_r = ((lane >> 4) & 1) * 8 + (lane & 7);
    const int b_uh = (lane >> 3) & 1;

    float m_[2] = {-1e30f, -1e30f};   // raw score units
    float l_[2] = {0.0f, 0.0f};
    float ctx[8][4];
#pragma unroll
    for (int fn = 0; fn < 8; fn++)
#pragma unroll
        for (int q = 0; q < 4; q++) ctx[fn][q] = 0.0f;

    for (int kt = 0; kt < 16; kt++) {
        CP_WAIT2();
        __syncthreads();
        const uint32_t st = sb + 16384 + (kt & 3) * ATTN_STAGE;

        // ---- S[16 q x 64 keys] = Q K^T (raw units) ----
        float S[8][4];
#pragma unroll
        for (int fn = 0; fn < 8; fn++)
#pragma unroll
            for (int q = 0; q < 4; q++) S[fn][q] = 0.0f;

#pragma unroll
        for (int ks = 0; ks < 4; ks++) {
            const int ua = ks * 2 + a_uh;
            const int ub = ks * 2 + b_uh;
            uint32_t q4[4];
            ldm_x4(q4, sb + swz8o(strip + a_r, ua));
#pragma unroll
            for (int fn2 = 0; fn2 < 4; fn2++) {
                uint32_t k4[4];
                ldm_x4(k4, st + swz8o(fn2 * 16 + b_r, ub));
                mma16816(S[fn2 * 2 + 0], q4, &k4[0]);
                mma16816(S[fn2 * 2 + 1], q4, &k4[2]);
            }
        }

        // ---- online quiet softmax (raw-unit max; fused scale in ex2 arg) ----
        float mx[2] = {-1e30f, -1e30f};
#pragma unroll
        for (int fn = 0; fn < 8; fn++) {
            mx[0] = fmaxf(mx[0], fmaxf(S[fn][0], S[fn][1]));
            mx[1] = fmaxf(mx[1], fmaxf(S[fn][2], S[fn][3]));
        }
        float corr[2], cc[2];
#pragma unroll
        for (int j = 0; j < 2; j++) {
            mx[j] = fmaxf(mx[j], __shfl_xor_sync(0xffffffffu, mx[j], 1));
            mx[j] = fmaxf(mx[j], __shfl_xor_sync(0xffffffffu, mx[j], 2));
            const float mn = fmaxf(m_[j], mx[j]);
            corr[j] = ex2((m_[j] - mn) * SCALEQ);
            m_[j] = mn;
            cc[j] = fmaf(-mn, SCALEQ, 10.0f);   // 10 - m*SCALEQ
        }
        float ps[2] = {0.0f, 0.0f};
#pragma unroll
        for (int fn = 0; fn < 8; fn++) {
            S[fn][0] = ex2(fmaf(S[fn][0], SCALEQ, cc[0]));
            S[fn][1] = ex2(fmaf(S[fn][1], SCALEQ, cc[0]));
            S[fn][2] = ex2(fmaf(S[fn][2], SCALEQ, cc[1]));
            S[fn][3] = ex2(fmaf(S[fn][3], SCALEQ, cc[1]));
            ps[0] += S[fn][0] + S[fn][1];
            ps[1] += S[fn][2] + S[fn][3];
        }
#pragma unroll
        for (int j = 0; j < 2; j++) {
            ps[j] += __shfl_xor_sync(0xffffffffu, ps[j], 1);
            ps[j] += __shfl_xor_sync(0xffffffffu, ps[j], 2);
            l_[j] = l_[j] * corr[j] + ps[j];
        }
#pragma unroll
        for (int fn = 0; fn < 8; fn++) {
            ctx[fn][0] *= corr[0];
            ctx[fn][1] *= corr[0];
            ctx[fn][2] *= corr[1];
            ctx[fn][3] *= corr[1];
        }

        // ---- ctx += P V  (P single fp16, V single) ----
#pragma unroll
        for (int kb = 0; kb < 4; kb++) {
            uint32_t pa[4];
            pa[0] = pack2h(__float2half_rn(S[2 * kb][0]), __float2half_rn(S[2 * kb][1]));
            pa[1] = pack2h(__float2half_rn(S[2 * kb][2]), __float2half_rn(S[2 * kb][3]));
            pa[2] = pack2h(__float2half_rn(S[2 * kb + 1][0]), __float2half_rn(S[2 * kb + 1][1]));
            pa[3] = pack2h(__float2half_rn(S[2 * kb + 1][2]), __float2half_rn(S[2 * kb + 1][3]));
            const int ub = kb * 2 + b_uh;
#pragma unroll
            for (int fn2 = 0; fn2 < 4; fn2++) {
                uint32_t v4[4];
                ldm_x4(v4, st + 8192 + swz8o(fn2 * 16 + b_r, ub));
#pragma unroll
                for (int hf = 0; hf < 2; hf++)
                    mma16816(ctx[fn2 * 2 + hf], pa, &v4[hf * 2]);
            }
        }
        // Single barrier per iter: refill slot (kt+3)&3 == (kt-1)&3 is safe
        // because every warp passed the top barrier of iter kt.
        if (kt + 3 < 16)
            attn_issue(sb + 16384 + ((kt + 3) & 3) * ATTN_STAGE,
                       k_, vt_, b, hoff, kt + 3, tid);
        CP_COMMIT();
    }

    // ---- epilogue: out = ctx' / (1024 + l'); emit half single ----
    const float inv0 = 1.0f / (1024.0f + l_[0]);
    const float inv1 = 1.0f / (1024.0f + l_[1]);
    const int rowA = q0 + strip + (lane >> 2);
    const int rowB = rowA + 8;
#pragma unroll
    for (int fn = 0; fn < 8; fn++) {
        const int col = hoff + fn * 8 + (lane & 3) * 2;
        *reinterpret_cast<uint32_t*>(&c_[(size_t)rowA * DD + col]) =
            pack2h(__float2half_rn(ctx[fn][0] * inv0), __float2half_rn(ctx[fn][1] * inv0));
        *reinterpret_cast<uint32_t*>(&c_[(size_t)rowB * DD + col]) =
            pack2h(__float2half_rn(ctx[fn][2] * inv1), __float2half_rn(ctx[fn][3] * inv1));
    }
}

// ---------------------------------------------------------------------------
// Launch
// ---------------------------------------------------------------------------
extern "C" void kernel_launch(void* const* d_in, const int* in_sizes, int n_in,
                              void* d_out, int out_size) {
    const float* x  = (const float*)d_in[0];
    const float* Wq = (const float*)d_in[1];
    const float* bq = (const float*)d_in[2];
    const float* Wk = (const float*)d_in[3];
    const float* bk = (const float*)d_in[4];
    const float* Wv = (const float*)d_in[5];
    const float* bv = (const float*)d_in[6];
    const float* Wo = (const float*)d_in[7];
    const float* bo = (const float*)d_in[8];
    float* out = (float*)d_out;
    (void)in_sizes; (void)n_in; (void)out_size;

    __half *xh, *xl, *q, *k, *vt, *c, *w;
    cudaGetSymbolAddress((void**)&xh, g_xh);
    cudaGetSymbolAddress((void**)&xl, g_xl);
    cudaGetSymbolAddress((void**)&q, g_q);
    cudaGetSymbolAddress((void**)&k, g_k);
    cudaGetSymbolAddress((void**)&vt, g_vt);
    cudaGetSymbolAddress((void**)&c, g_c);
    cudaGetSymbolAddress((void**)&w, g_w);

    cudaFuncSetAttribute(qkv_mma_kernel, cudaFuncAttributeMaxDynamicSharedMemorySize,
                         GEMM_SMEM_SPLIT);
    cudaFuncSetAttribute(out_mma_kernel, cudaFuncAttributeMaxDynamicSharedMemorySize,
                         GEMM_SMEM_SINGLE);
    cudaFuncSetAttribute(attn_mma_kernel, cudaFuncAttributeMaxDynamicSharedMemorySize,
                         ATTN_SMEM);

    const size_t ws = (size_t)DD * DD;
    dim3 blk(256);

    convert_split_kernel<<<MM * DD / 8 / 256, blk>>>(x, xh, xl);
    convert_wt_kernel<<<dim3(12, 12, 4), blk>>>(Wq, Wk, Wv, Wo, w);
    qkv_mma_kernel<<<dim3(6, 64, 3), blk, GEMM_SMEM_SPLIT>>>(xh, xl, w, bq, bk, bv,
                                                             q, k, vt);
    attn_mma_kernel<<<dim3(8, 96), blk, ATTN_SMEM>>>(q, k, vt, c);
    out_mma_kernel<<<dim3(6, 64), blk, GEMM_SMEM_SINGLE>>>(c, w + 3 * ws, bo, out);
}

// round 11
// speedup vs baseline: 7.7300x; 1.2811x over previous
#include <cuda_runtime.h>
#include <cuda_fp16.h>
#include <cstdint>

// Problem constants
#define BB 8
#define NN 1024
#define DD 768
#define HH 12
#define HD 64
#define MM (BB * NN)   // 8192 rows
#define SCALEQ 0.18033688011112042591f   // 0.125 * log2(e), applied post-MMA

// ---------------------------------------------------------------------------
// Scratch (__device__ globals; no allocation allowed)
// ---------------------------------------------------------------------------
__device__ __half g_x[MM * DD];                   // x single
__device__ __half g_q[MM * DD];                   // q single (UNSCALED)
__device__ __half g_k[MM * DD];                   // k single
__device__ __half g_vt[MM * DD];                  // v single, transposed [(b*768+d)][n]
__device__ __half g_c[MM * DD];                   // attention output single
__device__ __half g_w[4 * DD * DD];               // weights single, transposed [n][k]

// ---------------------------------------------------------------------------
// PTX helpers
// ---------------------------------------------------------------------------
__device__ __forceinline__ uint32_t s2u(const void* p) {
    uint32_t a;
    asm("{ .reg .u64 t; cvta.to.shared.u64 t, %1; cvt.u32.u64 %0, t; }"
        : "=r"(a) : "l"(p));
    return a;
}
__device__ __forceinline__ void cp16(uint32_t dst, const void* src) {
    asm volatile("cp.async.cg.shared.global [%0], [%1], 16;" :: "r"(dst), "l"(src));
}
#define CP_COMMIT() asm volatile("cp.async.commit_group;" ::: "memory")
#define CP_WAIT1()  asm volatile("cp.async.wait_group 1;" ::: "memory")
#define CP_WAIT2()  asm volatile("cp.async.wait_group 2;" ::: "memory")

__device__ __forceinline__ void ldm_x4(uint32_t* r, uint32_t addr) {
    asm volatile("ldmatrix.sync.aligned.m8n8.x4.shared.b16 {%0,%1,%2,%3}, [%4];"
                 : "=r"(r[0]), "=r"(r[1]), "=r"(r[2]), "=r"(r[3]) : "r"(addr));
}
__device__ __forceinline__ void mma16816(float* c, const uint32_t* a, const uint32_t* b) {
    asm volatile(
        "mma.sync.aligned.m16n8k16.row.col.f32.f16.f16.f32 "
        "{%0,%1,%2,%3}, {%4,%5,%6,%7}, {%8,%9}, {%0,%1,%2,%3};"
        : "+f"(c[0]), "+f"(c[1]), "+f"(c[2]), "+f"(c[3])
        : "r"(a[0]), "r"(a[1]), "r"(a[2]), "r"(a[3]), "r"(b[0]), "r"(b[1]));
}
__device__ __forceinline__ float ex2(float x) {
    float y;
    asm("ex2.approx.ftz.f32 %0, %1;" : "=f"(y) : "f"(x));
    return y;
}

// swizzled offset within a tile of 128B rows (8 16B units per row)
__device__ __forceinline__ uint32_t swz8o(int r, int u) {
    return (uint32_t)(r * 128 + ((u ^ (r & 7)) << 4));
}

__device__ __forceinline__ uint32_t pack2h(__half a, __half b) {
    return (uint32_t)__half_as_ushort(a) | ((uint32_t)__half_as_ushort(b) << 16);
}

// ---------------------------------------------------------------------------
// Conversions
// ---------------------------------------------------------------------------
__global__ __launch_bounds__(256) void convert_half_kernel(
    const float* __restrict__ src, __half* __restrict__ dst) {
    const int idx = blockIdx.x * 256 + threadIdx.x;
    const float4 v0 = *reinterpret_cast<const float4*>(&src[idx * 8]);
    const float4 v1 = *reinterpret_cast<const float4*>(&src[idx * 8 + 4]);
    uint4 p;
    p.x = pack2h(__float2half_rn(v0.x), __float2half_rn(v0.y));
    p.y = pack2h(__float2half_rn(v0.z), __float2half_rn(v0.w));
    p.z = pack2h(__float2half_rn(v1.x), __float2half_rn(v1.y));
    p.w = pack2h(__float2half_rn(v1.z), __float2half_rn(v1.w));
    reinterpret_cast<uint4*>(dst)[idx] = p;
}

__global__ __launch_bounds__(256) void convert_wt_kernel(
    const float* __restrict__ Wq, const float* __restrict__ Wk,
    const float* __restrict__ Wv, const float* __restrict__ Wo,
    __half* __restrict__ dw) {
    __shared__ float tile[64][65];
    const int z = blockIdx.z;
    const float* W = (z == 0) ? Wq : (z == 1) ? Wk : (z == 2) ? Wv : Wo;
    __half* ow = dw + (size_t)z * DD * DD;
    const int k0 = blockIdx.x * 64;
    const int n0 = blockIdx.y * 64;
    const int tid = threadIdx.x;
#pragma unroll
    for (int t = tid; t < 64 * 16; t += 256) {
        const int i = t >> 4;
        const int j4 = (t & 15) * 4;
        const float4 w = *reinterpret_cast<const float4*>(&W[(k0 + i) * DD + n0 + j4]);
        tile[i][j4 + 0] = w.x;
        tile[i][j4 + 1] = w.y;
        tile[i][j4 + 2] = w.z;
        tile[i][j4 + 3] = w.w;
    }
    __syncthreads();
#pragma unroll
    for (int t = tid; t < 64 * 8; t += 256) {
        const int nl = t >> 3;
        const int kin = (t & 7) * 8;
        uint4 pw;
        uint32_t* wp = &pw.x;
#pragma unroll
        for (int m = 0; m < 4; m++)
            wp[m] = pack2h(__float2half_rn(tile[kin + m * 2][nl]),
                           __float2half_rn(tile[kin + m * 2 + 1][nl]));
        reinterpret_cast<uint4*>(ow)[((size_t)(n0 + nl) * DD + k0 + kin) >> 3] = pw;
    }
}

// ---------------------------------------------------------------------------
// fp16 single GEMM: C = A @ B^T (+bias).
// CTA tile 128m x 128n, 8 warps (2m x 4n), warp tile 64x32.  KT=64,
// 2-stage cp.async pipeline.  Stage: A 16K | B 16K = 32K; x2 = 64K.
// Epilogue modes: 0 fp32+bias; 2 transposed half single; 3 half single.
// ---------------------------------------------------------------------------
#define KT 64
#define GEMM_STAGE 32768
#define GEMM_SMEM (2 * GEMM_STAGE)   // 65536

__device__ __forceinline__ void gemm_issue(
    uint32_t sb, const __half* A, const __half* B,
    int mBase, int nBase, int kBase, int tid) {
#pragma unroll
    for (int i = 0; i < 4; i++) {   // A: 1024 units (128 r x 8 u)
        const int t = tid + i * 256;
        const int r = (t >> 3) & 127, u = t & 7;
        cp16(sb + swz8o(r, u), A + (size_t)(mBase + r) * DD + kBase + u * 8);
    }
#pragma unroll
    for (int i = 0; i < 4; i++) {   // B: 1024 units (128 r x 8 u)
        const int t = tid + i * 256;
        const int r = (t >> 3) & 127, u = t & 7;
        cp16(sb + 16384 + swz8o(r, u),
             B + (size_t)(nBase + r) * DD + kBase + u * 8);
    }
}

__device__ __forceinline__ void gemm_body(
    const __half* __restrict__ A, const __half* __restrict__ B,
    const float* __restrict__ bias, int mode,
    float* __restrict__ C, __half* __restrict__ Oh) {
    extern __shared__ char smem[];
    const uint32_t sbase = s2u(smem);

    const int tid = threadIdx.x;
    const int wid = tid >> 5;
    const int lane = tid & 31;
    const int m0 = (wid >> 2) * 64;
    const int n0 = (wid & 3) * 32;
    const int mBase = blockIdx.y * 128;
    const int nBase = blockIdx.x * 128;

    float acc[4][4][4];
#pragma unroll
    for (int i = 0; i < 4; i++)
#pragma unroll
        for (int j = 0; j < 4; j++)
#pragma unroll
            for (int q = 0; q < 4; q++) acc[i][j][q] = 0.0f;

    gemm_issue(sbase, A, B, mBase, nBase, 0, tid);
    CP_COMMIT();
    gemm_issue(sbase + GEMM_STAGE, A, B, mBase, nBase, KT, tid);
    CP_COMMIT();

    const int a_r = lane & 15;
    const int a_uh = lane >> 4;
    const int b_r = ((lane >> 4) & 1) * 8 + (lane & 7);
    const int b_uh = (lane >> 3) & 1;

    const int NKT = DD / KT;   // 12
    for (int kt = 0; kt < NKT; kt++) {
        CP_WAIT1();
        __syncthreads();
        const uint32_t st = sbase + (kt & 1) * GEMM_STAGE;
#pragma unroll
        for (int ks = 0; ks < 4; ks++) {
            const int ua = ks * 2 + a_uh;
            const int ub = ks * 2 + b_uh;
            uint32_t a4[4][4];
#pragma unroll
            for (int fm = 0; fm < 4; fm++)
                ldm_x4(a4[fm], st + swz8o(m0 + fm * 16 + a_r, ua));
#pragma unroll
            for (int fn2 = 0; fn2 < 2; fn2++) {
                uint32_t b4[4];
                ldm_x4(b4, st + 16384 + swz8o(n0 + fn2 * 16 + b_r, ub));
#pragma unroll
                for (int fm = 0; fm < 4; fm++) {
#pragma unroll
                    for (int hf = 0; hf < 2; hf++)
                        mma16816(acc[fm][fn2 * 2 + hf], a4[fm], &b4[hf * 2]);
                }
            }
        }
        __syncthreads();
        if (kt + 2 < NKT)
            gemm_issue(sbase + (kt & 1) * GEMM_STAGE, A, B,
                       mBase, nBase, (kt + 2) * KT, tid);
        CP_COMMIT();
    }

    const int row_l = lane >> 2;
    const int col_l = (lane & 3) * 2;
#pragma unroll
    for (int fn = 0; fn < 4; fn++) {
        const int col = nBase + n0 + fn * 8 + col_l;
        const float2 bv = *reinterpret_cast<const float2*>(&bias[col]);
#pragma unroll
        for (int fm = 0; fm < 4; fm++) {
            const int row = mBase + m0 + fm * 16 + row_l;
            float v0 = acc[fm][fn][0] + bv.x;
            float v1 = acc[fm][fn][1] + bv.y;
            float v2 = acc[fm][fn][2] + bv.x;
            float v3 = acc[fm][fn][3] + bv.y;
            if (mode == 0) {
                *reinterpret_cast<float2*>(&C[(size_t)row * DD + col]) = make_float2(v0, v1);
                *reinterpret_cast<float2*>(&C[(size_t)(row + 8) * DD + col]) = make_float2(v2, v3);
            } else if (mode == 3) {
                *reinterpret_cast<uint32_t*>(&Oh[(size_t)row * DD + col]) =
                    pack2h(__float2half_rn(v0), __float2half_rn(v1));
                *reinterpret_cast<uint32_t*>(&Oh[(size_t)(row + 8) * DD + col]) =
                    pack2h(__float2half_rn(v2), __float2half_rn(v3));
            } else {
                // transposed single: vt[(b*768+col)][n]
                float vv[4] = {v0, v1, v2, v3};
#pragma unroll
                for (int e = 0; e < 4; e++) {
                    const int rr = row + (e >> 1) * 8;
                    const int cc = col + (e & 1);
                    const int bb = rr >> 10, nn = rr & 1023;
                    Oh[(size_t)(bb * DD + cc) * NN + nn] = __float2half_rn(vv[e]);
                }
            }
        }
    }
}

__global__ __launch_bounds__(256, 2) void qkv_mma_kernel(
    const __half* __restrict__ A, const __half* __restrict__ W,
    const float* __restrict__ bq, const float* __restrict__ bk,
    const float* __restrict__ bv,
    __half* __restrict__ q, __half* __restrict__ k, __half* __restrict__ vt) {
    const int z = blockIdx.z;
    const size_t ws = (size_t)z * DD * DD;
    if (z == 0)
        gemm_body(A, W + ws, bq, 3, nullptr, q);
    else if (z == 1)
        gemm_body(A, W + ws, bk, 3, nullptr, k);
    else
        gemm_body(A, W + ws, bv, 2, nullptr, vt);
}

__global__ __launch_bounds__(256, 2) void out_mma_kernel(
    const __half* __restrict__ A, const __half* __restrict__ W,
    const float* __restrict__ bias, float* __restrict__ C) {
    gemm_body(A, W, bias, 0, C, nullptr);
}

// ---------------------------------------------------------------------------
// fp16 tensor-core flash attention, quiet softmax.
// Raw-unit running max; P = ex2(fma(S, SCALEQ, 10 - m*SCALEQ)) (scaled 2^10).
// Q single, K single, P single, V single.
// Block = 128 q-rows of one (b,h); 8 warps x 16 rows; 64-key tiles, 16 iters.
// 4-stage pipeline, one barrier per iteration.
// smem: Q 16K | 4 x (K 8K | V 8K) = 80K.
// ---------------------------------------------------------------------------
#define ATTN_STAGE 16384
#define ATTN_SMEM (16384 + 4 * ATTN_STAGE)   // 81920

__device__ __forceinline__ void attn_issue(
    uint32_t st, const __half* k_, const __half* vt_,
    int b, int hoff, int kt, int tid) {
    const int tok0 = b * NN + kt * 64;
#pragma unroll
    for (int i = 0; i < 2; i++) {   // K: 512 units (64 rows x 8u)
        const int t = tid + i * 256;
        const int r = (t >> 3) & 63, u = t & 7;
        cp16(st + swz8o(r, u), k_ + (size_t)(tok0 + r) * DD + hoff + u * 8);
    }
#pragma unroll
    for (int i = 0; i < 2; i++) {   // V: 512 units (64 d-rows x 8u)
        const int t = tid + i * 256;
        const int r = (t >> 3) & 63, u = t & 7;
        cp16(st + 8192 + swz8o(r, u),
             vt_ + (size_t)(b * DD + hoff + r) * NN + kt * 64 + u * 8);
    }
}

__global__ __launch_bounds__(256, 2) void attn_mma_kernel(
    const __half* __restrict__ q_, const __half* __restrict__ k_,
    const __half* __restrict__ vt_, __half* __restrict__ c_) {
    extern __shared__ char smem[];
    const uint32_t sb = s2u(smem);
    const int tid = threadIdx.x;
    const int wid = tid >> 5;
    const int lane = tid & 31;
    const int qt = blockIdx.x;        // 0..7 (128-row tiles)
    const int bh = blockIdx.y;        // 0..95
    const int b = bh / HH;
    const int h = bh - b * HH;
    const int hoff = h * HD;
    const int q0 = b * NN + qt * 128;
    const int strip = wid * 16;

    // Q tile: 1024 units (128 rows x 8u)
#pragma unroll
    for (int i = 0; i < 4; i++) {
        const int t = tid + i * 256;
        const int r = (t >> 3) & 127, u = t & 7;
        cp16(sb + swz8o(r, u), q_ + (size_t)(q0 + r) * DD + hoff + u * 8);
    }
    CP_COMMIT();
    attn_issue(sb + 16384 + 0 * ATTN_STAGE, k_, vt_, b, hoff, 0, tid);
    CP_COMMIT();
    attn_issue(sb + 16384 + 1 * ATTN_STAGE, k_, vt_, b, hoff, 1, tid);
    CP_COMMIT();
    attn_issue(sb + 16384 + 2 * ATTN_STAGE, k_, vt_, b, hoff, 2, tid);
    CP_COMMIT();

    const int a_r = lane & 15;
    const int a_uh = lane >> 4;
    const int b_r = ((lane >> 4) & 1) * 8 + (lane & 7);
    const int b_uh = (lane >> 3) & 1;

    float m_[2] = {-1e30f, -1e30f};   // raw score units
    float l_[2] = {0.0f, 0.0f};
    float ctx[8][4];
#pragma unroll
    for (int fn = 0; fn < 8; fn++)
#pragma unroll
        for (int q = 0; q < 4; q++) ctx[fn][q] = 0.0f;

    for (int kt = 0; kt < 16; kt++) {
        CP_WAIT2();
        __syncthreads();
        const uint32_t st = sb + 16384 + (kt & 3) * ATTN_STAGE;

        // ---- S[16 q x 64 keys] = Q K^T (raw units) ----
        float S[8][4];
#pragma unroll
        for (int fn = 0; fn < 8; fn++)
#pragma unroll
            for (int q = 0; q < 4; q++) S[fn][q] = 0.0f;

#pragma unroll
        for (int ks = 0; ks < 4; ks++) {
            const int ua = ks * 2 + a_uh;
            const int ub = ks * 2 + b_uh;
            uint32_t q4[4];
            ldm_x4(q4, sb + swz8o(strip + a_r, ua));
#pragma unroll
            for (int fn2 = 0; fn2 < 4; fn2++) {
                uint32_t k4[4];
                ldm_x4(k4, st + swz8o(fn2 * 16 + b_r, ub));
                mma16816(S[fn2 * 2 + 0], q4, &k4[0]);
                mma16816(S[fn2 * 2 + 1], q4, &k4[2]);
            }
        }

        // ---- online quiet softmax (raw-unit max; fused scale in ex2 arg) ----
        float mx[2] = {-1e30f, -1e30f};
#pragma unroll
        for (int fn = 0; fn < 8; fn++) {
            mx[0] = fmaxf(mx[0], fmaxf(S[fn][0], S[fn][1]));
            mx[1] = fmaxf(mx[1], fmaxf(S[fn][2], S[fn][3]));
        }
        float corr[2], cc[2];
#pragma unroll
        for (int j = 0; j < 2; j++) {
            mx[j] = fmaxf(mx[j], __shfl_xor_sync(0xffffffffu, mx[j], 1));
            mx[j] = fmaxf(mx[j], __shfl_xor_sync(0xffffffffu, mx[j], 2));
            const float mn = fmaxf(m_[j], mx[j]);
            corr[j] = ex2((m_[j] - mn) * SCALEQ);
            m_[j] = mn;
            cc[j] = fmaf(-mn, SCALEQ, 10.0f);   // 10 - m*SCALEQ
        }
        float ps[2] = {0.0f, 0.0f};
#pragma unroll
        for (int fn = 0; fn < 8; fn++) {
            S[fn][0] = ex2(fmaf(S[fn][0], SCALEQ, cc[0]));
            S[fn][1] = ex2(fmaf(S[fn][1], SCALEQ, cc[0]));
            S[fn][2] = ex2(fmaf(S[fn][2], SCALEQ, cc[1]));
            S[fn][3] = ex2(fmaf(S[fn][3], SCALEQ, cc[1]));
            ps[0] += S[fn][0] + S[fn][1];
            ps[1] += S[fn][2] + S[fn][3];
        }
#pragma unroll
        for (int j = 0; j < 2; j++) {
            ps[j] += __shfl_xor_sync(0xffffffffu, ps[j], 1);
            ps[j] += __shfl_xor_sync(0xffffffffu, ps[j], 2);
            l_[j] = l_[j] * corr[j] + ps[j];
        }
#pragma unroll
        for (int fn = 0; fn < 8; fn++) {
            ctx[fn][0] *= corr[0];
            ctx[fn][1] *= corr[0];
            ctx[fn][2] *= corr[1];
            ctx[fn][3] *= corr[1];
        }

        // ---- ctx += P V  (P single fp16, V single) ----
#pragma unroll
        for (int kb = 0; kb < 4; kb++) {
            uint32_t pa[4];
            pa[0] = pack2h(__float2half_rn(S[2 * kb][0]), __float2half_rn(S[2 * kb][1]));
            pa[1] = pack2h(__float2half_rn(S[2 * kb][2]), __float2half_rn(S[2 * kb][3]));
            pa[2] = pack2h(__float2half_rn(S[2 * kb + 1][0]), __float2half_rn(S[2 * kb + 1][1]));
            pa[3] = pack2h(__float2half_rn(S[2 * kb + 1][2]), __float2half_rn(S[2 * kb + 1][3]));
            const int ub = kb * 2 + b_uh;
#pragma unroll
            for (int fn2 = 0; fn2 < 4; fn2++) {
                uint32_t v4[4];
                ldm_x4(v4, st + 8192 + swz8o(fn2 * 16 + b_r, ub));
#pragma unroll
                for (int hf = 0; hf < 2; hf++)
                    mma16816(ctx[fn2 * 2 + hf], pa, &v4[hf * 2]);
            }
        }
        // Single barrier per iter: refill slot (kt+3)&3 == (kt-1)&3 is safe
        // because every warp passed the top barrier of iter kt.
        if (kt + 3 < 16)
            attn_issue(sb + 16384 + ((kt + 3) & 3) * ATTN_STAGE,
                       k_, vt_, b, hoff, kt + 3, tid);
        CP_COMMIT();
    }

    // ---- epilogue: out = ctx' / (1024 + l'); emit half single ----
    const float inv0 = 1.0f / (1024.0f + l_[0]);
    const float inv1 = 1.0f / (1024.0f + l_[1]);
    const int rowA = q0 + strip + (lane >> 2);
    const int rowB = rowA + 8;
#pragma unroll
    for (int fn = 0; fn < 8; fn++) {
        const int col = hoff + fn * 8 + (lane & 3) * 2;
        *reinterpret_cast<uint32_t*>(&c_[(size_t)rowA * DD + col]) =
            pack2h(__float2half_rn(ctx[fn][0] * inv0), __float2half_rn(ctx[fn][1] * inv0));
        *reinterpret_cast<uint32_t*>(&c_[(size_t)rowB * DD + col]) =
            pack2h(__float2half_rn(ctx[fn][2] * inv1), __float2half_rn(ctx[fn][3] * inv1));
    }
}

// ---------------------------------------------------------------------------
// Launch
// ---------------------------------------------------------------------------
extern "C" void kernel_launch(void* const* d_in, const int* in_sizes, int n_in,
                              void* d_out, int out_size) {
    const float* x  = (const float*)d_in[0];
    const float* Wq = (const float*)d_in[1];
    const float* bq = (const float*)d_in[2];
    const float* Wk = (const float*)d_in[3];
    const float* bk = (const float*)d_in[4];
    const float* Wv = (const float*)d_in[5];
    const float* bv = (const float*)d_in[6];
    const float* Wo = (const float*)d_in[7];
    const float* bo = (const float*)d_in[8];
    float* out = (float*)d_out;
    (void)in_sizes; (void)n_in; (void)out_size;

    __half *xs, *q, *k, *vt, *c, *w;
    cudaGetSymbolAddress((void**)&xs, g_x);
    cudaGetSymbolAddress((void**)&q, g_q);
    cudaGetSymbolAddress((void**)&k, g_k);
    cudaGetSymbolAddress((void**)&vt, g_vt);
    cudaGetSymbolAddress((void**)&c, g_c);
    cudaGetSymbolAddress((void**)&w, g_w);

    cudaFuncSetAttribute(qkv_mma_kernel, cudaFuncAttributeMaxDynamicSharedMemorySize,
                         GEMM_SMEM);
    cudaFuncSetAttribute(out_mma_kernel, cudaFuncAttributeMaxDynamicSharedMemorySize,
                         GEMM_SMEM);
    cudaFuncSetAttribute(attn_mma_kernel, cudaFuncAttributeMaxDynamicSharedMemorySize,
                         ATTN_SMEM);

    const size_t ws = (size_t)DD * DD;
    dim3 blk(256);

    convert_half_kernel<<<MM * DD / 8 / 256, blk>>>(x, xs);
    convert_wt_kernel<<<dim3(12, 12, 4), blk>>>(Wq, Wk, Wv, Wo, w);
    qkv_mma_kernel<<<dim3(6, 64, 3), blk, GEMM_SMEM>>>(xs, w, bq, bk, bv, q, k, vt);
    attn_mma_kernel<<<dim3(8, 96), blk, ATTN_SMEM>>>(q, k, vt, c);
    out_mma_kernel<<<dim3(6, 64), blk, GEMM_SMEM>>>(c, w + 3 * ws, bo, out);
}

// round 12
// speedup vs baseline: 7.9414x; 1.0273x over previous
#include <cuda_runtime.h>
#include <cuda_fp16.h>
#include <cstdint>

// Problem constants
#define BB 8
#define NN 1024
#define DD 768
#define HH 12
#define HD 64
#define MM (BB * NN)   // 8192 rows
#define SCALEQ 0.18033688011112042591f   // 0.125 * log2(e), applied post-MMA

// ---------------------------------------------------------------------------
// Scratch (__device__ globals; no allocation allowed)
// ---------------------------------------------------------------------------
__device__ __half g_x[MM * DD];                   // x single
__device__ __half g_q[MM * DD];                   // q single (UNSCALED)
__device__ __half g_k[MM * DD];                   // k single
__device__ __half g_vt[MM * DD];                  // v single, transposed [(b*768+d)][n]
__device__ __half g_c[MM * DD];                   // attention output single
__device__ __half g_w[4 * DD * DD];               // weights single, transposed [n][k]

// ---------------------------------------------------------------------------
// PTX helpers
// ---------------------------------------------------------------------------
__device__ __forceinline__ uint32_t s2u(const void* p) {
    uint32_t a;
    asm("{ .reg .u64 t; cvta.to.shared.u64 t, %1; cvt.u32.u64 %0, t; }"
        : "=r"(a) : "l"(p));
    return a;
}
__device__ __forceinline__ void cp16(uint32_t dst, const void* src) {
    asm volatile("cp.async.cg.shared.global [%0], [%1], 16;" :: "r"(dst), "l"(src));
}
#define CP_COMMIT() asm volatile("cp.async.commit_group;" ::: "memory")
#define CP_WAIT1()  asm volatile("cp.async.wait_group 1;" ::: "memory")
#define CP_WAIT2()  asm volatile("cp.async.wait_group 2;" ::: "memory")

__device__ __forceinline__ void ldm_x4(uint32_t* r, uint32_t addr) {
    asm volatile("ldmatrix.sync.aligned.m8n8.x4.shared.b16 {%0,%1,%2,%3}, [%4];"
                 : "=r"(r[0]), "=r"(r[1]), "=r"(r[2]), "=r"(r[3]) : "r"(addr));
}
__device__ __forceinline__ void mma16816(float* c, const uint32_t* a, const uint32_t* b) {
    asm volatile(
        "mma.sync.aligned.m16n8k16.row.col.f32.f16.f16.f32 "
        "{%0,%1,%2,%3}, {%4,%5,%6,%7}, {%8,%9}, {%0,%1,%2,%3};"
        : "+f"(c[0]), "+f"(c[1]), "+f"(c[2]), "+f"(c[3])
        : "r"(a[0]), "r"(a[1]), "r"(a[2]), "r"(a[3]), "r"(b[0]), "r"(b[1]));
}
__device__ __forceinline__ float ex2(float x) {
    float y;
    asm("ex2.approx.ftz.f32 %0, %1;" : "=f"(y) : "f"(x));
    return y;
}
// pack two fp32 into f16x2 in ONE instruction.  First asm source = HIGH half.
__device__ __forceinline__ uint32_t cvt2h(float lo, float hi) {
    uint32_t r;
    asm("cvt.rn.f16x2.f32 %0, %1, %2;" : "=r"(r) : "f"(hi), "f"(lo));
    return r;
}

// swizzled offset within a tile of 128B rows (8 16B units per row)
__device__ __forceinline__ uint32_t swz8o(int r, int u) {
    return (uint32_t)(r * 128 + ((u ^ (r & 7)) << 4));
}

__device__ __forceinline__ uint32_t pack2h(__half a, __half b) {
    return (uint32_t)__half_as_ushort(a) | ((uint32_t)__half_as_ushort(b) << 16);
}

// ---------------------------------------------------------------------------
// Conversions
// ---------------------------------------------------------------------------
__global__ __launch_bounds__(256) void convert_half_kernel(
    const float* __restrict__ src, __half* __restrict__ dst) {
    const int idx = blockIdx.x * 256 + threadIdx.x;
    const float4 v0 = *reinterpret_cast<const float4*>(&src[idx * 8]);
    const float4 v1 = *reinterpret_cast<const float4*>(&src[idx * 8 + 4]);
    uint4 p;
    p.x = cvt2h(v0.x, v0.y);
    p.y = cvt2h(v0.z, v0.w);
    p.z = cvt2h(v1.x, v1.y);
    p.w = cvt2h(v1.z, v1.w);
    reinterpret_cast<uint4*>(dst)[idx] = p;
}

__global__ __launch_bounds__(256) void convert_wt_kernel(
    const float* __restrict__ Wq, const float* __restrict__ Wk,
    const float* __restrict__ Wv, const float* __restrict__ Wo,
    __half* __restrict__ dw) {
    __shared__ float tile[64][65];
    const int z = blockIdx.z;
    const float* W = (z == 0) ? Wq : (z == 1) ? Wk : (z == 2) ? Wv : Wo;
    __half* ow = dw + (size_t)z * DD * DD;
    const int k0 = blockIdx.x * 64;
    const int n0 = blockIdx.y * 64;
    const int tid = threadIdx.x;
#pragma unroll
    for (int t = tid; t < 64 * 16; t += 256) {
        const int i = t >> 4;
        const int j4 = (t & 15) * 4;
        const float4 w = *reinterpret_cast<const float4*>(&W[(k0 + i) * DD + n0 + j4]);
        tile[i][j4 + 0] = w.x;
        tile[i][j4 + 1] = w.y;
        tile[i][j4 + 2] = w.z;
        tile[i][j4 + 3] = w.w;
    }
    __syncthreads();
#pragma unroll
    for (int t = tid; t < 64 * 8; t += 256) {
        const int nl = t >> 3;
        const int kin = (t & 7) * 8;
        uint4 pw;
        uint32_t* wp = &pw.x;
#pragma unroll
        for (int m = 0; m < 4; m++)
            wp[m] = cvt2h(tile[kin + m * 2][nl], tile[kin + m * 2 + 1][nl]);
        reinterpret_cast<uint4*>(ow)[((size_t)(n0 + nl) * DD + k0 + kin) >> 3] = pw;
    }
}

// ---------------------------------------------------------------------------
// fp16 single GEMM: C = A @ B^T (+bias).
// CTA tile 128m x 128n, 8 warps (2m x 4n), warp tile 64x32.  KT=64,
// 2-stage cp.async pipeline.  Stage: A 16K | B 16K = 32K; x2 = 64K.
// Epilogue modes: 0 fp32+bias; 2 transposed half single; 3 half single.
// ---------------------------------------------------------------------------
#define KT 64
#define GEMM_STAGE 32768
#define GEMM_SMEM (2 * GEMM_STAGE)   // 65536

__device__ __forceinline__ void gemm_issue(
    uint32_t sb, const __half* A, const __half* B,
    int mBase, int nBase, int kBase, int tid) {
#pragma unroll
    for (int i = 0; i < 4; i++) {   // A: 1024 units (128 r x 8 u)
        const int t = tid + i * 256;
        const int r = (t >> 3) & 127, u = t & 7;
        cp16(sb + swz8o(r, u), A + (size_t)(mBase + r) * DD + kBase + u * 8);
    }
#pragma unroll
    for (int i = 0; i < 4; i++) {   // B: 1024 units (128 r x 8 u)
        const int t = tid + i * 256;
        const int r = (t >> 3) & 127, u = t & 7;
        cp16(sb + 16384 + swz8o(r, u),
             B + (size_t)(nBase + r) * DD + kBase + u * 8);
    }
}

__device__ __forceinline__ void gemm_body(
    const __half* __restrict__ A, const __half* __restrict__ B,
    const float* __restrict__ bias, int mode,
    float* __restrict__ C, __half* __restrict__ Oh) {
    extern __shared__ char smem[];
    const uint32_t sbase = s2u(smem);

    const int tid = threadIdx.x;
    const int wid = tid >> 5;
    const int lane = tid & 31;
    const int m0 = (wid >> 2) * 64;
    const int n0 = (wid & 3) * 32;
    const int mBase = blockIdx.y * 128;
    const int nBase = blockIdx.x * 128;

    float acc[4][4][4];
#pragma unroll
    for (int i = 0; i < 4; i++)
#pragma unroll
        for (int j = 0; j < 4; j++)
#pragma unroll
            for (int q = 0; q < 4; q++) acc[i][j][q] = 0.0f;

    gemm_issue(sbase, A, B, mBase, nBase, 0, tid);
    CP_COMMIT();
    gemm_issue(sbase + GEMM_STAGE, A, B, mBase, nBase, KT, tid);
    CP_COMMIT();

    const int a_r = lane & 15;
    const int a_uh = lane >> 4;
    const int b_r = ((lane >> 4) & 1) * 8 + (lane & 7);
    const int b_uh = (lane >> 3) & 1;

    const int NKT = DD / KT;   // 12
    for (int kt = 0; kt < NKT; kt++) {
        CP_WAIT1();
        __syncthreads();
        const uint32_t st = sbase + (kt & 1) * GEMM_STAGE;
#pragma unroll
        for (int ks = 0; ks < 4; ks++) {
            const int ua = ks * 2 + a_uh;
            const int ub = ks * 2 + b_uh;
            uint32_t a4[4][4];
#pragma unroll
            for (int fm = 0; fm < 4; fm++)
                ldm_x4(a4[fm], st + swz8o(m0 + fm * 16 + a_r, ua));
#pragma unroll
            for (int fn2 = 0; fn2 < 2; fn2++) {
                uint32_t b4[4];
                ldm_x4(b4, st + 16384 + swz8o(n0 + fn2 * 16 + b_r, ub));
#pragma unroll
                for (int fm = 0; fm < 4; fm++) {
#pragma unroll
                    for (int hf = 0; hf < 2; hf++)
                        mma16816(acc[fm][fn2 * 2 + hf], a4[fm], &b4[hf * 2]);
                }
            }
        }
        __syncthreads();
        if (kt + 2 < NKT)
            gemm_issue(sbase + (kt & 1) * GEMM_STAGE, A, B,
                       mBase, nBase, (kt + 2) * KT, tid);
        CP_COMMIT();
    }

    const int row_l = lane >> 2;
    const int col_l = (lane & 3) * 2;
#pragma unroll
    for (int fn = 0; fn < 4; fn++) {
        const int col = nBase + n0 + fn * 8 + col_l;
        const float2 bv = *reinterpret_cast<const float2*>(&bias[col]);
#pragma unroll
        for (int fm = 0; fm < 4; fm++) {
            const int row = mBase + m0 + fm * 16 + row_l;
            float v0 = acc[fm][fn][0] + bv.x;
            float v1 = acc[fm][fn][1] + bv.y;
            float v2 = acc[fm][fn][2] + bv.x;
            float v3 = acc[fm][fn][3] + bv.y;
            if (mode == 0) {
                *reinterpret_cast<float2*>(&C[(size_t)row * DD + col]) = make_float2(v0, v1);
                *reinterpret_cast<float2*>(&C[(size_t)(row + 8) * DD + col]) = make_float2(v2, v3);
            } else if (mode == 3) {
                *reinterpret_cast<uint32_t*>(&Oh[(size_t)row * DD + col]) = cvt2h(v0, v1);
                *reinterpret_cast<uint32_t*>(&Oh[(size_t)(row + 8) * DD + col]) = cvt2h(v2, v3);
            } else {
                // transposed single: vt[(b*768+col)][n]
                float vv[4] = {v0, v1, v2, v3};
#pragma unroll
                for (int e = 0; e < 4; e++) {
                    const int rr = row + (e >> 1) * 8;
                    const int cc = col + (e & 1);
                    const int bb = rr >> 10, nn = rr & 1023;
                    Oh[(size_t)(bb * DD + cc) * NN + nn] = __float2half_rn(vv[e]);
                }
            }
        }
    }
}

__global__ __launch_bounds__(256, 2) void qkv_mma_kernel(
    const __half* __restrict__ A, const __half* __restrict__ W,
    const float* __restrict__ bq, const float* __restrict__ bk,
    const float* __restrict__ bv,
    __half* __restrict__ q, __half* __restrict__ k, __half* __restrict__ vt) {
    const int z = blockIdx.z;
    const size_t ws = (size_t)z * DD * DD;
    if (z == 0)
        gemm_body(A, W + ws, bq, 3, nullptr, q);
    else if (z == 1)
        gemm_body(A, W + ws, bk, 3, nullptr, k);
    else
        gemm_body(A, W + ws, bv, 2, nullptr, vt);
}

__global__ __launch_bounds__(256, 2) void out_mma_kernel(
    const __half* __restrict__ A, const __half* __restrict__ W,
    const float* __restrict__ bias, float* __restrict__ C) {
    gemm_body(A, W, bias, 0, C, nullptr);
}

// ---------------------------------------------------------------------------
// fp16 tensor-core flash attention, quiet softmax.
// Raw-unit running max; P = ex2(fma(S, SCALEQ, 10 - m*SCALEQ)) (scaled 2^10).
// Q/K/P/V all single fp16.  PV stage INTERLEAVES exp+pack+MMA per 16-key
// block so MUFU overlaps the tensor pipe instead of serializing.
// Block = 128 q-rows of one (b,h); 8 warps x 16 rows; 64-key tiles, 16 iters.
// 4-stage pipeline, one barrier per iteration.
// smem: Q 16K | 4 x (K 8K | V 8K) = 80K.
// ---------------------------------------------------------------------------
#define ATTN_STAGE 16384
#define ATTN_SMEM (16384 + 4 * ATTN_STAGE)   // 81920

__device__ __forceinline__ void attn_issue(
    uint32_t st, const __half* k_, const __half* vt_,
    int b, int hoff, int kt, int tid) {
    const int tok0 = b * NN + kt * 64;
#pragma unroll
    for (int i = 0; i < 2; i++) {   // K: 512 units (64 rows x 8u)
        const int t = tid + i * 256;
        const int r = (t >> 3) & 63, u = t & 7;
        cp16(st + swz8o(r, u), k_ + (size_t)(tok0 + r) * DD + hoff + u * 8);
    }
#pragma unroll
    for (int i = 0; i < 2; i++) {   // V: 512 units (64 d-rows x 8u)
        const int t = tid + i * 256;
        const int r = (t >> 3) & 63, u = t & 7;
        cp16(st + 8192 + swz8o(r, u),
             vt_ + (size_t)(b * DD + hoff + r) * NN + kt * 64 + u * 8);
    }
}

__global__ __launch_bounds__(256, 2) void attn_mma_kernel(
    const __half* __restrict__ q_, const __half* __restrict__ k_,
    const __half* __restrict__ vt_, __half* __restrict__ c_) {
    extern __shared__ char smem[];
    const uint32_t sb = s2u(smem);
    const int tid = threadIdx.x;
    const int wid = tid >> 5;
    const int lane = tid & 31;
    const int qt = blockIdx.x;        // 0..7 (128-row tiles)
    const int bh = blockIdx.y;        // 0..95
    const int b = bh / HH;
    const int h = bh - b * HH;
    const int hoff = h * HD;
    const int q0 = b * NN + qt * 128;
    const int strip = wid * 16;

    // Q tile: 1024 units (128 rows x 8u)
#pragma unroll
    for (int i = 0; i < 4; i++) {
        const int t = tid + i * 256;
        const int r = (t >> 3) & 127, u = t & 7;
        cp16(sb + swz8o(r, u), q_ + (size_t)(q0 + r) * DD + hoff + u * 8);
    }
    CP_COMMIT();
    attn_issue(sb + 16384 + 0 * ATTN_STAGE, k_, vt_, b, hoff, 0, tid);
    CP_COMMIT();
    attn_issue(sb + 16384 + 1 * ATTN_STAGE, k_, vt_, b, hoff, 1, tid);
    CP_COMMIT();
    attn_issue(sb + 16384 + 2 * ATTN_STAGE, k_, vt_, b, hoff, 2, tid);
    CP_COMMIT();

    const int a_r = lane & 15;
    const int a_uh = lane >> 4;
    const int b_r = ((lane >> 4) & 1) * 8 + (lane & 7);
    const int b_uh = (lane >> 3) & 1;

    float m_[2] = {-1e30f, -1e30f};   // raw score units
    float l_[2] = {0.0f, 0.0f};
    float ctx[8][4];
#pragma unroll
    for (int fn = 0; fn < 8; fn++)
#pragma unroll
        for (int q = 0; q < 4; q++) ctx[fn][q] = 0.0f;

    for (int kt = 0; kt < 16; kt++) {
        CP_WAIT2();
        __syncthreads();
        const uint32_t st = sb + 16384 + (kt & 3) * ATTN_STAGE;

        // ---- S[16 q x 64 keys] = Q K^T (raw units) ----
        float S[8][4];
#pragma unroll
        for (int fn = 0; fn < 8; fn++)
#pragma unroll
            for (int q = 0; q < 4; q++) S[fn][q] = 0.0f;

#pragma unroll
        for (int ks = 0; ks < 4; ks++) {
            const int ua = ks * 2 + a_uh;
            const int ub = ks * 2 + b_uh;
            uint32_t q4[4];
            ldm_x4(q4, sb + swz8o(strip + a_r, ua));
#pragma unroll
            for (int fn2 = 0; fn2 < 4; fn2++) {
                uint32_t k4[4];
                ldm_x4(k4, st + swz8o(fn2 * 16 + b_r, ub));
                mma16816(S[fn2 * 2 + 0], q4, &k4[0]);
                mma16816(S[fn2 * 2 + 1], q4, &k4[2]);
            }
        }

        // ---- online quiet softmax: max reduce + ctx rescale ----
        float mx[2] = {-1e30f, -1e30f};
#pragma unroll
        for (int fn = 0; fn < 8; fn++) {
            mx[0] = fmaxf(mx[0], fmaxf(S[fn][0], S[fn][1]));
            mx[1] = fmaxf(mx[1], fmaxf(S[fn][2], S[fn][3]));
        }
        float corr[2], cc[2];
#pragma unroll
        for (int j = 0; j < 2; j++) {
            mx[j] = fmaxf(mx[j], __shfl_xor_sync(0xffffffffu, mx[j], 1));
            mx[j] = fmaxf(mx[j], __shfl_xor_sync(0xffffffffu, mx[j], 2));
            const float mn = fmaxf(m_[j], mx[j]);
            corr[j] = ex2((m_[j] - mn) * SCALEQ);
            m_[j] = mn;
            cc[j] = fmaf(-mn, SCALEQ, 10.0f);   // 10 - m*SCALEQ
        }
#pragma unroll
        for (int fn = 0; fn < 8; fn++) {
            ctx[fn][0] *= corr[0];
            ctx[fn][1] *= corr[0];
            ctx[fn][2] *= corr[1];
            ctx[fn][3] *= corr[1];
        }

        // ---- interleaved exp + pack + PV per 16-key block ----
        float ps0 = 0.0f, ps1 = 0.0f;
#pragma unroll
        for (int kb = 0; kb < 4; kb++) {
            const float e00 = ex2(fmaf(S[2 * kb][0], SCALEQ, cc[0]));
            const float e01 = ex2(fmaf(S[2 * kb][1], SCALEQ, cc[0]));
            const float e02 = ex2(fmaf(S[2 * kb][2], SCALEQ, cc[1]));
            const float e03 = ex2(fmaf(S[2 * kb][3], SCALEQ, cc[1]));
            const float e10 = ex2(fmaf(S[2 * kb + 1][0], SCALEQ, cc[0]));
            const float e11 = ex2(fmaf(S[2 * kb + 1][1], SCALEQ, cc[0]));
            const float e12 = ex2(fmaf(S[2 * kb + 1][2], SCALEQ, cc[1]));
            const float e13 = ex2(fmaf(S[2 * kb + 1][3], SCALEQ, cc[1]));
            ps0 += (e00 + e01) + (e10 + e11);
            ps1 += (e02 + e03) + (e12 + e13);
            uint32_t pa[4];
            pa[0] = cvt2h(e00, e01);
            pa[1] = cvt2h(e02, e03);
            pa[2] = cvt2h(e10, e11);
            pa[3] = cvt2h(e12, e13);
            const int ub = kb * 2 + b_uh;
#pragma unroll
            for (int fn2 = 0; fn2 < 4; fn2++) {
                uint32_t v4[4];
                ldm_x4(v4, st + 8192 + swz8o(fn2 * 16 + b_r, ub));
#pragma unroll
                for (int hf = 0; hf < 2; hf++)
                    mma16816(ctx[fn2 * 2 + hf], pa, &v4[hf * 2]);
            }
        }
        ps0 += __shfl_xor_sync(0xffffffffu, ps0, 1);
        ps0 += __shfl_xor_sync(0xffffffffu, ps0, 2);
        ps1 += __shfl_xor_sync(0xffffffffu, ps1, 1);
        ps1 += __shfl_xor_sync(0xffffffffu, ps1, 2);
        l_[0] = l_[0] * corr[0] + ps0;
        l_[1] = l_[1] * corr[1] + ps1;

        // Single barrier per iter: refill slot (kt+3)&3 == (kt-1)&3 is safe
        // because every warp passed the top barrier of iter kt.
        if (kt + 3 < 16)
            attn_issue(sb + 16384 + ((kt + 3) & 3) * ATTN_STAGE,
                       k_, vt_, b, hoff, kt + 3, tid);
        CP_COMMIT();
    }

    // ---- epilogue: out = ctx' / (1024 + l'); emit half single ----
    const float inv0 = 1.0f / (1024.0f + l_[0]);
    const float inv1 = 1.0f / (1024.0f + l_[1]);
    const int rowA = q0 + strip + (lane >> 2);
    const int rowB = rowA + 8;
#pragma unroll
    for (int fn = 0; fn < 8; fn++) {
        const int col = hoff + fn * 8 + (lane & 3) * 2;
        *reinterpret_cast<uint32_t*>(&c_[(size_t)rowA * DD + col]) =
            cvt2h(ctx[fn][0] * inv0, ctx[fn][1] * inv0);
        *reinterpret_cast<uint32_t*>(&c_[(size_t)rowB * DD + col]) =
            cvt2h(ctx[fn][2] * inv1, ctx[fn][3] * inv1);
    }
}

// ---------------------------------------------------------------------------
// Launch
// ---------------------------------------------------------------------------
extern "C" void kernel_launch(void* const* d_in, const int* in_sizes, int n_in,
                              void* d_out, int out_size) {
    const float* x  = (const float*)d_in[0];
    const float* Wq = (const float*)d_in[1];
    const float* bq = (const float*)d_in[2];
    const float* Wk = (const float*)d_in[3];
    const float* bk = (const float*)d_in[4];
    const float* Wv = (const float*)d_in[5];
    const float* bv = (const float*)d_in[6];
    const float* Wo = (const float*)d_in[7];
    const float* bo = (const float*)d_in[8];
    float* out = (float*)d_out;
    (void)in_sizes; (void)n_in; (void)out_size;

    __half *xs, *q, *k, *vt, *c, *w;
    cudaGetSymbolAddress((void**)&xs, g_x);
    cudaGetSymbolAddress((void**)&q, g_q);
    cudaGetSymbolAddress((void**)&k, g_k);
    cudaGetSymbolAddress((void**)&vt, g_vt);
    cudaGetSymbolAddress((void**)&c, g_c);
    cudaGetSymbolAddress((void**)&w, g_w);

    cudaFuncSetAttribute(qkv_mma_kernel, cudaFuncAttributeMaxDynamicSharedMemorySize,
                         GEMM_SMEM);
    cudaFuncSetAttribute(out_mma_kernel, cudaFuncAttributeMaxDynamicSharedMemorySize,
                         GEMM_SMEM);
    cudaFuncSetAttribute(attn_mma_kernel, cudaFuncAttributeMaxDynamicSharedMemorySize,
                         ATTN_SMEM);

    const size_t ws = (size_t)DD * DD;
    dim3 blk(256);

    convert_half_kernel<<<MM * DD / 8 / 256, blk>>>(x, xs);
    convert_wt_kernel<<<dim3(12, 12, 4), blk>>>(Wq, Wk, Wv, Wo, w);
    qkv_mma_kernel<<<dim3(6, 64, 3), blk, GEMM_SMEM>>>(xs, w, bq, bk, bv, q, k, vt);
    attn_mma_kernel<<<dim3(8, 96), blk, ATTN_SMEM>>>(q, k, vt, c);
    out_mma_kernel<<<dim3(6, 64), blk, GEMM_SMEM>>>(c, w + 3 * ws, bo, out);
}

// round 13
// speedup vs baseline: 8.1723x; 1.0291x over previous
#include <cuda_runtime.h>
#include <cuda_fp16.h>
#include <cstdint>

// Problem constants
#define BB 8
#define NN 1024
#define DD 768
#define HH 12
#define HD 64
#define MM (BB * NN)   // 8192 rows
#define SCALEQ 0.18033688011112042591f   // 0.125 * log2(e), applied post-MMA

// ---------------------------------------------------------------------------
// Scratch (__device__ globals; no allocation allowed)
// ---------------------------------------------------------------------------
__device__ __half g_x[MM * DD];                   // x single
__device__ __half g_q[MM * DD];                   // q single (UNSCALED)
__device__ __half g_k[MM * DD];                   // k single
__device__ __half g_vt[MM * DD];                  // v single, transposed [(b*768+d)][n]
__device__ __half g_c[MM * DD];                   // attention output single
__device__ __half g_w[4 * DD * DD];               // weights single, transposed [n][k]

// ---------------------------------------------------------------------------
// PTX helpers
// ---------------------------------------------------------------------------
__device__ __forceinline__ uint32_t s2u(const void* p) {
    uint32_t a;
    asm("{ .reg .u64 t; cvta.to.shared.u64 t, %1; cvt.u32.u64 %0, t; }"
        : "=r"(a) : "l"(p));
    return a;
}
__device__ __forceinline__ void cp16(uint32_t dst, const void* src) {
    asm volatile("cp.async.cg.shared.global [%0], [%1], 16;" :: "r"(dst), "l"(src));
}
#define CP_COMMIT() asm volatile("cp.async.commit_group;" ::: "memory")
#define CP_WAIT0()  asm volatile("cp.async.wait_group 0;" ::: "memory")
#define CP_WAIT1()  asm volatile("cp.async.wait_group 1;" ::: "memory")

__device__ __forceinline__ void ldm_x4(uint32_t* r, uint32_t addr) {
    asm volatile("ldmatrix.sync.aligned.m8n8.x4.shared.b16 {%0,%1,%2,%3}, [%4];"
                 : "=r"(r[0]), "=r"(r[1]), "=r"(r[2]), "=r"(r[3]) : "r"(addr));
}
__device__ __forceinline__ void mma16816(float* c, const uint32_t* a, const uint32_t* b) {
    asm volatile(
        "mma.sync.aligned.m16n8k16.row.col.f32.f16.f16.f32 "
        "{%0,%1,%2,%3}, {%4,%5,%6,%7}, {%8,%9}, {%0,%1,%2,%3};"
        : "+f"(c[0]), "+f"(c[1]), "+f"(c[2]), "+f"(c[3])
        : "r"(a[0]), "r"(a[1]), "r"(a[2]), "r"(a[3]), "r"(b[0]), "r"(b[1]));
}
__device__ __forceinline__ float ex2(float x) {
    float y;
    asm("ex2.approx.ftz.f32 %0, %1;" : "=f"(y) : "f"(x));
    return y;
}
// pack two fp32 into f16x2 in ONE instruction.  First asm source = HIGH half.
__device__ __forceinline__ uint32_t cvt2h(float lo, float hi) {
    uint32_t r;
    asm("cvt.rn.f16x2.f32 %0, %1, %2;" : "=r"(r) : "f"(hi), "f"(lo));
    return r;
}

// swizzled offset within a tile of 128B rows (8 16B units per row)
__device__ __forceinline__ uint32_t swz8o(int r, int u) {
    return (uint32_t)(r * 128 + ((u ^ (r & 7)) << 4));
}

// ---------------------------------------------------------------------------
// Conversions
// ---------------------------------------------------------------------------
__global__ __launch_bounds__(256) void convert_half_kernel(
    const float* __restrict__ src, __half* __restrict__ dst) {
    const int idx = blockIdx.x * 256 + threadIdx.x;
    const float4 v0 = *reinterpret_cast<const float4*>(&src[idx * 8]);
    const float4 v1 = *reinterpret_cast<const float4*>(&src[idx * 8 + 4]);
    uint4 p;
    p.x = cvt2h(v0.x, v0.y);
    p.y = cvt2h(v0.z, v0.w);
    p.z = cvt2h(v1.x, v1.y);
    p.w = cvt2h(v1.z, v1.w);
    reinterpret_cast<uint4*>(dst)[idx] = p;
}

__global__ __launch_bounds__(256) void convert_wt_kernel(
    const float* __restrict__ Wq, const float* __restrict__ Wk,
    const float* __restrict__ Wv, const float* __restrict__ Wo,
    __half* __restrict__ dw) {
    __shared__ float tile[64][65];
    const int z = blockIdx.z;
    const float* W = (z == 0) ? Wq : (z == 1) ? Wk : (z == 2) ? Wv : Wo;
    __half* ow = dw + (size_t)z * DD * DD;
    const int k0 = blockIdx.x * 64;
    const int n0 = blockIdx.y * 64;
    const int tid = threadIdx.x;
#pragma unroll
    for (int t = tid; t < 64 * 16; t += 256) {
        const int i = t >> 4;
        const int j4 = (t & 15) * 4;
        const float4 w = *reinterpret_cast<const float4*>(&W[(k0 + i) * DD + n0 + j4]);
        tile[i][j4 + 0] = w.x;
        tile[i][j4 + 1] = w.y;
        tile[i][j4 + 2] = w.z;
        tile[i][j4 + 3] = w.w;
    }
    __syncthreads();
#pragma unroll
    for (int t = tid; t < 64 * 8; t += 256) {
        const int nl = t >> 3;
        const int kin = (t & 7) * 8;
        uint4 pw;
        uint32_t* wp = &pw.x;
#pragma unroll
        for (int m = 0; m < 4; m++)
            wp[m] = cvt2h(tile[kin + m * 2][nl], tile[kin + m * 2 + 1][nl]);
        reinterpret_cast<uint4*>(ow)[((size_t)(n0 + nl) * DD + k0 + kin) >> 3] = pw;
    }
}

// ---------------------------------------------------------------------------
// fp16 single GEMM: C = A @ B^T (+bias).
// CTA tile 128m x 128n, 8 warps (2m x 4n), warp tile 64x32.  KT=64,
// 2-stage cp.async pipeline.  Stage: A 16K | B 16K = 32K; x2 = 64K.
// Epilogue modes: 0 fp32+bias; 2 transposed half single; 3 half single.
// ---------------------------------------------------------------------------
#define KT 64
#define GEMM_STAGE 32768
#define GEMM_SMEM (2 * GEMM_STAGE)   // 65536

__device__ __forceinline__ void gemm_issue(
    uint32_t sb, const __half* A, const __half* B,
    int mBase, int nBase, int kBase, int tid) {
#pragma unroll
    for (int i = 0; i < 4; i++) {   // A: 1024 units (128 r x 8 u)
        const int t = tid + i * 256;
        const int r = (t >> 3) & 127, u = t & 7;
        cp16(sb + swz8o(r, u), A + (size_t)(mBase + r) * DD + kBase + u * 8);
    }
#pragma unroll
    for (int i = 0; i < 4; i++) {   // B: 1024 units (128 r x 8 u)
        const int t = tid + i * 256;
        const int r = (t >> 3) & 127, u = t & 7;
        cp16(sb + 16384 + swz8o(r, u),
             B + (size_t)(nBase + r) * DD + kBase + u * 8);
    }
}

__device__ __forceinline__ void gemm_body(
    const __half* __restrict__ A, const __half* __restrict__ B,
    const float* __restrict__ bias, int mode,
    float* __restrict__ C, __half* __restrict__ Oh) {
    extern __shared__ char smem[];
    const uint32_t sbase = s2u(smem);

    const int tid = threadIdx.x;
    const int wid = tid >> 5;
    const int lane = tid & 31;
    const int m0 = (wid >> 2) * 64;
    const int n0 = (wid & 3) * 32;
    const int mBase = blockIdx.y * 128;
    const int nBase = blockIdx.x * 128;

    float acc[4][4][4];
#pragma unroll
    for (int i = 0; i < 4; i++)
#pragma unroll
        for (int j = 0; j < 4; j++)
#pragma unroll
            for (int q = 0; q < 4; q++) acc[i][j][q] = 0.0f;

    gemm_issue(sbase, A, B, mBase, nBase, 0, tid);
    CP_COMMIT();
    gemm_issue(sbase + GEMM_STAGE, A, B, mBase, nBase, KT, tid);
    CP_COMMIT();

    const int a_r = lane & 15;
    const int a_uh = lane >> 4;
    const int b_r = ((lane >> 4) & 1) * 8 + (lane & 7);
    const int b_uh = (lane >> 3) & 1;

    const int NKT = DD / KT;   // 12
    for (int kt = 0; kt < NKT; kt++) {
        CP_WAIT1();
        __syncthreads();
        const uint32_t st = sbase + (kt & 1) * GEMM_STAGE;
#pragma unroll
        for (int ks = 0; ks < 4; ks++) {
            const int ua = ks * 2 + a_uh;
            const int ub = ks * 2 + b_uh;
            uint32_t a4[4][4];
#pragma unroll
            for (int fm = 0; fm < 4; fm++)
                ldm_x4(a4[fm], st + swz8o(m0 + fm * 16 + a_r, ua));
#pragma unroll
            for (int fn2 = 0; fn2 < 2; fn2++) {
                uint32_t b4[4];
                ldm_x4(b4, st + 16384 + swz8o(n0 + fn2 * 16 + b_r, ub));
#pragma unroll
                for (int fm = 0; fm < 4; fm++) {
#pragma unroll
                    for (int hf = 0; hf < 2; hf++)
                        mma16816(acc[fm][fn2 * 2 + hf], a4[fm], &b4[hf * 2]);
                }
            }
        }
        __syncthreads();
        if (kt + 2 < NKT)
            gemm_issue(sbase + (kt & 1) * GEMM_STAGE, A, B,
                       mBase, nBase, (kt + 2) * KT, tid);
        CP_COMMIT();
    }

    const int row_l = lane >> 2;
    const int col_l = (lane & 3) * 2;
#pragma unroll
    for (int fn = 0; fn < 4; fn++) {
        const int col = nBase + n0 + fn * 8 + col_l;
        const float2 bv = *reinterpret_cast<const float2*>(&bias[col]);
#pragma unroll
        for (int fm = 0; fm < 4; fm++) {
            const int row = mBase + m0 + fm * 16 + row_l;
            float v0 = acc[fm][fn][0] + bv.x;
            float v1 = acc[fm][fn][1] + bv.y;
            float v2 = acc[fm][fn][2] + bv.x;
            float v3 = acc[fm][fn][3] + bv.y;
            if (mode == 0) {
                *reinterpret_cast<float2*>(&C[(size_t)row * DD + col]) = make_float2(v0, v1);
                *reinterpret_cast<float2*>(&C[(size_t)(row + 8) * DD + col]) = make_float2(v2, v3);
            } else if (mode == 3) {
                *reinterpret_cast<uint32_t*>(&Oh[(size_t)row * DD + col]) = cvt2h(v0, v1);
                *reinterpret_cast<uint32_t*>(&Oh[(size_t)(row + 8) * DD + col]) = cvt2h(v2, v3);
            } else {
                // transposed single: vt[(b*768+col)][n]
                float vv[4] = {v0, v1, v2, v3};
#pragma unroll
                for (int e = 0; e < 4; e++) {
                    const int rr = row + (e >> 1) * 8;
                    const int cc = col + (e & 1);
                    const int bb = rr >> 10, nn = rr & 1023;
                    Oh[(size_t)(bb * DD + cc) * NN + nn] = __float2half_rn(vv[e]);
                }
            }
        }
    }
}

__global__ __launch_bounds__(256, 2) void qkv_mma_kernel(
    const __half* __restrict__ A, const __half* __restrict__ W,
    const float* __restrict__ bq, const float* __restrict__ bk,
    const float* __restrict__ bv,
    __half* __restrict__ q, __half* __restrict__ k, __half* __restrict__ vt) {
    const int z = blockIdx.z;
    const size_t ws = (size_t)z * DD * DD;
    if (z == 0)
        gemm_body(A, W + ws, bq, 3, nullptr, q);
    else if (z == 1)
        gemm_body(A, W + ws, bk, 3, nullptr, k);
    else
        gemm_body(A, W + ws, bv, 2, nullptr, vt);
}

__global__ __launch_bounds__(256, 2) void out_mma_kernel(
    const __half* __restrict__ A, const __half* __restrict__ W,
    const float* __restrict__ bias, float* __restrict__ C) {
    gemm_body(A, W, bias, 0, C, nullptr);
}

// ---------------------------------------------------------------------------
// fp16 tensor-core flash attention, quiet softmax.
// Raw-unit running max; P = ex2(fma(S, SCALEQ, 10 - m*SCALEQ)) (scaled 2^10).
// Q/K/P/V all single fp16.  PV interleaves exp+pack+MMA per 16-key block.
// RESTRUCTURED: 128-thread CTAs (4 warps x 16 q-rows = 64 q-rows/CTA),
// 40KB smem -> 4 CTAs/SM = 4 independent barrier domains (phase decorrelation).
// 2-stage pipeline, refill at top of loop: wait(kt) -> bar -> issue(kt+1)
// (slot kt-1's buffer; all warps finished it) -> compute(kt).
// smem: Q 8K | 2 x (K 8K | V 8K) = 40K.
// ---------------------------------------------------------------------------
#define ATTN_STAGE 16384
#define ATTN_SMEM (8192 + 2 * ATTN_STAGE)   // 40960

__device__ __forceinline__ void attn_issue(
    uint32_t st, const __half* k_, const __half* vt_,
    int b, int hoff, int kt, int tid) {
    const int tok0 = b * NN + kt * 64;
#pragma unroll
    for (int i = 0; i < 4; i++) {   // K: 512 units (64 rows x 8u)
        const int t = tid + i * 128;
        const int r = (t >> 3) & 63, u = t & 7;
        cp16(st + swz8o(r, u), k_ + (size_t)(tok0 + r) * DD + hoff + u * 8);
    }
#pragma unroll
    for (int i = 0; i < 4; i++) {   // V: 512 units (64 d-rows x 8u)
        const int t = tid + i * 128;
        const int r = (t >> 3) & 63, u = t & 7;
        cp16(st + 8192 + swz8o(r, u),
             vt_ + (size_t)(b * DD + hoff + r) * NN + kt * 64 + u * 8);
    }
}

__global__ __launch_bounds__(128, 4) void attn_mma_kernel(
    const __half* __restrict__ q_, const __half* __restrict__ k_,
    const __half* __restrict__ vt_, __half* __restrict__ c_) {
    extern __shared__ char smem[];
    const uint32_t sb = s2u(smem);
    const int tid = threadIdx.x;
    const int wid = tid >> 5;
    const int lane = tid & 31;
    const int qt = blockIdx.x;        // 0..15 (64-row tiles)
    const int bh = blockIdx.y;        // 0..95
    const int b = bh / HH;
    const int h = bh - b * HH;
    const int hoff = h * HD;
    const int q0 = b * NN + qt * 64;
    const int strip = wid * 16;

    // Q tile: 512 units (64 rows x 8u) + stage 0 in one group
#pragma unroll
    for (int i = 0; i < 4; i++) {
        const int t = tid + i * 128;
        const int r = (t >> 3) & 63, u = t & 7;
        cp16(sb + swz8o(r, u), q_ + (size_t)(q0 + r) * DD + hoff + u * 8);
    }
    attn_issue(sb + 8192, k_, vt_, b, hoff, 0, tid);
    CP_COMMIT();

    const int a_r = lane & 15;
    const int a_uh = lane >> 4;
    const int b_r = ((lane >> 4) & 1) * 8 + (lane & 7);
    const int b_uh = (lane >> 3) & 1;

    float m_[2] = {-1e30f, -1e30f};   // raw score units
    float l_[2] = {0.0f, 0.0f};
    float ctx[8][4];
#pragma unroll
    for (int fn = 0; fn < 8; fn++)
#pragma unroll
        for (int q = 0; q < 4; q++) ctx[fn][q] = 0.0f;

    for (int kt = 0; kt < 16; kt++) {
        CP_WAIT0();
        __syncthreads();
        // Refill the OTHER slot (buffer of kt-1; all warps are done with it).
        if (kt + 1 < 16) {
            attn_issue(sb + 8192 + ((kt + 1) & 1) * ATTN_STAGE,
                       k_, vt_, b, hoff, kt + 1, tid);
        }
        CP_COMMIT();
        const uint32_t st = sb + 8192 + (kt & 1) * ATTN_STAGE;

        // ---- S[16 q x 64 keys] = Q K^T (raw units) ----
        float S[8][4];
#pragma unroll
        for (int fn = 0; fn < 8; fn++)
#pragma unroll
            for (int q = 0; q < 4; q++) S[fn][q] = 0.0f;

#pragma unroll
        for (int ks = 0; ks < 4; ks++) {
            const int ua = ks * 2 + a_uh;
            const int ub = ks * 2 + b_uh;
            uint32_t q4[4];
            ldm_x4(q4, sb + swz8o(strip + a_r, ua));
#pragma unroll
            for (int fn2 = 0; fn2 < 4; fn2++) {
                uint32_t k4[4];
                ldm_x4(k4, st + swz8o(fn2 * 16 + b_r, ub));
                mma16816(S[fn2 * 2 + 0], q4, &k4[0]);
                mma16816(S[fn2 * 2 + 1], q4, &k4[2]);
            }
        }

        // ---- online quiet softmax: max reduce + ctx rescale ----
        float mx[2] = {-1e30f, -1e30f};
#pragma unroll
        for (int fn = 0; fn < 8; fn++) {
            mx[0] = fmaxf(mx[0], fmaxf(S[fn][0], S[fn][1]));
            mx[1] = fmaxf(mx[1], fmaxf(S[fn][2], S[fn][3]));
        }
        float corr[2], cc[2];
#pragma unroll
        for (int j = 0; j < 2; j++) {
            mx[j] = fmaxf(mx[j], __shfl_xor_sync(0xffffffffu, mx[j], 1));
            mx[j] = fmaxf(mx[j], __shfl_xor_sync(0xffffffffu, mx[j], 2));
            const float mn = fmaxf(m_[j], mx[j]);
            corr[j] = ex2((m_[j] - mn) * SCALEQ);
            m_[j] = mn;
            cc[j] = fmaf(-mn, SCALEQ, 10.0f);   // 10 - m*SCALEQ
        }
#pragma unroll
        for (int fn = 0; fn < 8; fn++) {
            ctx[fn][0] *= corr[0];
            ctx[fn][1] *= corr[0];
            ctx[fn][2] *= corr[1];
            ctx[fn][3] *= corr[1];
        }

        // ---- interleaved exp + pack + PV per 16-key block ----
        float ps0 = 0.0f, ps1 = 0.0f;
#pragma unroll
        for (int kb = 0; kb < 4; kb++) {
            const float e00 = ex2(fmaf(S[2 * kb][0], SCALEQ, cc[0]));
            const float e01 = ex2(fmaf(S[2 * kb][1], SCALEQ, cc[0]));
            const float e02 = ex2(fmaf(S[2 * kb][2], SCALEQ, cc[1]));
            const float e03 = ex2(fmaf(S[2 * kb][3], SCALEQ, cc[1]));
            const float e10 = ex2(fmaf(S[2 * kb + 1][0], SCALEQ, cc[0]));
            const float e11 = ex2(fmaf(S[2 * kb + 1][1], SCALEQ, cc[0]));
            const float e12 = ex2(fmaf(S[2 * kb + 1][2], SCALEQ, cc[1]));
            const float e13 = ex2(fmaf(S[2 * kb + 1][3], SCALEQ, cc[1]));
            ps0 += (e00 + e01) + (e10 + e11);
            ps1 += (e02 + e03) + (e12 + e13);
            uint32_t pa[4];
            pa[0] = cvt2h(e00, e01);
            pa[1] = cvt2h(e02, e03);
            pa[2] = cvt2h(e10, e11);
            pa[3] = cvt2h(e12, e13);
            const int ub = kb * 2 + b_uh;
#pragma unroll
            for (int fn2 = 0; fn2 < 4; fn2++) {
                uint32_t v4[4];
                ldm_x4(v4, st + 8192 + swz8o(fn2 * 16 + b_r, ub));
#pragma unroll
                for (int hf = 0; hf < 2; hf++)
                    mma16816(ctx[fn2 * 2 + hf], pa, &v4[hf * 2]);
            }
        }
        ps0 += __shfl_xor_sync(0xffffffffu, ps0, 1);
        ps0 += __shfl_xor_sync(0xffffffffu, ps0, 2);
        ps1 += __shfl_xor_sync(0xffffffffu, ps1, 1);
        ps1 += __shfl_xor_sync(0xffffffffu, ps1, 2);
        l_[0] = l_[0] * corr[0] + ps0;
        l_[1] = l_[1] * corr[1] + ps1;
    }

    // ---- epilogue: out = ctx' / (1024 + l'); emit half single ----
    const float inv0 = 1.0f / (1024.0f + l_[0]);
    const float inv1 = 1.0f / (1024.0f + l_[1]);
    const int rowA = q0 + strip + (lane >> 2);
    const int rowB = rowA + 8;
#pragma unroll
    for (int fn = 0; fn < 8; fn++) {
        const int col = hoff + fn * 8 + (lane & 3) * 2;
        *reinterpret_cast<uint32_t*>(&c_[(size_t)rowA * DD + col]) =
            cvt2h(ctx[fn][0] * inv0, ctx[fn][1] * inv0);
        *reinterpret_cast<uint32_t*>(&c_[(size_t)rowB * DD + col]) =
            cvt2h(ctx[fn][2] * inv1, ctx[fn][3] * inv1);
    }
}

// ---------------------------------------------------------------------------
// Launch
// ---------------------------------------------------------------------------
extern "C" void kernel_launch(void* const* d_in, const int* in_sizes, int n_in,
                              void* d_out, int out_size) {
    const float* x  = (const float*)d_in[0];
    const float* Wq = (const float*)d_in[1];
    const float* bq = (const float*)d_in[2];
    const float* Wk = (const float*)d_in[3];
    const float* bk = (const float*)d_in[4];
    const float* Wv = (const float*)d_in[5];
    const float* bv = (const float*)d_in[6];
    const float* Wo = (const float*)d_in[7];
    const float* bo = (const float*)d_in[8];
    float* out = (float*)d_out;
    (void)in_sizes; (void)n_in; (void)out_size;

    __half *xs, *q, *k, *vt, *c, *w;
    cudaGetSymbolAddress((void**)&xs, g_x);
    cudaGetSymbolAddress((void**)&q, g_q);
    cudaGetSymbolAddress((void**)&k, g_k);
    cudaGetSymbolAddress((void**)&vt, g_vt);
    cudaGetSymbolAddress((void**)&c, g_c);
    cudaGetSymbolAddress((void**)&w, g_w);

    cudaFuncSetAttribute(qkv_mma_kernel, cudaFuncAttributeMaxDynamicSharedMemorySize,
                         GEMM_SMEM);
    cudaFuncSetAttribute(out_mma_kernel, cudaFuncAttributeMaxDynamicSharedMemorySize,
                         GEMM_SMEM);
    cudaFuncSetAttribute(attn_mma_kernel, cudaFuncAttributeMaxDynamicSharedMemorySize,
                         ATTN_SMEM);

    const size_t ws = (size_t)DD * DD;

    convert_half_kernel<<<MM * DD / 8 / 256, 256>>>(x, xs);
    convert_wt_kernel<<<dim3(12, 12, 4), 256>>>(Wq, Wk, Wv, Wo, w);
    qkv_mma_kernel<<<dim3(6, 64, 3), 256, GEMM_SMEM>>>(xs, w, bq, bk, bv, q, k, vt);
    attn_mma_kernel<<<dim3(16, 96), 128, ATTN_SMEM>>>(q, k, vt, c);
    out_mma_kernel<<<dim3(6, 64), 256, GEMM_SMEM>>>(c, w + 3 * ws, bo, out);
}

// round 14
// speedup vs baseline: 8.2844x; 1.0137x over previous
#include <cuda_runtime.h>
#include <cuda_fp16.h>
#include <cstdint>

// Problem constants
#define BB 8
#define NN 1024
#define DD 768
#define HH 12
#define HD 64
#define MM (BB * NN)   // 8192 rows
#define SCALEQ 0.18033688011112042591f   // 0.125 * log2(e), applied post-MMA

// ---------------------------------------------------------------------------
// Scratch (__device__ globals; no allocation allowed)
// ---------------------------------------------------------------------------
__device__ __half g_x[MM * DD];                   // x single
__device__ __half g_q[MM * DD];                   // q single (UNSCALED)
__device__ __half g_k[MM * DD];                   // k single
__device__ __half g_vt[MM * DD];                  // v single, transposed [(b*768+d)][n]
__device__ __half g_c[MM * DD];                   // attention output single
__device__ __half g_w[4 * DD * DD];               // weights single, transposed [n][k]

// ---------------------------------------------------------------------------
// PTX helpers
// ---------------------------------------------------------------------------
__device__ __forceinline__ uint32_t s2u(const void* p) {
    uint32_t a;
    asm("{ .reg .u64 t; cvta.to.shared.u64 t, %1; cvt.u32.u64 %0, t; }"
        : "=r"(a) : "l"(p));
    return a;
}
__device__ __forceinline__ void cp16(uint32_t dst, const void* src) {
    asm volatile("cp.async.cg.shared.global [%0], [%1], 16;" :: "r"(dst), "l"(src));
}
#define CP_COMMIT() asm volatile("cp.async.commit_group;" ::: "memory")
#define CP_WAIT0()  asm volatile("cp.async.wait_group 0;" ::: "memory")
#define CP_WAIT1()  asm volatile("cp.async.wait_group 1;" ::: "memory")

__device__ __forceinline__ void ldm_x4(uint32_t* r, uint32_t addr) {
    asm volatile("ldmatrix.sync.aligned.m8n8.x4.shared.b16 {%0,%1,%2,%3}, [%4];"
                 : "=r"(r[0]), "=r"(r[1]), "=r"(r[2]), "=r"(r[3]) : "r"(addr));
}
__device__ __forceinline__ void mma16816(float* c, const uint32_t* a, const uint32_t* b) {
    asm volatile(
        "mma.sync.aligned.m16n8k16.row.col.f32.f16.f16.f32 "
        "{%0,%1,%2,%3}, {%4,%5,%6,%7}, {%8,%9}, {%0,%1,%2,%3};"
        : "+f"(c[0]), "+f"(c[1]), "+f"(c[2]), "+f"(c[3])
        : "r"(a[0]), "r"(a[1]), "r"(a[2]), "r"(a[3]), "r"(b[0]), "r"(b[1]));
}
__device__ __forceinline__ float ex2(float x) {
    float y;
    asm("ex2.approx.ftz.f32 %0, %1;" : "=f"(y) : "f"(x));
    return y;
}
// pack two fp32 into f16x2 in ONE instruction.  First asm source = HIGH half.
__device__ __forceinline__ uint32_t cvt2h(float lo, float hi) {
    uint32_t r;
    asm("cvt.rn.f16x2.f32 %0, %1, %2;" : "=r"(r) : "f"(hi), "f"(lo));
    return r;
}

// swizzled offset within a tile of 128B rows (8 16B units per row)
__device__ __forceinline__ uint32_t swz8o(int r, int u) {
    return (uint32_t)(r * 128 + ((u ^ (r & 7)) << 4));
}

// ---------------------------------------------------------------------------
// Conversions
// ---------------------------------------------------------------------------
__global__ __launch_bounds__(256) void convert_half_kernel(
    const float* __restrict__ src, __half* __restrict__ dst) {
    const int idx = blockIdx.x * 256 + threadIdx.x;
    const float4 v0 = *reinterpret_cast<const float4*>(&src[idx * 8]);
    const float4 v1 = *reinterpret_cast<const float4*>(&src[idx * 8 + 4]);
    uint4 p;
    p.x = cvt2h(v0.x, v0.y);
    p.y = cvt2h(v0.z, v0.w);
    p.z = cvt2h(v1.x, v1.y);
    p.w = cvt2h(v1.z, v1.w);
    reinterpret_cast<uint4*>(dst)[idx] = p;
}

__global__ __launch_bounds__(256) void convert_wt_kernel(
    const float* __restrict__ Wq, const float* __restrict__ Wk,
    const float* __restrict__ Wv, const float* __restrict__ Wo,
    __half* __restrict__ dw) {
    __shared__ float tile[64][65];
    const int z = blockIdx.z;
    const float* W = (z == 0) ? Wq : (z == 1) ? Wk : (z == 2) ? Wv : Wo;
    __half* ow = dw + (size_t)z * DD * DD;
    const int k0 = blockIdx.x * 64;
    const int n0 = blockIdx.y * 64;
    const int tid = threadIdx.x;
#pragma unroll
    for (int t = tid; t < 64 * 16; t += 256) {
        const int i = t >> 4;
        const int j4 = (t & 15) * 4;
        const float4 w = *reinterpret_cast<const float4*>(&W[(k0 + i) * DD + n0 + j4]);
        tile[i][j4 + 0] = w.x;
        tile[i][j4 + 1] = w.y;
        tile[i][j4 + 2] = w.z;
        tile[i][j4 + 3] = w.w;
    }
    __syncthreads();
#pragma unroll
    for (int t = tid; t < 64 * 8; t += 256) {
        const int nl = t >> 3;
        const int kin = (t & 7) * 8;
        uint4 pw;
        uint32_t* wp = &pw.x;
#pragma unroll
        for (int m = 0; m < 4; m++)
            wp[m] = cvt2h(tile[kin + m * 2][nl], tile[kin + m * 2 + 1][nl]);
        reinterpret_cast<uint4*>(ow)[((size_t)(n0 + nl) * DD + k0 + kin) >> 3] = pw;
    }
}

// ---------------------------------------------------------------------------
// fp16 single GEMM: C = A @ B^T (+bias).
// CTA tile 128m x 128n, 8 warps (2m x 4n), warp tile 64x32.  KT=64,
// 2-stage cp.async pipeline.  Stage: A 16K | B 16K = 32K; x2 = 64K.
// Epilogue modes: 0 fp32+bias; 2 transposed half single; 3 half single.
// ---------------------------------------------------------------------------
#define KT 64
#define GEMM_STAGE 32768
#define GEMM_SMEM (2 * GEMM_STAGE)   // 65536

__device__ __forceinline__ void gemm_issue(
    uint32_t sb, const __half* A, const __half* B,
    int mBase, int nBase, int kBase, int tid) {
#pragma unroll
    for (int i = 0; i < 4; i++) {   // A: 1024 units (128 r x 8 u)
        const int t = tid + i * 256;
        const int r = (t >> 3) & 127, u = t & 7;
        cp16(sb + swz8o(r, u), A + (size_t)(mBase + r) * DD + kBase + u * 8);
    }
#pragma unroll
    for (int i = 0; i < 4; i++) {   // B: 1024 units (128 r x 8 u)
        const int t = tid + i * 256;
        const int r = (t >> 3) & 127, u = t & 7;
        cp16(sb + 16384 + swz8o(r, u),
             B + (size_t)(nBase + r) * DD + kBase + u * 8);
    }
}

__device__ __forceinline__ void gemm_body(
    const __half* __restrict__ A, const __half* __restrict__ B,
    const float* __restrict__ bias, int mode,
    float* __restrict__ C, __half* __restrict__ Oh) {
    extern __shared__ char smem[];
    const uint32_t sbase = s2u(smem);

    const int tid = threadIdx.x;
    const int wid = tid >> 5;
    const int lane = tid & 31;
    const int m0 = (wid >> 2) * 64;
    const int n0 = (wid & 3) * 32;
    const int mBase = blockIdx.y * 128;
    const int nBase = blockIdx.x * 128;

    float acc[4][4][4];
#pragma unroll
    for (int i = 0; i < 4; i++)
#pragma unroll
        for (int j = 0; j < 4; j++)
#pragma unroll
            for (int q = 0; q < 4; q++) acc[i][j][q] = 0.0f;

    gemm_issue(sbase, A, B, mBase, nBase, 0, tid);
    CP_COMMIT();
    gemm_issue(sbase + GEMM_STAGE, A, B, mBase, nBase, KT, tid);
    CP_COMMIT();

    const int a_r = lane & 15;
    const int a_uh = lane >> 4;
    const int b_r = ((lane >> 4) & 1) * 8 + (lane & 7);
    const int b_uh = (lane >> 3) & 1;

    const int NKT = DD / KT;   // 12
    for (int kt = 0; kt < NKT; kt++) {
        CP_WAIT1();
        __syncthreads();
        const uint32_t st = sbase + (kt & 1) * GEMM_STAGE;
#pragma unroll
        for (int ks = 0; ks < 4; ks++) {
            const int ua = ks * 2 + a_uh;
            const int ub = ks * 2 + b_uh;
            uint32_t a4[4][4];
#pragma unroll
            for (int fm = 0; fm < 4; fm++)
                ldm_x4(a4[fm], st + swz8o(m0 + fm * 16 + a_r, ua));
#pragma unroll
            for (int fn2 = 0; fn2 < 2; fn2++) {
                uint32_t b4[4];
                ldm_x4(b4, st + 16384 + swz8o(n0 + fn2 * 16 + b_r, ub));
#pragma unroll
                for (int fm = 0; fm < 4; fm++) {
#pragma unroll
                    for (int hf = 0; hf < 2; hf++)
                        mma16816(acc[fm][fn2 * 2 + hf], a4[fm], &b4[hf * 2]);
                }
            }
        }
        __syncthreads();
        if (kt + 2 < NKT)
            gemm_issue(sbase + (kt & 1) * GEMM_STAGE, A, B,
                       mBase, nBase, (kt + 2) * KT, tid);
        CP_COMMIT();
    }

    const int row_l = lane >> 2;
    const int col_l = (lane & 3) * 2;
#pragma unroll
    for (int fn = 0; fn < 4; fn++) {
        const int col = nBase + n0 + fn * 8 + col_l;
        const float2 bv = *reinterpret_cast<const float2*>(&bias[col]);
#pragma unroll
        for (int fm = 0; fm < 4; fm++) {
            const int row = mBase + m0 + fm * 16 + row_l;
            float v0 = acc[fm][fn][0] + bv.x;
            float v1 = acc[fm][fn][1] + bv.y;
            float v2 = acc[fm][fn][2] + bv.x;
            float v3 = acc[fm][fn][3] + bv.y;
            if (mode == 0) {
                *reinterpret_cast<float2*>(&C[(size_t)row * DD + col]) = make_float2(v0, v1);
                *reinterpret_cast<float2*>(&C[(size_t)(row + 8) * DD + col]) = make_float2(v2, v3);
            } else if (mode == 3) {
                *reinterpret_cast<uint32_t*>(&Oh[(size_t)row * DD + col]) = cvt2h(v0, v1);
                *reinterpret_cast<uint32_t*>(&Oh[(size_t)(row + 8) * DD + col]) = cvt2h(v2, v3);
            } else {
                // transposed single: vt[(b*768+col)][n]
                float vv[4] = {v0, v1, v2, v3};
#pragma unroll
                for (int e = 0; e < 4; e++) {
                    const int rr = row + (e >> 1) * 8;
                    const int cc = col + (e & 1);
                    const int bb = rr >> 10, nn = rr & 1023;
                    Oh[(size_t)(bb * DD + cc) * NN + nn] = __float2half_rn(vv[e]);
                }
            }
        }
    }
}

__global__ __launch_bounds__(256, 2) void qkv_mma_kernel(
    const __half* __restrict__ A, const __half* __restrict__ W,
    const float* __restrict__ bq, const float* __restrict__ bk,
    const float* __restrict__ bv,
    __half* __restrict__ q, __half* __restrict__ k, __half* __restrict__ vt) {
    const int z = blockIdx.z;
    const size_t ws = (size_t)z * DD * DD;
    if (z == 0)
        gemm_body(A, W + ws, bq, 3, nullptr, q);
    else if (z == 1)
        gemm_body(A, W + ws, bk, 3, nullptr, k);
    else
        gemm_body(A, W + ws, bv, 2, nullptr, vt);
}

__global__ __launch_bounds__(256, 2) void out_mma_kernel(
    const __half* __restrict__ A, const __half* __restrict__ W,
    const float* __restrict__ bias, float* __restrict__ C) {
    gemm_body(A, W, bias, 0, C, nullptr);
}

// ---------------------------------------------------------------------------
// fp16 tensor-core flash attention, quiet softmax.
// Raw-unit running max; P = ex2(fma(S, SCALEQ, 10 - m*SCALEQ)) (scaled 2^10).
// Q/K/P/V all single fp16.
// RESTRUCTURED: warp tile 32q x 64k; Q fragments HELD IN REGISTERS (loaded
// once) -> per iter only 32 ldmatrix for 128 MMAs (ratio 0.25 vs 0.75).
// CTA = 4 warps = 128 q-rows; grid (8, 96); 2 CTAs/SM (48K smem, ~190 regs).
// 2-stage pipeline, refill at top of loop.
// smem: Q 16K | 2 x (K 8K | V 8K) = 48K.
// ---------------------------------------------------------------------------
#define ATTN_STAGE 16384
#define ATTN_SMEM (16384 + 2 * ATTN_STAGE)   // 49152

__device__ __forceinline__ void attn_issue(
    uint32_t st, const __half* k_, const __half* vt_,
    int b, int hoff, int kt, int tid) {
    const int tok0 = b * NN + kt * 64;
#pragma unroll
    for (int i = 0; i < 4; i++) {   // K: 512 units (64 rows x 8u)
        const int t = tid + i * 128;
        const int r = (t >> 3) & 63, u = t & 7;
        cp16(st + swz8o(r, u), k_ + (size_t)(tok0 + r) * DD + hoff + u * 8);
    }
#pragma unroll
    for (int i = 0; i < 4; i++) {   // V: 512 units (64 d-rows x 8u)
        const int t = tid + i * 128;
        const int r = (t >> 3) & 63, u = t & 7;
        cp16(st + 8192 + swz8o(r, u),
             vt_ + (size_t)(b * DD + hoff + r) * NN + kt * 64 + u * 8);
    }
}

__global__ __launch_bounds__(128, 2) void attn_mma_kernel(
    const __half* __restrict__ q_, const __half* __restrict__ k_,
    const __half* __restrict__ vt_, __half* __restrict__ c_) {
    extern __shared__ char smem[];
    const uint32_t sb = s2u(smem);
    const int tid = threadIdx.x;
    const int wid = tid >> 5;
    const int lane = tid & 31;
    const int qt = blockIdx.x;        // 0..7 (128-row tiles)
    const int bh = blockIdx.y;        // 0..95
    const int b = bh / HH;
    const int h = bh - b * HH;
    const int hoff = h * HD;
    const int q0 = b * NN + qt * 128;
    const int strip = wid * 32;

    // Q tile: 1024 units (128 rows x 8u), + stage 0, one group
#pragma unroll
    for (int i = 0; i < 8; i++) {
        const int t = tid + i * 128;
        const int r = (t >> 3) & 127, u = t & 7;
        cp16(sb + swz8o(r, u), q_ + (size_t)(q0 + r) * DD + hoff + u * 8);
    }
    attn_issue(sb + 16384, k_, vt_, b, hoff, 0, tid);
    CP_COMMIT();

    const int a_r = lane & 15;
    const int a_uh = lane >> 4;
    const int b_r = ((lane >> 4) & 1) * 8 + (lane & 7);
    const int b_uh = (lane >> 3) & 1;

    // Wait for Q + stage0, hoist Q fragments into registers, start stage1
    CP_WAIT0();
    __syncthreads();
    uint32_t qf[4][2][4];
#pragma unroll
    for (int ks = 0; ks < 4; ks++)
#pragma unroll
        for (int fm = 0; fm < 2; fm++)
            ldm_x4(qf[ks][fm], sb + swz8o(strip + fm * 16 + a_r, ks * 2 + a_uh));
    attn_issue(sb + 16384 + ATTN_STAGE, k_, vt_, b, hoff, 1, tid);
    CP_COMMIT();

    float m_[4], l_[4];
#pragma unroll
    for (int j = 0; j < 4; j++) { m_[j] = -1e30f; l_[j] = 0.0f; }
    float ctx[2][8][4];
#pragma unroll
    for (int fm = 0; fm < 2; fm++)
#pragma unroll
        for (int fn = 0; fn < 8; fn++)
#pragma unroll
            for (int q = 0; q < 4; q++) ctx[fm][fn][q] = 0.0f;

    for (int kt = 0; kt < 16; kt++) {
        if (kt > 0) {
            CP_WAIT0();
            __syncthreads();
            // Refill the slot of kt-1 (all warps passed the barrier => done).
            if (kt + 1 < 16)
                attn_issue(sb + 16384 + ((kt + 1) & 1) * ATTN_STAGE,
                           k_, vt_, b, hoff, kt + 1, tid);
            CP_COMMIT();
        }
        const uint32_t st = sb + 16384 + (kt & 1) * ATTN_STAGE;

        // ---- S[32 q x 64 keys] = Q K^T (raw units) ----
        float S[2][8][4];
#pragma unroll
        for (int fm = 0; fm < 2; fm++)
#pragma unroll
            for (int fn = 0; fn < 8; fn++)
#pragma unroll
                for (int q = 0; q < 4; q++) S[fm][fn][q] = 0.0f;

#pragma unroll
        for (int ks = 0; ks < 4; ks++) {
            const int ub = ks * 2 + b_uh;
#pragma unroll
            for (int fn2 = 0; fn2 < 4; fn2++) {
                uint32_t k4[4];
                ldm_x4(k4, st + swz8o(fn2 * 16 + b_r, ub));
#pragma unroll
                for (int fm = 0; fm < 2; fm++) {
                    mma16816(S[fm][fn2 * 2 + 0], qf[ks][fm], &k4[0]);
                    mma16816(S[fm][fn2 * 2 + 1], qf[ks][fm], &k4[2]);
                }
            }
        }

        // ---- online quiet softmax: max reduce + ctx rescale (4 row groups) ----
        float mx[4] = {-1e30f, -1e30f, -1e30f, -1e30f};
#pragma unroll
        for (int fm = 0; fm < 2; fm++)
#pragma unroll
            for (int fn = 0; fn < 8; fn++) {
                mx[fm * 2 + 0] = fmaxf(mx[fm * 2 + 0], fmaxf(S[fm][fn][0], S[fm][fn][1]));
                mx[fm * 2 + 1] = fmaxf(mx[fm * 2 + 1], fmaxf(S[fm][fn][2], S[fm][fn][3]));
            }
        float corr[4], cc[4];
#pragma unroll
        for (int j = 0; j < 4; j++) {
            mx[j] = fmaxf(mx[j], __shfl_xor_sync(0xffffffffu, mx[j], 1));
            mx[j] = fmaxf(mx[j], __shfl_xor_sync(0xffffffffu, mx[j], 2));
            const float mn = fmaxf(m_[j], mx[j]);
            corr[j] = ex2((m_[j] - mn) * SCALEQ);
            m_[j] = mn;
            cc[j] = fmaf(-mn, SCALEQ, 10.0f);   // 10 - m*SCALEQ
        }
#pragma unroll
        for (int fm = 0; fm < 2; fm++)
#pragma unroll
            for (int fn = 0; fn < 8; fn++) {
                ctx[fm][fn][0] *= corr[fm * 2];
                ctx[fm][fn][1] *= corr[fm * 2];
                ctx[fm][fn][2] *= corr[fm * 2 + 1];
                ctx[fm][fn][3] *= corr[fm * 2 + 1];
            }

        // ---- interleaved exp + pack + PV per 16-key block ----
        float ps[4] = {0.0f, 0.0f, 0.0f, 0.0f};
#pragma unroll
        for (int kb = 0; kb < 4; kb++) {
            uint32_t pa[2][4];
#pragma unroll
            for (int fm = 0; fm < 2; fm++) {
                const float e00 = ex2(fmaf(S[fm][2 * kb][0], SCALEQ, cc[fm * 2]));
                const float e01 = ex2(fmaf(S[fm][2 * kb][1], SCALEQ, cc[fm * 2]));
                const float e02 = ex2(fmaf(S[fm][2 * kb][2], SCALEQ, cc[fm * 2 + 1]));
                const float e03 = ex2(fmaf(S[fm][2 * kb][3], SCALEQ, cc[fm * 2 + 1]));
                const float e10 = ex2(fmaf(S[fm][2 * kb + 1][0], SCALEQ, cc[fm * 2]));
                const float e11 = ex2(fmaf(S[fm][2 * kb + 1][1], SCALEQ, cc[fm * 2]));
                const float e12 = ex2(fmaf(S[fm][2 * kb + 1][2], SCALEQ, cc[fm * 2 + 1]));
                const float e13 = ex2(fmaf(S[fm][2 * kb + 1][3], SCALEQ, cc[fm * 2 + 1]));
                ps[fm * 2 + 0] += (e00 + e01) + (e10 + e11);
                ps[fm * 2 + 1] += (e02 + e03) + (e12 + e13);
                pa[fm][0] = cvt2h(e00, e01);
                pa[fm][1] = cvt2h(e02, e03);
                pa[fm][2] = cvt2h(e10, e11);
                pa[fm][3] = cvt2h(e12, e13);
            }
            const int ub = kb * 2 + b_uh;
#pragma unroll
            for (int fn2 = 0; fn2 < 4; fn2++) {
                uint32_t v4[4];
                ldm_x4(v4, st + 8192 + swz8o(fn2 * 16 + b_r, ub));
#pragma unroll
                for (int fm = 0; fm < 2; fm++) {
                    mma16816(ctx[fm][fn2 * 2 + 0], pa[fm], &v4[0]);
                    mma16816(ctx[fm][fn2 * 2 + 1], pa[fm], &v4[2]);
                }
            }
        }
#pragma unroll
        for (int j = 0; j < 4; j++) {
            ps[j] += __shfl_xor_sync(0xffffffffu, ps[j], 1);
            ps[j] += __shfl_xor_sync(0xffffffffu, ps[j], 2);
            l_[j] = l_[j] * corr[j] + ps[j];
        }
    }

    // ---- epilogue: out = ctx' / (1024 + l'); emit half single ----
#pragma unroll
    for (int fm = 0; fm < 2; fm++) {
        const float inv0 = 1.0f / (1024.0f + l_[fm * 2]);
        const float inv1 = 1.0f / (1024.0f + l_[fm * 2 + 1]);
        const int rowA = q0 + strip + fm * 16 + (lane >> 2);
        const int rowB = rowA + 8;
#pragma unroll
        for (int fn = 0; fn < 8; fn++) {
            const int col = hoff + fn * 8 + (lane & 3) * 2;
            *reinterpret_cast<uint32_t*>(&c_[(size_t)rowA * DD + col]) =
                cvt2h(ctx[fm][fn][0] * inv0, ctx[fm][fn][1] * inv0);
            *reinterpret_cast<uint32_t*>(&c_[(size_t)rowB * DD + col]) =
                cvt2h(ctx[fm][fn][2] * inv1, ctx[fm][fn][3] * inv1);
        }
    }
}

// ---------------------------------------------------------------------------
// Launch
// ---------------------------------------------------------------------------
extern "C" void kernel_launch(void* const* d_in, const int* in_sizes, int n_in,
                              void* d_out, int out_size) {
    const float* x  = (const float*)d_in[0];
    const float* Wq = (const float*)d_in[1];
    const float* bq = (const float*)d_in[2];
    const float* Wk = (const float*)d_in[3];
    const float* bk = (const float*)d_in[4];
    const float* Wv = (const float*)d_in[5];
    const float* bv = (const float*)d_in[6];
    const float* Wo = (const float*)d_in[7];
    const float* bo = (const float*)d_in[8];
    float* out = (float*)d_out;
    (void)in_sizes; (void)n_in; (void)out_size;

    __half *xs, *q, *k, *vt, *c, *w;
    cudaGetSymbolAddress((void**)&xs, g_x);
    cudaGetSymbolAddress((void**)&q, g_q);
    cudaGetSymbolAddress((void**)&k, g_k);
    cudaGetSymbolAddress((void**)&vt, g_vt);
    cudaGetSymbolAddress((void**)&c, g_c);
    cudaGetSymbolAddress((void**)&w, g_w);

    cudaFuncSetAttribute(qkv_mma_kernel, cudaFuncAttributeMaxDynamicSharedMemorySize,
                         GEMM_SMEM);
    cudaFuncSetAttribute(out_mma_kernel, cudaFuncAttributeMaxDynamicSharedMemorySize,
                         GEMM_SMEM);
    cudaFuncSetAttribute(attn_mma_kernel, cudaFuncAttributeMaxDynamicSharedMemorySize,
                         ATTN_SMEM);

    const size_t ws = (size_t)DD * DD;

    convert_half_kernel<<<MM * DD / 8 / 256, 256>>>(x, xs);
    convert_wt_kernel<<<dim3(12, 12, 4), 256>>>(Wq, Wk, Wv, Wo, w);
    qkv_mma_kernel<<<dim3(6, 64, 3), 256, GEMM_SMEM>>>(xs, w, bq, bk, bv, q, k, vt);
    attn_mma_kernel<<<dim3(8, 96), 128, ATTN_SMEM>>>(q, k, vt, c);
    out_mma_kernel<<<dim3(6, 64), 256, GEMM_SMEM>>>(c, w + 3 * ws, bo, out);
}